// round 6
// baseline (speedup 1.0000x reference)
#include <cuda_runtime.h>
#include <cuda_bf16.h>
#include <cstdint>
#include <math.h>

#define T_TOK 2048
#define H_DIM 2048
#define S_LEN 1024
#define NHEAD 16
#define E_NUM 16
#define I_DIM 1408
#define TWO_I 2816
#define SHI_DIM 2816
#define SH2 5632

// ---------------- fp32 scratch ----------------
__device__ float g_Q   [(size_t)T_TOK * 2048];
__device__ float g_KV  [(size_t)T_TOK * 4096];
__device__ float g_attn[(size_t)T_TOK * 2048];
__device__ float g_hid [(size_t)T_TOK * H_DIM];
__device__ float g_X2  [(size_t)T_TOK * H_DIM];
__device__ float g_sgu [(size_t)T_TOK * SH2];
__device__ float g_gu  [(size_t)E_NUM * T_TOK * TWO_I];
__device__ float g_down[(size_t)E_NUM * T_TOK * H_DIM];
__device__ int   g_cnt [E_NUM];
__device__ int   g_tok [E_NUM * T_TOK];
__device__ int   g_texp[T_TOK * 4];
__device__ int   g_trow[T_TOK * 4];
__device__ float g_twt [T_TOK * 4];

// ---------------- int8 hi/lo planes + row scales ----------------
__device__ int8_t p_Xh [(size_t)T_TOK * H_DIM],   p_Xl [(size_t)T_TOK * H_DIM];
__device__ int8_t p_ath[(size_t)T_TOK * 2048],    p_atl[(size_t)T_TOK * 2048];
__device__ int8_t p_X2h[(size_t)T_TOK * H_DIM],   p_X2l[(size_t)T_TOK * H_DIM];
__device__ int8_t p_guh[(size_t)E_NUM * T_TOK * I_DIM], p_gul[(size_t)E_NUM * T_TOK * I_DIM];
__device__ int8_t p_sah[(size_t)T_TOK * SHI_DIM], p_sal[(size_t)T_TOK * SHI_DIM];
__device__ int8_t p_qwh[(size_t)2048 * 2048],     p_qwl[(size_t)2048 * 2048];
__device__ int8_t p_kvh[(size_t)4096 * 2048],     p_kvl[(size_t)4096 * 2048];
__device__ int8_t p_owh[(size_t)2048 * 2048],     p_owl[(size_t)2048 * 2048];
__device__ int8_t p_w1h[(size_t)E_NUM * TWO_I * H_DIM], p_w1l[(size_t)E_NUM * TWO_I * H_DIM];
__device__ int8_t p_w2h[(size_t)E_NUM * H_DIM * I_DIM], p_w2l[(size_t)E_NUM * H_DIM * I_DIM];
__device__ int8_t p_sgh[(size_t)SH2 * H_DIM],     p_sgl[(size_t)SH2 * H_DIM];
__device__ int8_t p_sdh[(size_t)H_DIM * SHI_DIM], p_sdl[(size_t)H_DIM * SHI_DIM];

__device__ float s_X [T_TOK], s_at[T_TOK], s_X2[T_TOK];
__device__ float s_gu[E_NUM * T_TOK], s_sa[T_TOK];
__device__ float s_qw[2048], s_kv[4096], s_ow[2048];
__device__ float s_w1[E_NUM * TWO_I], s_w2[E_NUM * H_DIM];
__device__ float s_sg[SH2], s_sd[H_DIM];

// ================= helpers =================
static __device__ __forceinline__ uint32_t smem_u32(const void* p) {
    uint32_t a;
    asm("{ .reg .u64 t; cvta.to.shared.u64 t, %1; cvt.u32.u64 %0, t; }" : "=r"(a) : "l"(p));
    return a;
}
#define LDM4(r, a) \
    asm volatile("ldmatrix.sync.aligned.m8n8.x4.shared.b16 {%0,%1,%2,%3}, [%4];" \
        : "=r"((r)[0]), "=r"((r)[1]), "=r"((r)[2]), "=r"((r)[3]) : "r"(a))
#define IMMA(c, a, b0, b1) \
    asm volatile("mma.sync.aligned.m16n8k32.row.col.s32.s8.s8.s32 " \
        "{%0,%1,%2,%3}, {%4,%5,%6,%7}, {%8,%9}, {%0,%1,%2,%3};" \
        : "+r"((c)[0]), "+r"((c)[1]), "+r"((c)[2]), "+r"((c)[3]) \
        : "r"((a)[0]), "r"((a)[1]), "r"((a)[2]), "r"((a)[3]), "r"(b0), "r"(b1))
#define CPA16(d, s, n) \
    asm volatile("cp.async.cg.shared.global [%0], [%1], 16, %2;" :: "r"(d), "l"(s), "r"(n) : "memory")
#define CPA_COMMIT() asm volatile("cp.async.commit_group;" ::: "memory")
#define CPA_WAIT2()  asm volatile("cp.async.wait_group 2;" ::: "memory")

// x ~= s*(h + l/256)
static __device__ __forceinline__ void qpair(float x, float inv, int& h, int& l) {
    float q = x * inv;
    h = __float2int_rn(q);
    h = max(-127, min(127, h));
    l = __float2int_rn((q - (float)h) * 256.f);
    l = max(-127, min(127, l));
}
static __device__ __forceinline__ float blockmax8(const float* red) {
    return fmaxf(fmaxf(fmaxf(red[0], red[1]), fmaxf(red[2], red[3])),
                 fmaxf(fmaxf(red[4], red[5]), fmaxf(red[6], red[7])));
}

// ================= row quantizer (weights + generic fp32 rows) =================
__global__ void __launch_bounds__(256) quantW(const float* __restrict__ src,
                                              int8_t* __restrict__ qh, int8_t* __restrict__ ql,
                                              float* __restrict__ sc, int K, int remap) {
    __shared__ float buf[2816];
    __shared__ float red[8];
    int row = blockIdx.x, tid = threadIdx.x;
    int sr = remap ? ((row >> 7) * 192 + (row & 127)) : row;
    const float* s = src + (size_t)sr * K;
    float mx = 0.f;
    for (int i = tid * 4; i < K; i += 1024) {
        float4 v = *(const float4*)(s + i);
        buf[i] = v.x; buf[i + 1] = v.y; buf[i + 2] = v.z; buf[i + 3] = v.w;
        mx = fmaxf(mx, fmaxf(fmaxf(fabsf(v.x), fabsf(v.y)), fmaxf(fabsf(v.z), fabsf(v.w))));
    }
    #pragma unroll
    for (int o = 16; o; o >>= 1) mx = fmaxf(mx, __shfl_xor_sync(0xffffffffu, mx, o));
    if ((tid & 31) == 0) red[tid >> 5] = mx;
    __syncthreads();
    float M = blockmax8(red);
    float inv = (M > 0.f) ? 127.f / M : 0.f;
    if (tid == 0) sc[row] = (M > 0.f) ? M / 127.f : 0.f;
    for (int i = tid * 4; i < K; i += 1024) {
        int h0, l0, h1, l1, h2, l2, h3, l3;
        qpair(buf[i], inv, h0, l0); qpair(buf[i + 1], inv, h1, l1);
        qpair(buf[i + 2], inv, h2, l2); qpair(buf[i + 3], inv, h3, l3);
        *(char4*)(qh + (size_t)row * K + i) = make_char4((signed char)h0, (signed char)h1, (signed char)h2, (signed char)h3);
        *(char4*)(ql + (size_t)row * K + i) = make_char4((signed char)l0, (signed char)l1, (signed char)l2, (signed char)l3);
    }
}

// ================= IMMA s8x3 GEMM: C = A @ W^T (+addsrc) =================
// 128x128 tile, BK=64 (2 k32 steps), 8 warps (32x64 warp tile), 4-stage cp.async ring.
// Stage: Ahi[128x80B] Alo Bhi Blo (10240B each) = 40960B; 4 stages = 160KB.
#define GSMEM_BYTES (4 * 40960)

template <int MODE, bool ADD>
__global__ void __launch_bounds__(256, 1) gemm_i8(
    const int8_t* __restrict__ Ahi, const int8_t* __restrict__ Alo,
    const float* __restrict__ sA, long long aestride, long long sAstride, int lda,
    const int8_t* __restrict__ Bhi, const int8_t* __restrict__ Blo,
    const float* __restrict__ sB, long long bestride, long long sBstride,
    float* __restrict__ C, long long cstride, int ldc,
    int M, int K,
    const float* __restrict__ addsrc, int ldadd)
{
    extern __shared__ char smem[];
    const int e  = blockIdx.z;
    const int Me = (MODE == 0) ? M : g_cnt[e];
    const int bm = blockIdx.y * 128, bn = blockIdx.x * 128;
    if (bm >= Me) return;
    const int8_t* AhiB = Ahi + (MODE == 2 ? (long long)e * aestride : 0LL);
    const int8_t* AloB = Alo + (MODE == 2 ? (long long)e * aestride : 0LL);
    const int8_t* BhiB = Bhi + (long long)e * bestride;
    const int8_t* BloB = Blo + (long long)e * bestride;
    const float*  sBe  = sB + (long long)e * sBstride;
    float* Cb = C + (long long)e * cstride;

    const uint32_t sb = smem_u32(smem);
    const int tid = threadIdx.x, wid = tid >> 5, lid = tid & 31;
    const int wm = wid & 3, wn = wid >> 2;

    uint32_t sOff[2]; uint32_t aval[2];
    const char *aHp[2], *aLp[2], *bHp[2], *bLp[2];
    #pragma unroll
    for (int i = 0; i < 2; i++) {
        int q = tid + i * 256;
        int row = q >> 2, seg = q & 3;
        sOff[i] = (uint32_t)(row * 80 + seg * 16);
        int gm = bm + row;
        aval[i] = (gm < Me) ? 16u : 0u;
        long long arow;
        if (MODE == 1) arow = (gm < Me) ? (long long)g_tok[e * T_TOK + gm] : 0LL;
        else           arow = (gm < Me) ? (long long)gm : 0LL;
        aHp[i] = (const char*)(AhiB + arow * (long long)lda) + seg * 16;
        aLp[i] = (const char*)(AloB + arow * (long long)lda) + seg * 16;
        long long brow = (long long)(bn + row);
        bHp[i] = (const char*)(BhiB + brow * (long long)lda) + seg * 16;
        bLp[i] = (const char*)(BloB + brow * (long long)lda) + seg * 16;
    }

    const int laneRow = lid & 15, laneChk = lid >> 4;
    uint32_t aOff[2], bOff[4];
    #pragma unroll
    for (int t = 0; t < 2; t++)
        aOff[t] = (uint32_t)((wm * 32 + t * 16 + laneRow) * 80 + laneChk * 16);
    #pragma unroll
    for (int p = 0; p < 4; p++)
        bOff[p] = (uint32_t)(20480 + (wn * 64 + p * 16 + laneRow) * 80 + laneChk * 16);

    int am[2][8][4], ax[2][8][4];
    #pragma unroll
    for (int t = 0; t < 2; t++)
        #pragma unroll
        for (int n8 = 0; n8 < 8; n8++)
            #pragma unroll
            for (int j = 0; j < 4; j++) { am[t][n8][j] = 0; ax[t][n8][j] = 0; }

    const int NC = K / 64;

    #define ISSUE(c) do { \
        uint32_t st_ = sb + (uint32_t)((c) & 3) * 40960u; \
        long long kb_ = (long long)(c) * 64; \
        _Pragma("unroll") \
        for (int i_ = 0; i_ < 2; i_++) { \
            CPA16(st_ + sOff[i_],          aHp[i_] + kb_, aval[i_]); \
            CPA16(st_ + 10240u + sOff[i_], aLp[i_] + kb_, aval[i_]); \
            CPA16(st_ + 20480u + sOff[i_], bHp[i_] + kb_, 16u); \
            CPA16(st_ + 30720u + sOff[i_], bLp[i_] + kb_, 16u); \
        } \
    } while (0)

    ISSUE(0); CPA_COMMIT();
    if (NC > 1) { ISSUE(1); } CPA_COMMIT();
    if (NC > 2) { ISSUE(2); } CPA_COMMIT();

    for (int c = 0; c < NC; c++) {
        CPA_WAIT2();
        __syncthreads();
        const uint32_t stg = sb + (uint32_t)(c & 3) * 40960u;
        #pragma unroll
        for (int h = 0; h < 2; h++) {   // two k32 steps (32 bytes each)
            uint32_t ah0[4], ah1[4], al0[4], al1[4];
            LDM4(ah0, stg + aOff[0] + h * 32);
            LDM4(ah1, stg + aOff[1] + h * 32);
            LDM4(al0, stg + aOff[0] + 10240u + h * 32);
            LDM4(al1, stg + aOff[1] + 10240u + h * 32);
            #pragma unroll
            for (int p = 0; p < 4; p++) {
                uint32_t bh[4], bl[4];
                LDM4(bh, stg + bOff[p] + h * 32);
                LDM4(bl, stg + bOff[p] + 10240u + h * 32);
                // main: h*h
                IMMA(am[0][2 * p],     ah0, bh[0], bh[2]);
                IMMA(am[0][2 * p + 1], ah0, bh[1], bh[3]);
                IMMA(am[1][2 * p],     ah1, bh[0], bh[2]);
                IMMA(am[1][2 * p + 1], ah1, bh[1], bh[3]);
                // cross: l*h + h*l (shared 1/256 scale)
                IMMA(ax[0][2 * p],     al0, bh[0], bh[2]);
                IMMA(ax[0][2 * p + 1], al0, bh[1], bh[3]);
                IMMA(ax[1][2 * p],     al1, bh[0], bh[2]);
                IMMA(ax[1][2 * p + 1], al1, bh[1], bh[3]);
                IMMA(ax[0][2 * p],     ah0, bl[0], bl[2]);
                IMMA(ax[0][2 * p + 1], ah0, bl[1], bl[3]);
                IMMA(ax[1][2 * p],     ah1, bl[0], bl[2]);
                IMMA(ax[1][2 * p + 1], ah1, bl[1], bl[3]);
            }
        }
        __syncthreads();
        if (c + 3 < NC) ISSUE(c + 3);
        CPA_COMMIT();
    }
    #undef ISSUE

    const int g = lid >> 2, tg = lid & 3;
    #pragma unroll
    for (int t = 0; t < 2; t++) {
        #pragma unroll
        for (int half = 0; half < 2; half++) {
            int row = bm + wm * 32 + t * 16 + g + half * 8;
            if (row >= Me) continue;
            float sa;
            if (MODE == 1)      sa = sA[g_tok[e * T_TOK + row]];
            else if (MODE == 2) sa = sA[e * sAstride + row];
            else                sa = sA[row];
            float* cp = Cb + (long long)row * ldc + bn + wn * 64 + tg * 2;
            const float* ap = ADD ? (addsrc + (long long)row * ldadd + bn + wn * 64 + tg * 2) : (const float*)0;
            #pragma unroll
            for (int n8 = 0; n8 < 8; n8++) {
                int col = bn + wn * 64 + n8 * 8 + tg * 2;
                float sb0 = sBe[col], sb1 = sBe[col + 1];
                float v0 = sa * sb0 * ((float)am[t][n8][half * 2]     + (float)ax[t][n8][half * 2]     * 0.00390625f);
                float v1 = sa * sb1 * ((float)am[t][n8][half * 2 + 1] + (float)ax[t][n8][half * 2 + 1] * 0.00390625f);
                if (ADD) { v0 += ap[n8 * 8]; v1 += ap[n8 * 8 + 1]; }
                cp[n8 * 8] = v0; cp[n8 * 8 + 1] = v1;
            }
        }
    }
}

// ---------------- rmsnorm (+quant, optional fp32 out) ----------------
__global__ __launch_bounds__(256) void rmsnorm_q(const float* __restrict__ in,
                                                 const float* __restrict__ w,
                                                 float* __restrict__ out,
                                                 int8_t* __restrict__ qh, int8_t* __restrict__ ql,
                                                 float* __restrict__ sc) {
    __shared__ float buf[H_DIM];
    __shared__ float red[8];
    int t = blockIdx.x, tid = threadIdx.x;
    const float* row = in + (size_t)t * H_DIM;
    float ss = 0.f;
    for (int i = tid * 4; i < H_DIM; i += 1024) {
        float4 v = *(const float4*)(row + i);
        buf[i] = v.x; buf[i + 1] = v.y; buf[i + 2] = v.z; buf[i + 3] = v.w;
        ss += v.x * v.x + v.y * v.y + v.z * v.z + v.w * v.w;
    }
    #pragma unroll
    for (int o = 16; o; o >>= 1) ss += __shfl_xor_sync(0xffffffffu, ss, o);
    if ((tid & 31) == 0) red[tid >> 5] = ss;
    __syncthreads();
    float tot = red[0] + red[1] + red[2] + red[3] + red[4] + red[5] + red[6] + red[7];
    float invr = rsqrtf(tot * (1.0f / H_DIM) + 1e-6f);
    __syncthreads();
    float mx = 0.f;
    for (int i = tid * 4; i < H_DIM; i += 1024) {
        float a0 = buf[i] * invr * w[i];
        float a1 = buf[i + 1] * invr * w[i + 1];
        float a2 = buf[i + 2] * invr * w[i + 2];
        float a3 = buf[i + 3] * invr * w[i + 3];
        buf[i] = a0; buf[i + 1] = a1; buf[i + 2] = a2; buf[i + 3] = a3;
        mx = fmaxf(mx, fmaxf(fmaxf(fabsf(a0), fabsf(a1)), fmaxf(fabsf(a2), fabsf(a3))));
        if (out) *(float4*)(out + (size_t)t * H_DIM + i) = make_float4(a0, a1, a2, a3);
    }
    #pragma unroll
    for (int o = 16; o; o >>= 1) mx = fmaxf(mx, __shfl_xor_sync(0xffffffffu, mx, o));
    if ((tid & 31) == 0) red[tid >> 5] = mx;
    __syncthreads();
    float M = blockmax8(red);
    float inv = (M > 0.f) ? 127.f / M : 0.f;
    if (tid == 0) sc[t] = (M > 0.f) ? M / 127.f : 0.f;
    for (int i = tid * 4; i < H_DIM; i += 1024) {
        int h0, l0, h1, l1, h2, l2, h3, l3;
        qpair(buf[i], inv, h0, l0); qpair(buf[i + 1], inv, h1, l1);
        qpair(buf[i + 2], inv, h2, l2); qpair(buf[i + 3], inv, h3, l3);
        *(char4*)(qh + (size_t)t * H_DIM + i) = make_char4((signed char)h0, (signed char)h1, (signed char)h2, (signed char)h3);
        *(char4*)(ql + (size_t)t * H_DIM + i) = make_char4((signed char)l0, (signed char)l1, (signed char)l2, (signed char)l3);
    }
}

// ---------------- flash attention (fp32, causal, D=128, 64x64 tiles) ----------------
__global__ void __launch_bounds__(256) attn_kernel() {
    extern __shared__ float sm[];
    float* Qs = sm;
    float* Ks = Qs + 64 * 129;
    float* Vs = Ks + 64 * 129;
    float* Ps = Vs + 64 * 132;
    float* mrow = Ps + 64 * 65;
    float* lrow = mrow + 64;
    float* corr = lrow + 64;

    int bh = blockIdx.y; int b = bh >> 4, h = bh & 15;
    int q0 = blockIdx.x * 64;
    int tb = b * S_LEN;
    int tid = threadIdx.x;
    int ty = tid / 16, tx = tid % 16;

    for (int i = tid; i < 64 * 32; i += 256) {
        int r = i >> 5, c4 = (i & 31) * 4;
        float4 v = *(const float4*)(g_Q + (size_t)(tb + q0 + r) * 2048 + h * 128 + c4);
        Qs[r * 129 + c4] = v.x; Qs[r * 129 + c4 + 1] = v.y;
        Qs[r * 129 + c4 + 2] = v.z; Qs[r * 129 + c4 + 3] = v.w;
    }
    if (tid < 64) { mrow[tid] = -1e30f; lrow[tid] = 0.f; }
    float acc[4][8];
    #pragma unroll
    for (int i = 0; i < 4; i++)
        #pragma unroll
        for (int j = 0; j < 8; j++) acc[i][j] = 0.f;
    const float scale = 1.0f / sqrtf(192.0f);
    __syncthreads();

    int nkt = blockIdx.x + 1;
    for (int kt = 0; kt < nkt; kt++) {
        int k0 = kt * 64;
        for (int i = tid; i < 64 * 32; i += 256) {
            int r = i >> 5, c4 = (i & 31) * 4;
            const float* kp = g_KV + (size_t)(tb + k0 + r) * 4096 + h * 128;
            float4 kv4 = *(const float4*)(kp + c4);
            Ks[r * 129 + c4] = kv4.x; Ks[r * 129 + c4 + 1] = kv4.y;
            Ks[r * 129 + c4 + 2] = kv4.z; Ks[r * 129 + c4 + 3] = kv4.w;
            float4 vv4 = *(const float4*)(kp + 2048 + c4);
            Vs[r * 132 + c4] = vv4.x; Vs[r * 132 + c4 + 1] = vv4.y;
            Vs[r * 132 + c4 + 2] = vv4.z; Vs[r * 132 + c4 + 3] = vv4.w;
        }
        __syncthreads();
        float s[4][4];
        #pragma unroll
        for (int i = 0; i < 4; i++)
            #pragma unroll
            for (int j = 0; j < 4; j++) s[i][j] = 0.f;
        #pragma unroll 4
        for (int k = 0; k < 128; k++) {
            float qa[4], kb[4];
            #pragma unroll
            for (int i = 0; i < 4; i++) qa[i] = Qs[(4 * ty + i) * 129 + k];
            #pragma unroll
            for (int j = 0; j < 4; j++) kb[j] = Ks[(4 * tx + j) * 129 + k];
            #pragma unroll
            for (int i = 0; i < 4; i++)
                #pragma unroll
                for (int j = 0; j < 4; j++) s[i][j] += qa[i] * kb[j];
        }
        #pragma unroll
        for (int i = 0; i < 4; i++)
            #pragma unroll
            for (int j = 0; j < 4; j++) {
                int rq = q0 + 4 * ty + i, ck = k0 + 4 * tx + j;
                Ps[(4 * ty + i) * 65 + 4 * tx + j] = (ck <= rq) ? s[i][j] * scale : -1e30f;
            }
        __syncthreads();
        if (tid < 64) {
            float m0 = mrow[tid], mx = m0;
            for (int c = 0; c < 64; c++) mx = fmaxf(mx, Ps[tid * 65 + c]);
            float cr = __expf(m0 - mx);
            float l = lrow[tid] * cr;
            for (int c = 0; c < 64; c++) {
                float p = __expf(Ps[tid * 65 + c] - mx);
                Ps[tid * 65 + c] = p; l += p;
            }
            mrow[tid] = mx; lrow[tid] = l; corr[tid] = cr;
        }
        __syncthreads();
        #pragma unroll
        for (int i = 0; i < 4; i++) {
            float cr = corr[4 * ty + i];
            #pragma unroll
            for (int j = 0; j < 8; j++) acc[i][j] *= cr;
        }
        #pragma unroll 2
        for (int c = 0; c < 64; c++) {
            float p[4], v[8];
            #pragma unroll
            for (int i = 0; i < 4; i++) p[i] = Ps[(4 * ty + i) * 65 + c];
            #pragma unroll
            for (int j = 0; j < 8; j++) v[j] = Vs[c * 132 + 8 * tx + j];
            #pragma unroll
            for (int i = 0; i < 4; i++)
                #pragma unroll
                for (int j = 0; j < 8; j++) acc[i][j] += p[i] * v[j];
        }
        __syncthreads();
    }
    #pragma unroll
    for (int i = 0; i < 4; i++) {
        int r = 4 * ty + i;
        float inv = 1.0f / lrow[r];
        #pragma unroll
        for (int j = 0; j < 8; j++)
            g_attn[(size_t)(tb + q0 + r) * 2048 + h * 128 + 8 * tx + j] = acc[i][j] * inv;
    }
}

// ---------------- gate ----------------
__global__ void __launch_bounds__(512) zero_cnt() { if (threadIdx.x < E_NUM) g_cnt[threadIdx.x] = 0; }

__global__ void __launch_bounds__(512) gate_kernel(const float* __restrict__ gate_w) {
    int t = blockIdx.x;
    int w = threadIdx.x >> 5, lane = threadIdx.x & 31;
    const float* x = g_X2 + (size_t)t * H_DIM;
    const float* gw = gate_w + (size_t)w * H_DIM;
    float s = 0.f;
    for (int i = lane; i < H_DIM; i += 32) s += x[i] * gw[i];
    #pragma unroll
    for (int o = 16; o; o >>= 1) s += __shfl_xor_sync(0xffffffffu, s, o);
    __shared__ float lg[E_NUM];
    if (lane == 0) lg[w] = s;
    __syncthreads();
    if (threadIdx.x == 0) {
        float mx = -1e30f;
        for (int e = 0; e < E_NUM; e++) mx = fmaxf(mx, lg[e]);
        float pe[E_NUM];
        for (int e = 0; e < E_NUM; e++) pe[e] = expf(lg[e] - mx);
        bool used[E_NUM];
        for (int e = 0; e < E_NUM; e++) used[e] = false;
        int sel[4]; float sw[4]; float wsum = 0.f;
        for (int j = 0; j < 4; j++) {
            int bi = -1; float bv = -1.f;
            for (int e = 0; e < E_NUM; e++)
                if (!used[e] && pe[e] > bv) { bv = pe[e]; bi = e; }
            used[bi] = true; sel[j] = bi; sw[j] = bv; wsum += bv;
        }
        for (int j = 0; j < 4; j++) {
            int e = sel[j];
            int pos = atomicAdd(&g_cnt[e], 1);
            g_tok[e * T_TOK + pos] = t;
            g_texp[t * 4 + j] = e;
            g_trow[t * 4 + j] = pos;
            g_twt [t * 4 + j] = sw[j] / wsum;
        }
    }
}

// ---------------- activations (+quant) ----------------
__device__ __forceinline__ float silu_f(float x) { return x / (1.0f + __expf(-x)); }

__global__ void __launch_bounds__(256) act_moe_q() {
    __shared__ float buf[I_DIM];
    __shared__ float red[8];
    int e = blockIdx.y, r = blockIdx.x, tid = threadIdx.x;
    if (r >= g_cnt[e]) return;
    const float* row = g_gu + ((size_t)e * T_TOK + r) * TWO_I;
    float mx = 0.f;
    for (int i = tid * 4; i < I_DIM; i += 1024) {
        #pragma unroll
        for (int k = 0; k < 4; k++) {
            float v = silu_f(row[i + k]) * row[I_DIM + i + k];
            buf[i + k] = v;
            mx = fmaxf(mx, fabsf(v));
        }
    }
    #pragma unroll
    for (int o = 16; o; o >>= 1) mx = fmaxf(mx, __shfl_xor_sync(0xffffffffu, mx, o));
    if ((tid & 31) == 0) red[tid >> 5] = mx;
    __syncthreads();
    float M = blockmax8(red);
    float inv = (M > 0.f) ? 127.f / M : 0.f;
    if (tid == 0) s_gu[e * T_TOK + r] = (M > 0.f) ? M / 127.f : 0.f;
    size_t pb = ((size_t)e * T_TOK + r) * I_DIM;
    for (int i = tid * 4; i < I_DIM; i += 1024) {
        int h0, l0, h1, l1, h2, l2, h3, l3;
        qpair(buf[i], inv, h0, l0); qpair(buf[i + 1], inv, h1, l1);
        qpair(buf[i + 2], inv, h2, l2); qpair(buf[i + 3], inv, h3, l3);
        *(char4*)(p_guh + pb + i) = make_char4((signed char)h0, (signed char)h1, (signed char)h2, (signed char)h3);
        *(char4*)(p_gul + pb + i) = make_char4((signed char)l0, (signed char)l1, (signed char)l2, (signed char)l3);
    }
}

__global__ void __launch_bounds__(256) act_shared_q() {
    __shared__ float buf[SHI_DIM];
    __shared__ float red[8];
    int t = blockIdx.x, tid = threadIdx.x;
    const float* row = g_sgu + (size_t)t * SH2;
    float mx = 0.f;
    for (int i = tid * 4; i < SHI_DIM; i += 1024) {
        #pragma unroll
        for (int k = 0; k < 4; k++) {
            float v = silu_f(row[i + k]) * row[SHI_DIM + i + k];
            buf[i + k] = v;
            mx = fmaxf(mx, fabsf(v));
        }
    }
    #pragma unroll
    for (int o = 16; o; o >>= 1) mx = fmaxf(mx, __shfl_xor_sync(0xffffffffu, mx, o));
    if ((tid & 31) == 0) red[tid >> 5] = mx;
    __syncthreads();
    float M = blockmax8(red);
    float inv = (M > 0.f) ? 127.f / M : 0.f;
    if (tid == 0) s_sa[t] = (M > 0.f) ? M / 127.f : 0.f;
    size_t pb = (size_t)t * SHI_DIM;
    for (int i = tid * 4; i < SHI_DIM; i += 1024) {
        int h0, l0, h1, l1, h2, l2, h3, l3;
        qpair(buf[i], inv, h0, l0); qpair(buf[i + 1], inv, h1, l1);
        qpair(buf[i + 2], inv, h2, l2); qpair(buf[i + 3], inv, h3, l3);
        *(char4*)(p_sah + pb + i) = make_char4((signed char)h0, (signed char)h1, (signed char)h2, (signed char)h3);
        *(char4*)(p_sal + pb + i) = make_char4((signed char)l0, (signed char)l1, (signed char)l2, (signed char)l3);
    }
}

// ---------------- final sum ----------------
__global__ void __launch_bounds__(256) final_sum(float* __restrict__ out) {
    int t = blockIdx.x;
    int e0 = g_texp[t * 4 + 0], e1 = g_texp[t * 4 + 1], e2 = g_texp[t * 4 + 2], e3 = g_texp[t * 4 + 3];
    int r0 = g_trow[t * 4 + 0], r1 = g_trow[t * 4 + 1], r2 = g_trow[t * 4 + 2], r3 = g_trow[t * 4 + 3];
    float w0 = g_twt[t * 4 + 0], w1v = g_twt[t * 4 + 1], w2v = g_twt[t * 4 + 2], w3 = g_twt[t * 4 + 3];
    const float* d0 = g_down + ((size_t)e0 * T_TOK + r0) * H_DIM;
    const float* d1 = g_down + ((size_t)e1 * T_TOK + r1) * H_DIM;
    const float* d2 = g_down + ((size_t)e2 * T_TOK + r2) * H_DIM;
    const float* d3 = g_down + ((size_t)e3 * T_TOK + r3) * H_DIM;
    for (int h = threadIdx.x; h < H_DIM; h += 256) {
        float v = out[(size_t)t * H_DIM + h];
        v += w0 * d0[h] + w1v * d1[h] + w2v * d2[h] + w3 * d3[h];
        out[(size_t)t * H_DIM + h] = v;
    }
}

// ---------------- launch ----------------
extern "C" void kernel_launch(void* const* d_in, const int* in_sizes, int n_in,
                              void* d_out, int out_size) {
    (void)in_sizes; (void)n_in; (void)out_size;
    const float* hidden  = (const float*)d_in[0];
    const float* ln1_w   = (const float*)d_in[2];
    const float* ln2_w   = (const float*)d_in[3];
    const float* q_w     = (const float*)d_in[4];
    const float* kv_w    = (const float*)d_in[5];
    const float* o_w     = (const float*)d_in[6];
    const float* gate_w  = (const float*)d_in[7];
    const float* w1      = (const float*)d_in[8];
    const float* w2      = (const float*)d_in[9];
    const float* sh_gu_w = (const float*)d_in[10];
    const float* sh_dn_w = (const float*)d_in[11];
    float* out = (float*)d_out;

    float *pQ, *pKV, *pAttn, *pHid, *pX2, *pSgu, *pGu, *pDown;
    cudaGetSymbolAddress((void**)&pQ, g_Q);
    cudaGetSymbolAddress((void**)&pKV, g_KV);
    cudaGetSymbolAddress((void**)&pAttn, g_attn);
    cudaGetSymbolAddress((void**)&pHid, g_hid);
    cudaGetSymbolAddress((void**)&pX2, g_X2);
    cudaGetSymbolAddress((void**)&pSgu, g_sgu);
    cudaGetSymbolAddress((void**)&pGu, g_gu);
    cudaGetSymbolAddress((void**)&pDown, g_down);

    int8_t *Xh, *Xl, *ath, *atl, *X2h, *X2l, *guh, *gul, *sah, *sal;
    int8_t *qwh, *qwl, *kvh, *kvl, *owh, *owl, *w1h, *w1l, *w2h, *w2l, *sgh, *sgl, *sdh, *sdl;
    float *sX, *sat, *sX2, *sgu, *ssa, *sqw, *skv, *sow, *sw1, *sw2, *ssg, *ssd;
    cudaGetSymbolAddress((void**)&Xh, p_Xh);   cudaGetSymbolAddress((void**)&Xl, p_Xl);
    cudaGetSymbolAddress((void**)&ath, p_ath); cudaGetSymbolAddress((void**)&atl, p_atl);
    cudaGetSymbolAddress((void**)&X2h, p_X2h); cudaGetSymbolAddress((void**)&X2l, p_X2l);
    cudaGetSymbolAddress((void**)&guh, p_guh); cudaGetSymbolAddress((void**)&gul, p_gul);
    cudaGetSymbolAddress((void**)&sah, p_sah); cudaGetSymbolAddress((void**)&sal, p_sal);
    cudaGetSymbolAddress((void**)&qwh, p_qwh); cudaGetSymbolAddress((void**)&qwl, p_qwl);
    cudaGetSymbolAddress((void**)&kvh, p_kvh); cudaGetSymbolAddress((void**)&kvl, p_kvl);
    cudaGetSymbolAddress((void**)&owh, p_owh); cudaGetSymbolAddress((void**)&owl, p_owl);
    cudaGetSymbolAddress((void**)&w1h, p_w1h); cudaGetSymbolAddress((void**)&w1l, p_w1l);
    cudaGetSymbolAddress((void**)&w2h, p_w2h); cudaGetSymbolAddress((void**)&w2l, p_w2l);
    cudaGetSymbolAddress((void**)&sgh, p_sgh); cudaGetSymbolAddress((void**)&sgl, p_sgl);
    cudaGetSymbolAddress((void**)&sdh, p_sdh); cudaGetSymbolAddress((void**)&sdl, p_sdl);
    cudaGetSymbolAddress((void**)&sX, s_X);    cudaGetSymbolAddress((void**)&sat, s_at);
    cudaGetSymbolAddress((void**)&sX2, s_X2);  cudaGetSymbolAddress((void**)&sgu, s_gu);
    cudaGetSymbolAddress((void**)&ssa, s_sa);  cudaGetSymbolAddress((void**)&sqw, s_qw);
    cudaGetSymbolAddress((void**)&skv, s_kv);  cudaGetSymbolAddress((void**)&sow, s_ow);
    cudaGetSymbolAddress((void**)&sw1, s_w1);  cudaGetSymbolAddress((void**)&sw2, s_w2);
    cudaGetSymbolAddress((void**)&ssg, s_sg);  cudaGetSymbolAddress((void**)&ssd, s_sd);

    const int ATTN_SMEM = (64 * 129 + 64 * 129 + 64 * 132 + 64 * 65 + 192) * 4;
    cudaFuncSetAttribute(attn_kernel, cudaFuncAttributeMaxDynamicSharedMemorySize, ATTN_SMEM);
    cudaFuncSetAttribute(gemm_i8<0, false>, cudaFuncAttributeMaxDynamicSharedMemorySize, GSMEM_BYTES);
    cudaFuncSetAttribute(gemm_i8<0, true >, cudaFuncAttributeMaxDynamicSharedMemorySize, GSMEM_BYTES);
    cudaFuncSetAttribute(gemm_i8<1, false>, cudaFuncAttributeMaxDynamicSharedMemorySize, GSMEM_BYTES);
    cudaFuncSetAttribute(gemm_i8<2, false>, cudaFuncAttributeMaxDynamicSharedMemorySize, GSMEM_BYTES);

    // 0) weight quantization
    quantW<<<2048, 256>>>(q_w,     qwh, qwl, sqw, 2048, 1);
    quantW<<<4096, 256>>>(kv_w,    kvh, kvl, skv, 2048, 0);
    quantW<<<2048, 256>>>(o_w,     owh, owl, sow, 2048, 0);
    quantW<<<E_NUM * TWO_I, 256>>>(w1, w1h, w1l, sw1, 2048, 0);
    quantW<<<E_NUM * H_DIM, 256>>>(w2, w2h, w2l, sw2, 1408, 0);
    quantW<<<SH2, 256>>>(sh_gu_w,  sgh, sgl, ssg, 2048, 0);
    quantW<<<H_DIM, 256>>>(sh_dn_w, sdh, sdl, ssd, 2816, 0);

    // 1) x = rmsnorm(hidden) -> q-planes (no fp32 needed)
    rmsnorm_q<<<T_TOK, 256>>>(hidden, ln1_w, nullptr, Xh, Xl, sX);
    // 2) Q
    gemm_i8<0, false><<<dim3(16, 16, 1), 256, GSMEM_BYTES>>>(
        Xh, Xl, sX, 0, 0, 2048, qwh, qwl, sqw, 0, 0, pQ, 0, 2048, T_TOK, 2048, nullptr, 0);
    // 3) KV
    gemm_i8<0, false><<<dim3(32, 16, 1), 256, GSMEM_BYTES>>>(
        Xh, Xl, sX, 0, 0, 2048, kvh, kvl, skv, 0, 0, pKV, 0, 4096, T_TOK, 2048, nullptr, 0);
    // 4) attention (fp32)
    attn_kernel<<<dim3(16, 32), 256, ATTN_SMEM>>>();
    // 4b) quantize attn rows
    quantW<<<T_TOK, 256>>>(pAttn, ath, atl, sat, 2048, 0);
    // 5) hid = attn @ o_w^T + hidden
    gemm_i8<0, true><<<dim3(16, 16, 1), 256, GSMEM_BYTES>>>(
        ath, atl, sat, 0, 0, 2048, owh, owl, sow, 0, 0, pHid, 0, H_DIM, T_TOK, 2048, hidden, H_DIM);
    // 6) x2 = rmsnorm(hid) -> fp32 (for gate) + q-planes
    rmsnorm_q<<<T_TOK, 256>>>(pHid, ln2_w, pX2, X2h, X2l, sX2);
    // 7) routing
    zero_cnt<<<1, 32>>>();
    gate_kernel<<<T_TOK, 512>>>(gate_w);
    // 8) routed GU
    gemm_i8<1, false><<<dim3(22, 16, E_NUM), 256, GSMEM_BYTES>>>(
        X2h, X2l, sX2, 0, 0, 2048,
        w1h, w1l, sw1, (long long)TWO_I * H_DIM, TWO_I,
        pGu, (long long)T_TOK * TWO_I, TWO_I, 0, 2048, nullptr, 0);
    // 9) routed act + quant
    act_moe_q<<<dim3(T_TOK, E_NUM), 256>>>();
    // 10) routed down
    gemm_i8<2, false><<<dim3(16, 16, E_NUM), 256, GSMEM_BYTES>>>(
        guh, gul, sgu, (long long)T_TOK * I_DIM, T_TOK, 1408,
        w2h, w2l, sw2, (long long)H_DIM * I_DIM, H_DIM,
        pDown, (long long)T_TOK * H_DIM, H_DIM, 0, 1408, nullptr, 0);
    // 11) shared GU
    gemm_i8<0, false><<<dim3(44, 16, 1), 256, GSMEM_BYTES>>>(
        X2h, X2l, sX2, 0, 0, 2048, sgh, sgl, ssg, 0, 0, pSgu, 0, SH2, T_TOK, 2048, nullptr, 0);
    // 12) shared act + quant
    act_shared_q<<<T_TOK, 256>>>();
    // 13) out = act @ sh_dn^T + hid
    gemm_i8<0, true><<<dim3(16, 16, 1), 256, GSMEM_BYTES>>>(
        sah, sal, ssa, 0, 0, 2816, sdh, sdl, ssd, 0, 0, out, 0, H_DIM, T_TOK, 2816, pHid, H_DIM);
    // 14) out += weighted routed contributions
    final_sum<<<T_TOK, 256>>>(out);
}

// round 7
// speedup vs baseline: 2.1425x; 2.1425x over previous
#include <cuda_runtime.h>
#include <cuda_fp16.h>
#include <cstdint>
#include <math.h>

#define T_TOK 2048
#define H_DIM 2048
#define S_LEN 1024
#define E_NUM 16
#define I_DIM 1408
#define TWO_I 2816
#define SHI_DIM 2816
#define SH2 5632

// ---------------- fp32 scratch ----------------
__device__ float g_Q   [(size_t)T_TOK * 2048];
__device__ float g_KV  [(size_t)T_TOK * 4096];
__device__ float g_hid [(size_t)T_TOK * H_DIM];
__device__ float g_X2  [(size_t)T_TOK * H_DIM];
__device__ float g_sgu [(size_t)T_TOK * SH2];
__device__ float g_gu  [(size_t)E_NUM * T_TOK * TWO_I];
__device__ float g_down[(size_t)E_NUM * T_TOK * H_DIM];
__device__ int   g_cnt [E_NUM];
__device__ int   g_tok [E_NUM * T_TOK];
__device__ int   g_texp[T_TOK * 4];
__device__ int   g_trow[T_TOK * 4];
__device__ float g_twt [T_TOK * 4];

// ---------------- fp16 hi/lo planes (lo pre-scaled x1024) ----------------
__device__ __half c_Xh [(size_t)T_TOK * H_DIM],   c_Xl [(size_t)T_TOK * H_DIM];
__device__ __half c_ath[(size_t)T_TOK * 2048],    c_atl[(size_t)T_TOK * 2048];
__device__ __half c_X2h[(size_t)T_TOK * H_DIM],   c_X2l[(size_t)T_TOK * H_DIM];
__device__ __half c_guh[(size_t)E_NUM * T_TOK * I_DIM], c_gul[(size_t)E_NUM * T_TOK * I_DIM];
__device__ __half c_sah[(size_t)T_TOK * SHI_DIM], c_sal[(size_t)T_TOK * SHI_DIM];
__device__ __half c_qwh[(size_t)2048 * 2048],     c_qwl[(size_t)2048 * 2048];
__device__ __half c_kvh[(size_t)4096 * 2048],     c_kvl[(size_t)4096 * 2048];
__device__ __half c_owh[(size_t)2048 * 2048],     c_owl[(size_t)2048 * 2048];
__device__ __half c_w1h[(size_t)E_NUM * TWO_I * H_DIM], c_w1l[(size_t)E_NUM * TWO_I * H_DIM];
__device__ __half c_w2h[(size_t)E_NUM * H_DIM * I_DIM], c_w2l[(size_t)E_NUM * H_DIM * I_DIM];
__device__ __half c_sgh[(size_t)SH2 * H_DIM],     c_sgl[(size_t)SH2 * H_DIM];
__device__ __half c_sdh[(size_t)H_DIM * SHI_DIM], c_sdl[(size_t)H_DIM * SHI_DIM];

#define CORR_SCALE 0.0009765625f   // 1/1024

// ================= helpers =================
static __device__ __forceinline__ uint32_t smem_u32(const void* p) {
    uint32_t a;
    asm("{ .reg .u64 t; cvta.to.shared.u64 t, %1; cvt.u32.u64 %0, t; }" : "=r"(a) : "l"(p));
    return a;
}
// pack fp16 hi/lo (lo scaled x1024) for 2 floats
static __device__ __forceinline__ void hl2(float x, float y, uint32_t& h, uint32_t& l) {
    __half hx = __float2half_rn(x), hy = __float2half_rn(y);
    float lx = (x - __half2float(hx)) * 1024.f;
    float ly = (y - __half2float(hy)) * 1024.f;
    __half2 hp = __halves2half2(hx, hy);
    __half2 lp = __halves2half2(__float2half_rn(lx), __float2half_rn(ly));
    h = *(uint32_t*)&hp; l = *(uint32_t*)&lp;
}
#define LDM4(r, a) \
    asm volatile("ldmatrix.sync.aligned.m8n8.x4.shared.b16 {%0,%1,%2,%3}, [%4];" \
        : "=r"((r)[0]), "=r"((r)[1]), "=r"((r)[2]), "=r"((r)[3]) : "r"(a))
#define MMAF32(c, a, b0, b1) \
    asm volatile("mma.sync.aligned.m16n8k16.row.col.f32.f16.f16.f32 " \
        "{%0,%1,%2,%3}, {%4,%5,%6,%7}, {%8,%9}, {%0,%1,%2,%3};" \
        : "+f"((c)[0]), "+f"((c)[1]), "+f"((c)[2]), "+f"((c)[3]) \
        : "r"((a)[0]), "r"((a)[1]), "r"((a)[2]), "r"((a)[3]), "r"(b0), "r"(b1))
#define MMAF16(c, a, b0, b1) \
    asm volatile("mma.sync.aligned.m16n8k16.row.col.f16.f16.f16.f16 " \
        "{%0,%1}, {%2,%3,%4,%5}, {%6,%7}, {%0,%1};" \
        : "+r"((c)[0]), "+r"((c)[1]) \
        : "r"((a)[0]), "r"((a)[1]), "r"((a)[2]), "r"((a)[3]), "r"(b0), "r"(b1))
#define CPA16(d, s, n) \
    asm volatile("cp.async.cg.shared.global [%0], [%1], 16, %2;" :: "r"(d), "l"(s), "r"(n) : "memory")
#define CPA_COMMIT() asm volatile("cp.async.commit_group;" ::: "memory")
#define CPA_WAIT2()  asm volatile("cp.async.wait_group 2;" ::: "memory")

// ================= fp16 conversion (weights + generic rows) =================
__global__ void __launch_bounds__(256) convW(const float* __restrict__ src,
                                             __half* __restrict__ dh, __half* __restrict__ dl,
                                             int K, int remap) {
    int row = blockIdx.x, tid = threadIdx.x;
    int sr = remap ? ((row >> 7) * 192 + (row & 127)) : row;
    const float* s = src + (size_t)sr * K;
    for (int i = tid * 4; i < K; i += 1024) {
        float4 v = *(const float4*)(s + i);
        uint32_t h0, l0, h1, l1;
        hl2(v.x, v.y, h0, l0); hl2(v.z, v.w, h1, l1);
        *(uint2*)(dh + (size_t)row * K + i) = make_uint2(h0, h1);
        *(uint2*)(dl + (size_t)row * K + i) = make_uint2(l0, l1);
    }
}

// ================= HMMA fp16x3 GEMM (f32-acc main, f16-acc corrections) =================
// C[M,N] = A @ W^T (+addsrc). 128x128 tile, BK=32, 8 warps, 4-stage cp.async ring.
// Stage: Ah[128x80B] Al Bh Bl (10240B each) = 40960B; 4 stages = 160KB.
#define GSMEM_BYTES (4 * 40960)

template <int MODE, bool ADD>
__global__ void __launch_bounds__(256, 1) gemm_h(
    const __half* __restrict__ Ahp, const __half* __restrict__ Alp,
    long long aestride, int lda,
    const __half* __restrict__ Bhp, const __half* __restrict__ Blp,
    long long bestride,
    float* __restrict__ C, long long cstride, int ldc,
    int M, int K,
    const float* __restrict__ addsrc, int ldadd)
{
    extern __shared__ char smem[];
    const int e  = blockIdx.z;
    const int Me = (MODE == 0) ? M : g_cnt[e];
    const int bm = blockIdx.y * 128, bn = blockIdx.x * 128;
    if (bm >= Me) return;
    const __half* AhB = Ahp + (MODE == 2 ? (long long)e * aestride : 0LL);
    const __half* AlB = Alp + (MODE == 2 ? (long long)e * aestride : 0LL);
    const __half* BhB = Bhp + (long long)e * bestride;
    const __half* BlB = Blp + (long long)e * bestride;
    float* Cb = C + (long long)e * cstride;

    const uint32_t sb = smem_u32(smem);
    const int tid = threadIdx.x, wid = tid >> 5, lid = tid & 31;
    const int wm = wid & 3, wn = wid >> 2;

    uint32_t sOff[2]; uint32_t aval[2];
    const char *aHp[2], *aLp[2], *bHp[2], *bLp[2];
    #pragma unroll
    for (int i = 0; i < 2; i++) {
        int q = tid + i * 256;
        int row = q >> 2, seg = q & 3;
        sOff[i] = (uint32_t)(row * 80 + seg * 16);
        int gm = bm + row;
        aval[i] = (gm < Me) ? 16u : 0u;
        long long arow;
        if (MODE == 1) arow = (gm < Me) ? (long long)g_tok[e * T_TOK + gm] : 0LL;
        else           arow = (gm < Me) ? (long long)gm : 0LL;
        aHp[i] = (const char*)(AhB + arow * (long long)lda) + seg * 16;
        aLp[i] = (const char*)(AlB + arow * (long long)lda) + seg * 16;
        long long brow = (long long)(bn + row);
        bHp[i] = (const char*)(BhB + brow * (long long)lda) + seg * 16;
        bLp[i] = (const char*)(BlB + brow * (long long)lda) + seg * 16;
    }

    const int laneRow = lid & 15, laneChk = lid >> 4;
    uint32_t aOff[2], bOff[4];
    #pragma unroll
    for (int t = 0; t < 2; t++)
        aOff[t] = (uint32_t)((wm * 32 + t * 16 + laneRow) * 80 + laneChk * 16);
    #pragma unroll
    for (int p = 0; p < 4; p++)
        bOff[p] = (uint32_t)(20480 + (wn * 64 + p * 16 + laneRow) * 80 + laneChk * 16);

    float    am[2][8][4];
    uint32_t cc[2][8][2];
    #pragma unroll
    for (int t = 0; t < 2; t++)
        #pragma unroll
        for (int n8 = 0; n8 < 8; n8++) {
            #pragma unroll
            for (int j = 0; j < 4; j++) am[t][n8][j] = 0.f;
            cc[t][n8][0] = 0u; cc[t][n8][1] = 0u;
        }

    const int NC = K / 32;

    #define ISSUE(c) do { \
        uint32_t st_ = sb + (uint32_t)((c) & 3) * 40960u; \
        long long kb_ = (long long)(c) * 64; \
        _Pragma("unroll") \
        for (int i_ = 0; i_ < 2; i_++) { \
            CPA16(st_ + sOff[i_],          aHp[i_] + kb_, aval[i_]); \
            CPA16(st_ + 10240u + sOff[i_], aLp[i_] + kb_, aval[i_]); \
            CPA16(st_ + 20480u + sOff[i_], bHp[i_] + kb_, 16u); \
            CPA16(st_ + 30720u + sOff[i_], bLp[i_] + kb_, 16u); \
        } \
    } while (0)

    ISSUE(0); CPA_COMMIT();
    if (NC > 1) { ISSUE(1); } CPA_COMMIT();
    if (NC > 2) { ISSUE(2); } CPA_COMMIT();

    for (int c = 0; c < NC; c++) {
        CPA_WAIT2();
        __syncthreads();
        const uint32_t stg = sb + (uint32_t)(c & 3) * 40960u;
        #pragma unroll
        for (int h = 0; h < 2; h++) {
            uint32_t ah0[4], ah1[4], al0[4], al1[4];
            LDM4(ah0, stg + aOff[0] + h * 32);
            LDM4(ah1, stg + aOff[1] + h * 32);
            LDM4(al0, stg + aOff[0] + 10240u + h * 32);
            LDM4(al1, stg + aOff[1] + 10240u + h * 32);
            #pragma unroll
            for (int p = 0; p < 4; p++) {
                uint32_t bh[4], bl[4];
                LDM4(bh, stg + bOff[p] + h * 32);
                LDM4(bl, stg + bOff[p] + 10240u + h * 32);
                // main term (f32 acc)
                MMAF32(am[0][2 * p],     ah0, bh[0], bh[2]);
                MMAF32(am[0][2 * p + 1], ah0, bh[1], bh[3]);
                MMAF32(am[1][2 * p],     ah1, bh[0], bh[2]);
                MMAF32(am[1][2 * p + 1], ah1, bh[1], bh[3]);
                // corrections (f16 acc): Al'*Bh + Ah*Bl'  (both x1024)
                MMAF16(cc[0][2 * p],     al0, bh[0], bh[2]);
                MMAF16(cc[0][2 * p + 1], al0, bh[1], bh[3]);
                MMAF16(cc[1][2 * p],     al1, bh[0], bh[2]);
                MMAF16(cc[1][2 * p + 1], al1, bh[1], bh[3]);
                MMAF16(cc[0][2 * p],     ah0, bl[0], bl[2]);
                MMAF16(cc[0][2 * p + 1], ah0, bl[1], bl[3]);
                MMAF16(cc[1][2 * p],     ah1, bl[0], bl[2]);
                MMAF16(cc[1][2 * p + 1], ah1, bl[1], bl[3]);
            }
        }
        __syncthreads();
        if (c + 3 < NC) ISSUE(c + 3);
        CPA_COMMIT();
    }
    #undef ISSUE

    const int g = lid >> 2, tg = lid & 3;
    #pragma unroll
    for (int t = 0; t < 2; t++) {
        #pragma unroll
        for (int half = 0; half < 2; half++) {
            int row = bm + wm * 32 + t * 16 + g + half * 8;
            if (row >= Me) continue;
            float* cp = Cb + (long long)row * ldc + bn + wn * 64 + tg * 2;
            const float* ap = ADD ? (addsrc + (long long)row * ldadd + bn + wn * 64 + tg * 2) : (const float*)0;
            #pragma unroll
            for (int n8 = 0; n8 < 8; n8++) {
                float2 cf = __half22float2(*(__half2*)&cc[t][n8][half]);
                float v0 = am[t][n8][half * 2]     + cf.x * CORR_SCALE;
                float v1 = am[t][n8][half * 2 + 1] + cf.y * CORR_SCALE;
                if (ADD) { v0 += ap[n8 * 8]; v1 += ap[n8 * 8 + 1]; }
                cp[n8 * 8] = v0; cp[n8 * 8 + 1] = v1;
            }
        }
    }
}

// ---------------- rmsnorm (optional fp32 out + fp16 planes) ----------------
__global__ __launch_bounds__(256) void rmsnorm_h(const float* __restrict__ in,
                                                 const float* __restrict__ w,
                                                 float* __restrict__ out,
                                                 __half* __restrict__ ph, __half* __restrict__ pl) {
    __shared__ float red[8];
    int t = blockIdx.x, tid = threadIdx.x;
    const float* row = in + (size_t)t * H_DIM;
    float ss = 0.f;
    for (int i = tid; i < H_DIM; i += 256) { float v = row[i]; ss += v * v; }
    #pragma unroll
    for (int o = 16; o; o >>= 1) ss += __shfl_xor_sync(0xffffffffu, ss, o);
    if ((tid & 31) == 0) red[tid >> 5] = ss;
    __syncthreads();
    float tot = red[0] + red[1] + red[2] + red[3] + red[4] + red[5] + red[6] + red[7];
    float inv = rsqrtf(tot * (1.0f / H_DIM) + 1e-6f);
    for (int i = tid * 2; i < H_DIM; i += 512) {
        float a = row[i] * inv * w[i];
        float b = row[i + 1] * inv * w[i + 1];
        if (out) { out[(size_t)t * H_DIM + i] = a; out[(size_t)t * H_DIM + i + 1] = b; }
        uint32_t h, l;
        hl2(a, b, h, l);
        ((uint32_t*)ph)[((size_t)t * H_DIM + i) >> 1] = h;
        ((uint32_t*)pl)[((size_t)t * H_DIM + i) >> 1] = l;
    }
}

// ---------------- flash attention (fp32, causal, D=128; parallel softmax; fp16-plane out) ----------------
__global__ void __launch_bounds__(256) attn_kernel() {
    extern __shared__ float sm[];
    float* Qs = sm;                  // [64][129]
    float* Ks = Qs + 64 * 129;       // [64][129]
    float* Vs = Ks + 64 * 129;       // [64][132]
    float* Ps = Vs + 64 * 132;       // [64][65]
    float* mrow = Ps + 64 * 65;      // 64
    float* lrow = mrow + 64;         // 64
    float* corr = lrow + 64;         // 64
    float* pm4  = corr + 64;         // 64*4
    float* ps4  = pm4 + 256;         // 64*4

    int bh = blockIdx.y; int b = bh >> 4, h = bh & 15;
    int q0 = blockIdx.x * 64;
    int tb = b * S_LEN;
    int tid = threadIdx.x;
    int ty = tid / 16, tx = tid % 16;

    for (int i = tid; i < 64 * 32; i += 256) {
        int r = i >> 5, c4 = (i & 31) * 4;
        float4 v = *(const float4*)(g_Q + (size_t)(tb + q0 + r) * 2048 + h * 128 + c4);
        Qs[r * 129 + c4] = v.x; Qs[r * 129 + c4 + 1] = v.y;
        Qs[r * 129 + c4 + 2] = v.z; Qs[r * 129 + c4 + 3] = v.w;
    }
    if (tid < 64) { mrow[tid] = -1e30f; lrow[tid] = 0.f; }
    float acc[4][8];
    #pragma unroll
    for (int i = 0; i < 4; i++)
        #pragma unroll
        for (int j = 0; j < 8; j++) acc[i][j] = 0.f;
    const float scale = 1.0f / sqrtf(192.0f);
    __syncthreads();

    int nkt = blockIdx.x + 1;
    for (int kt = 0; kt < nkt; kt++) {
        int k0 = kt * 64;
        for (int i = tid; i < 64 * 32; i += 256) {
            int r = i >> 5, c4 = (i & 31) * 4;
            const float* kp = g_KV + (size_t)(tb + k0 + r) * 4096 + h * 128;
            float4 kv4 = *(const float4*)(kp + c4);
            Ks[r * 129 + c4] = kv4.x; Ks[r * 129 + c4 + 1] = kv4.y;
            Ks[r * 129 + c4 + 2] = kv4.z; Ks[r * 129 + c4 + 3] = kv4.w;
            float4 vv4 = *(const float4*)(kp + 2048 + c4);
            Vs[r * 132 + c4] = vv4.x; Vs[r * 132 + c4 + 1] = vv4.y;
            Vs[r * 132 + c4 + 2] = vv4.z; Vs[r * 132 + c4 + 3] = vv4.w;
        }
        __syncthreads();
        float s[4][4];
        #pragma unroll
        for (int i = 0; i < 4; i++)
            #pragma unroll
            for (int j = 0; j < 4; j++) s[i][j] = 0.f;
        #pragma unroll 4
        for (int k = 0; k < 128; k++) {
            float qa[4], kb[4];
            #pragma unroll
            for (int i = 0; i < 4; i++) qa[i] = Qs[(4 * ty + i) * 129 + k];
            #pragma unroll
            for (int j = 0; j < 4; j++) kb[j] = Ks[(4 * tx + j) * 129 + k];
            #pragma unroll
            for (int i = 0; i < 4; i++)
                #pragma unroll
                for (int j = 0; j < 4; j++) s[i][j] += qa[i] * kb[j];
        }
        #pragma unroll
        for (int i = 0; i < 4; i++)
            #pragma unroll
            for (int j = 0; j < 4; j++) {
                int rq = q0 + 4 * ty + i, ck = k0 + 4 * tx + j;
                Ps[(4 * ty + i) * 65 + 4 * tx + j] = (ck <= rq) ? s[i][j] * scale : -1e30f;
            }
        __syncthreads();
        // parallel softmax: 4 threads per row
        {
            int r = tid & 63, qd = tid >> 6;
            float m0 = mrow[r];
            float pm = -1e30f;
            #pragma unroll 4
            for (int c = qd * 16; c < qd * 16 + 16; c++) pm = fmaxf(pm, Ps[r * 65 + c]);
            pm4[r * 4 + qd] = pm;
            __syncthreads();
            float mx = fmaxf(m0, fmaxf(fmaxf(pm4[r * 4], pm4[r * 4 + 1]),
                                       fmaxf(pm4[r * 4 + 2], pm4[r * 4 + 3])));
            float sum = 0.f;
            #pragma unroll 4
            for (int c = qd * 16; c < qd * 16 + 16; c++) {
                float p = __expf(Ps[r * 65 + c] - mx);
                Ps[r * 65 + c] = p; sum += p;
            }
            ps4[r * 4 + qd] = sum;
            __syncthreads();
            if (qd == 0) {
                float cr = __expf(m0 - mx);
                corr[r] = cr;
                lrow[r] = lrow[r] * cr + ps4[r * 4] + ps4[r * 4 + 1] + ps4[r * 4 + 2] + ps4[r * 4 + 3];
                mrow[r] = mx;
            }
        }
        __syncthreads();
        #pragma unroll
        for (int i = 0; i < 4; i++) {
            float cr = corr[4 * ty + i];
            #pragma unroll
            for (int j = 0; j < 8; j++) acc[i][j] *= cr;
        }
        #pragma unroll 2
        for (int c = 0; c < 64; c++) {
            float p[4], v[8];
            #pragma unroll
            for (int i = 0; i < 4; i++) p[i] = Ps[(4 * ty + i) * 65 + c];
            #pragma unroll
            for (int j = 0; j < 8; j++) v[j] = Vs[c * 132 + 8 * tx + j];
            #pragma unroll
            for (int i = 0; i < 4; i++)
                #pragma unroll
                for (int j = 0; j < 8; j++) acc[i][j] += p[i] * v[j];
        }
        __syncthreads();
    }
    #pragma unroll
    for (int i = 0; i < 4; i++) {
        int r = 4 * ty + i;
        float inv = 1.0f / lrow[r];
        float v[8];
        #pragma unroll
        for (int j = 0; j < 8; j++) v[j] = acc[i][j] * inv;
        size_t base = (size_t)(tb + q0 + r) * 2048 + h * 128 + 8 * tx;
        uint32_t h0, l0, h1, l1, h2, l2, h3, l3;
        hl2(v[0], v[1], h0, l0); hl2(v[2], v[3], h1, l1);
        hl2(v[4], v[5], h2, l2); hl2(v[6], v[7], h3, l3);
        *(uint2*)(c_ath + base)     = make_uint2(h0, h1);
        *(uint2*)(c_ath + base + 4) = make_uint2(h2, h3);
        *(uint2*)(c_atl + base)     = make_uint2(l0, l1);
        *(uint2*)(c_atl + base + 4) = make_uint2(l2, l3);
    }
}

// ---------------- gate ----------------
__global__ void __launch_bounds__(512) zero_cnt() { if (threadIdx.x < E_NUM) g_cnt[threadIdx.x] = 0; }

__global__ void __launch_bounds__(512) gate_kernel(const float* __restrict__ gate_w) {
    int t = blockIdx.x;
    int w = threadIdx.x >> 5, lane = threadIdx.x & 31;
    const float* x = g_X2 + (size_t)t * H_DIM;
    const float* gw = gate_w + (size_t)w * H_DIM;
    float s = 0.f;
    for (int i = lane; i < H_DIM; i += 32) s += x[i] * gw[i];
    #pragma unroll
    for (int o = 16; o; o >>= 1) s += __shfl_xor_sync(0xffffffffu, s, o);
    __shared__ float lg[E_NUM];
    if (lane == 0) lg[w] = s;
    __syncthreads();
    if (threadIdx.x == 0) {
        float mx = -1e30f;
        for (int e = 0; e < E_NUM; e++) mx = fmaxf(mx, lg[e]);
        float pe[E_NUM];
        for (int e = 0; e < E_NUM; e++) pe[e] = expf(lg[e] - mx);
        bool used[E_NUM];
        for (int e = 0; e < E_NUM; e++) used[e] = false;
        int sel[4]; float sw[4]; float wsum = 0.f;
        for (int j = 0; j < 4; j++) {
            int bi = -1; float bv = -1.f;
            for (int e = 0; e < E_NUM; e++)
                if (!used[e] && pe[e] > bv) { bv = pe[e]; bi = e; }
            used[bi] = true; sel[j] = bi; sw[j] = bv; wsum += bv;
        }
        for (int j = 0; j < 4; j++) {
            int e = sel[j];
            int pos = atomicAdd(&g_cnt[e], 1);
            g_tok[e * T_TOK + pos] = t;
            g_texp[t * 4 + j] = e;
            g_trow[t * 4 + j] = pos;
            g_twt [t * 4 + j] = sw[j] / wsum;
        }
    }
}

// ---------------- activations (fp16-plane out) ----------------
__device__ __forceinline__ float silu_f(float x) { return x / (1.0f + __expf(-x)); }

__global__ void __launch_bounds__(256) act_moe_h() {
    int e = blockIdx.y, r = blockIdx.x;
    if (r >= g_cnt[e]) return;
    const float* row = g_gu + ((size_t)e * T_TOK + r) * TWO_I;
    size_t pb = ((size_t)e * T_TOK + r) * I_DIM;
    for (int i = threadIdx.x * 2; i < I_DIM; i += 512) {
        float a = silu_f(row[i])     * row[I_DIM + i];
        float b = silu_f(row[i + 1]) * row[I_DIM + i + 1];
        uint32_t h, l;
        hl2(a, b, h, l);
        ((uint32_t*)c_guh)[(pb + i) >> 1] = h;
        ((uint32_t*)c_gul)[(pb + i) >> 1] = l;
    }
}

__global__ void __launch_bounds__(256) act_shared_h() {
    int t = blockIdx.x;
    const float* row = g_sgu + (size_t)t * SH2;
    size_t pb = (size_t)t * SHI_DIM;
    for (int i = threadIdx.x * 2; i < SHI_DIM; i += 512) {
        float a = silu_f(row[i])     * row[SHI_DIM + i];
        float b = silu_f(row[i + 1]) * row[SHI_DIM + i + 1];
        uint32_t h, l;
        hl2(a, b, h, l);
        ((uint32_t*)c_sah)[(pb + i) >> 1] = h;
        ((uint32_t*)c_sal)[(pb + i) >> 1] = l;
    }
}

// ---------------- final sum ----------------
__global__ void __launch_bounds__(256) final_sum(float* __restrict__ out) {
    int t = blockIdx.x;
    int e0 = g_texp[t * 4 + 0], e1 = g_texp[t * 4 + 1], e2 = g_texp[t * 4 + 2], e3 = g_texp[t * 4 + 3];
    int r0 = g_trow[t * 4 + 0], r1 = g_trow[t * 4 + 1], r2 = g_trow[t * 4 + 2], r3 = g_trow[t * 4 + 3];
    float w0 = g_twt[t * 4 + 0], w1v = g_twt[t * 4 + 1], w2v = g_twt[t * 4 + 2], w3 = g_twt[t * 4 + 3];
    const float* d0 = g_down + ((size_t)e0 * T_TOK + r0) * H_DIM;
    const float* d1 = g_down + ((size_t)e1 * T_TOK + r1) * H_DIM;
    const float* d2 = g_down + ((size_t)e2 * T_TOK + r2) * H_DIM;
    const float* d3 = g_down + ((size_t)e3 * T_TOK + r3) * H_DIM;
    for (int h = threadIdx.x; h < H_DIM; h += 256) {
        float v = out[(size_t)t * H_DIM + h];
        v += w0 * d0[h] + w1v * d1[h] + w2v * d2[h] + w3 * d3[h];
        out[(size_t)t * H_DIM + h] = v;
    }
}

// ---------------- launch ----------------
extern "C" void kernel_launch(void* const* d_in, const int* in_sizes, int n_in,
                              void* d_out, int out_size) {
    (void)in_sizes; (void)n_in; (void)out_size;
    const float* hidden  = (const float*)d_in[0];
    const float* ln1_w   = (const float*)d_in[2];
    const float* ln2_w   = (const float*)d_in[3];
    const float* q_w     = (const float*)d_in[4];
    const float* kv_w    = (const float*)d_in[5];
    const float* o_w     = (const float*)d_in[6];
    const float* gate_w  = (const float*)d_in[7];
    const float* w1      = (const float*)d_in[8];
    const float* w2      = (const float*)d_in[9];
    const float* sh_gu_w = (const float*)d_in[10];
    const float* sh_dn_w = (const float*)d_in[11];
    float* out = (float*)d_out;

    static cudaStream_t s1 = nullptr, s2 = nullptr;
    static cudaEvent_t ev[10];
    if (!s1) {
        cudaStreamCreateWithFlags(&s1, cudaStreamNonBlocking);
        cudaStreamCreateWithFlags(&s2, cudaStreamNonBlocking);
        for (int i = 0; i < 10; i++) cudaEventCreateWithFlags(&ev[i], cudaEventDisableTiming);
    }

    float *pQ, *pKV, *pHid, *pX2, *pSgu, *pGu, *pDown;
    cudaGetSymbolAddress((void**)&pQ, g_Q);
    cudaGetSymbolAddress((void**)&pKV, g_KV);
    cudaGetSymbolAddress((void**)&pHid, g_hid);
    cudaGetSymbolAddress((void**)&pX2, g_X2);
    cudaGetSymbolAddress((void**)&pSgu, g_sgu);
    cudaGetSymbolAddress((void**)&pGu, g_gu);
    cudaGetSymbolAddress((void**)&pDown, g_down);

    __half *Xh, *Xl, *ath, *atl, *X2h, *X2l, *guh, *gul, *sah, *sal;
    __half *qwh, *qwl, *kvh, *kvl, *owh, *owl, *w1h, *w1l, *w2h, *w2l, *sgh, *sgl, *sdh, *sdl;
    cudaGetSymbolAddress((void**)&Xh, c_Xh);   cudaGetSymbolAddress((void**)&Xl, c_Xl);
    cudaGetSymbolAddress((void**)&ath, c_ath); cudaGetSymbolAddress((void**)&atl, c_atl);
    cudaGetSymbolAddress((void**)&X2h, c_X2h); cudaGetSymbolAddress((void**)&X2l, c_X2l);
    cudaGetSymbolAddress((void**)&guh, c_guh); cudaGetSymbolAddress((void**)&gul, c_gul);
    cudaGetSymbolAddress((void**)&sah, c_sah); cudaGetSymbolAddress((void**)&sal, c_sal);
    cudaGetSymbolAddress((void**)&qwh, c_qwh); cudaGetSymbolAddress((void**)&qwl, c_qwl);
    cudaGetSymbolAddress((void**)&kvh, c_kvh); cudaGetSymbolAddress((void**)&kvl, c_kvl);
    cudaGetSymbolAddress((void**)&owh, c_owh); cudaGetSymbolAddress((void**)&owl, c_owl);
    cudaGetSymbolAddress((void**)&w1h, c_w1h); cudaGetSymbolAddress((void**)&w1l, c_w1l);
    cudaGetSymbolAddress((void**)&w2h, c_w2h); cudaGetSymbolAddress((void**)&w2l, c_w2l);
    cudaGetSymbolAddress((void**)&sgh, c_sgh); cudaGetSymbolAddress((void**)&sgl, c_sgl);
    cudaGetSymbolAddress((void**)&sdh, c_sdh); cudaGetSymbolAddress((void**)&sdl, c_sdl);

    const int ATTN_SMEM = (64 * 129 * 2 + 64 * 132 + 64 * 65 + 64 * 3 + 512 + 64) * 4;
    cudaFuncSetAttribute(attn_kernel, cudaFuncAttributeMaxDynamicSharedMemorySize, ATTN_SMEM);
    cudaFuncSetAttribute(gemm_h<0, false>, cudaFuncAttributeMaxDynamicSharedMemorySize, GSMEM_BYTES);
    cudaFuncSetAttribute(gemm_h<0, true >, cudaFuncAttributeMaxDynamicSharedMemorySize, GSMEM_BYTES);
    cudaFuncSetAttribute(gemm_h<1, false>, cudaFuncAttributeMaxDynamicSharedMemorySize, GSMEM_BYTES);
    cudaFuncSetAttribute(gemm_h<2, false>, cudaFuncAttributeMaxDynamicSharedMemorySize, GSMEM_BYTES);

    // fork side streams from captured root
    cudaEventRecord(ev[0], 0);
    cudaStreamWaitEvent(s1, ev[0], 0);
    cudaStreamWaitEvent(s2, ev[0], 0);

    // s1: all weight conversions (DRAM-bound; overlap under compute)
    convW<<<2048, 256, 0, s1>>>(q_w, qwh, qwl, 2048, 1);           cudaEventRecord(ev[1], s1);
    convW<<<4096, 256, 0, s1>>>(kv_w, kvh, kvl, 2048, 0);          cudaEventRecord(ev[2], s1);
    convW<<<2048, 256, 0, s1>>>(o_w, owh, owl, 2048, 0);           cudaEventRecord(ev[3], s1);
    convW<<<E_NUM * TWO_I, 256, 0, s1>>>(w1, w1h, w1l, 2048, 0);   cudaEventRecord(ev[4], s1);
    convW<<<SH2, 256, 0, s1>>>(sh_gu_w, sgh, sgl, 2048, 0);        cudaEventRecord(ev[5], s1);
    convW<<<E_NUM * H_DIM, 256, 0, s1>>>(w2, w2h, w2l, 1408, 0);   cudaEventRecord(ev[6], s1);
    convW<<<H_DIM, 256, 0, s1>>>(sh_dn_w, sdh, sdl, 2816, 0);      cudaEventRecord(ev[7], s1);

    // s0 (default): attention path
    rmsnorm_h<<<T_TOK, 256>>>(hidden, ln1_w, nullptr, Xh, Xl);
    cudaStreamWaitEvent(0, ev[1], 0);
    gemm_h<0, false><<<dim3(16, 16, 1), 256, GSMEM_BYTES>>>(
        Xh, Xl, 0LL, 2048, qwh, qwl, 0LL, pQ, 0LL, 2048, T_TOK, 2048, nullptr, 0);
    cudaStreamWaitEvent(0, ev[2], 0);
    gemm_h<0, false><<<dim3(32, 16, 1), 256, GSMEM_BYTES>>>(
        Xh, Xl, 0LL, 2048, kvh, kvl, 0LL, pKV, 0LL, 4096, T_TOK, 2048, nullptr, 0);
    attn_kernel<<<dim3(16, 32), 256, ATTN_SMEM>>>();
    cudaStreamWaitEvent(0, ev[3], 0);
    gemm_h<0, true><<<dim3(16, 16, 1), 256, GSMEM_BYTES>>>(
        ath, atl, 0LL, 2048, owh, owl, 0LL, pHid, 0LL, H_DIM, T_TOK, 2048, hidden, H_DIM);
    rmsnorm_h<<<T_TOK, 256>>>(pHid, ln2_w, pX2, X2h, X2l);
    cudaEventRecord(ev[8], 0);  // X2 ready

    // s2: routed branch
    cudaStreamWaitEvent(s2, ev[8], 0);
    zero_cnt<<<1, 32, 0, s2>>>();
    gate_kernel<<<T_TOK, 512, 0, s2>>>(gate_w);
    cudaStreamWaitEvent(s2, ev[4], 0);
    gemm_h<1, false><<<dim3(22, 16, E_NUM), 256, GSMEM_BYTES, s2>>>(
        X2h, X2l, 0LL, 2048, w1h, w1l, (long long)TWO_I * H_DIM,
        pGu, (long long)T_TOK * TWO_I, TWO_I, 0, 2048, nullptr, 0);
    act_moe_h<<<dim3(T_TOK, E_NUM), 256, 0, s2>>>();
    cudaStreamWaitEvent(s2, ev[6], 0);
    gemm_h<2, false><<<dim3(16, 16, E_NUM), 256, GSMEM_BYTES, s2>>>(
        guh, gul, (long long)T_TOK * I_DIM, 1408, w2h, w2l, (long long)H_DIM * I_DIM,
        pDown, (long long)T_TOK * H_DIM, H_DIM, 0, 1408, nullptr, 0);
    cudaEventRecord(ev[9], s2);

    // s0: shared branch (concurrent with routed)
    cudaStreamWaitEvent(0, ev[5], 0);
    gemm_h<0, false><<<dim3(44, 16, 1), 256, GSMEM_BYTES>>>(
        X2h, X2l, 0LL, 2048, sgh, sgl, 0LL, pSgu, 0LL, SH2, T_TOK, 2048, nullptr, 0);
    act_shared_h<<<T_TOK, 256>>>();
    cudaStreamWaitEvent(0, ev[7], 0);
    gemm_h<0, true><<<dim3(16, 16, 1), 256, GSMEM_BYTES>>>(
        sah, sal, 0LL, 2816, sdh, sdl, 0LL, out, 0LL, H_DIM, T_TOK, 2816, pHid, H_DIM);

    // join routed, final combine
    cudaStreamWaitEvent(0, ev[9], 0);
    final_sum<<<T_TOK, 256>>>(out);
}

// round 8
// speedup vs baseline: 2.7329x; 1.2756x over previous
#include <cuda_runtime.h>
#include <cuda_fp16.h>
#include <cstdint>
#include <math.h>

#define T_TOK 2048
#define H_DIM 2048
#define S_LEN 1024
#define E_NUM 16
#define I_DIM 1408
#define TWO_I 2816
#define SHI_DIM 2816
#define SH2 5632

// ---------------- fp32 scratch ----------------
__device__ float g_Q   [(size_t)T_TOK * 2048];
__device__ float g_KV  [(size_t)T_TOK * 4096];
__device__ float g_hid [(size_t)T_TOK * H_DIM];
__device__ float g_X2  [(size_t)T_TOK * H_DIM];
__device__ float g_sgu [(size_t)T_TOK * SH2];
__device__ float g_gu  [(size_t)E_NUM * T_TOK * TWO_I];
__device__ float g_down[(size_t)E_NUM * T_TOK * H_DIM];
__device__ int   g_cnt [E_NUM];
__device__ int   g_tok [E_NUM * T_TOK];
__device__ int   g_texp[T_TOK * 4];
__device__ int   g_trow[T_TOK * 4];
__device__ float g_twt [T_TOK * 4];

// ---------------- fp16 planes: activations hi/lo (lo x1024), weights hi only ----------------
__device__ __half c_Xh [(size_t)T_TOK * H_DIM],   c_Xl [(size_t)T_TOK * H_DIM];
__device__ __half c_ath[(size_t)T_TOK * 2048],    c_atl[(size_t)T_TOK * 2048];
__device__ __half c_X2h[(size_t)T_TOK * H_DIM],   c_X2l[(size_t)T_TOK * H_DIM];
__device__ __half c_guh[(size_t)E_NUM * T_TOK * I_DIM], c_gul[(size_t)E_NUM * T_TOK * I_DIM];
__device__ __half c_sah[(size_t)T_TOK * SHI_DIM], c_sal[(size_t)T_TOK * SHI_DIM];
__device__ __half c_qwh[(size_t)2048 * 2048];
__device__ __half c_kvh[(size_t)4096 * 2048];
__device__ __half c_owh[(size_t)2048 * 2048];
__device__ __half c_w1h[(size_t)E_NUM * TWO_I * H_DIM];
__device__ __half c_w2h[(size_t)E_NUM * H_DIM * I_DIM];
__device__ __half c_sgh[(size_t)SH2 * H_DIM];
__device__ __half c_sdh[(size_t)H_DIM * SHI_DIM];

#define CORR_SCALE 0.0009765625f   // 1/1024

// ================= helpers =================
static __device__ __forceinline__ uint32_t smem_u32(const void* p) {
    uint32_t a;
    asm("{ .reg .u64 t; cvta.to.shared.u64 t, %1; cvt.u32.u64 %0, t; }" : "=r"(a) : "l"(p));
    return a;
}
// pack fp16 hi/lo (lo scaled x1024) for 2 floats
static __device__ __forceinline__ void hl2(float x, float y, uint32_t& h, uint32_t& l) {
    __half hx = __float2half_rn(x), hy = __float2half_rn(y);
    float lx = (x - __half2float(hx)) * 1024.f;
    float ly = (y - __half2float(hy)) * 1024.f;
    __half2 hp = __halves2half2(hx, hy);
    __half2 lp = __halves2half2(__float2half_rn(lx), __float2half_rn(ly));
    h = *(uint32_t*)&hp; l = *(uint32_t*)&lp;
}
static __device__ __forceinline__ uint32_t h2only(float x, float y) {
    __half2 hp = __halves2half2(__float2half_rn(x), __float2half_rn(y));
    return *(uint32_t*)&hp;
}
#define LDM4(r, a) \
    asm volatile("ldmatrix.sync.aligned.m8n8.x4.shared.b16 {%0,%1,%2,%3}, [%4];" \
        : "=r"((r)[0]), "=r"((r)[1]), "=r"((r)[2]), "=r"((r)[3]) : "r"(a))
#define MMAF32(c, a, b0, b1) \
    asm volatile("mma.sync.aligned.m16n8k16.row.col.f32.f16.f16.f32 " \
        "{%0,%1,%2,%3}, {%4,%5,%6,%7}, {%8,%9}, {%0,%1,%2,%3};" \
        : "+f"((c)[0]), "+f"((c)[1]), "+f"((c)[2]), "+f"((c)[3]) \
        : "r"((a)[0]), "r"((a)[1]), "r"((a)[2]), "r"((a)[3]), "r"(b0), "r"(b1))
#define MMAF16(c, a, b0, b1) \
    asm volatile("mma.sync.aligned.m16n8k16.row.col.f16.f16.f16.f16 " \
        "{%0,%1}, {%2,%3,%4,%5}, {%6,%7}, {%0,%1};" \
        : "+r"((c)[0]), "+r"((c)[1]) \
        : "r"((a)[0]), "r"((a)[1]), "r"((a)[2]), "r"((a)[3]), "r"(b0), "r"(b1))
#define CPA16(d, s, n) \
    asm volatile("cp.async.cg.shared.global [%0], [%1], 16, %2;" :: "r"(d), "l"(s), "r"(n) : "memory")
#define CPA_COMMIT() asm volatile("cp.async.commit_group;" ::: "memory")
#define CPA_WAIT2()  asm volatile("cp.async.wait_group 2;" ::: "memory")

// ================= weight conversion (single fp16 plane) =================
__global__ void __launch_bounds__(256) convW(const float* __restrict__ src,
                                             __half* __restrict__ dh,
                                             int K, int remap) {
    int row = blockIdx.x, tid = threadIdx.x;
    int sr = remap ? ((row >> 7) * 192 + (row & 127)) : row;
    const float* s = src + (size_t)sr * K;
    for (int i = tid * 4; i < K; i += 1024) {
        float4 v = *(const float4*)(s + i);
        *(uint2*)(dh + (size_t)row * K + i) = make_uint2(h2only(v.x, v.y), h2only(v.z, v.w));
    }
}

// ================= HMMA fp16x2 GEMM: main f32-acc + correction f16-acc =================
// C[M,N] = A @ W^T (+addsrc). 128x128 tile, BK=32, 8 warps, 4-stage cp.async ring.
// Stage: Ah[128x80B] Al Bh (10240B each) = 30720B; 4 stages = 122880B.
#define GSMEM_BYTES (4 * 30720)

template <int MODE, bool ADD>
__global__ void __launch_bounds__(256, 1) gemm_h(
    const __half* __restrict__ Ahp, const __half* __restrict__ Alp,
    long long aestride, int lda,
    const __half* __restrict__ Bhp, long long bestride,
    float* __restrict__ C, long long cstride, int ldc,
    int M, int K,
    const float* __restrict__ addsrc, int ldadd)
{
    extern __shared__ char smem[];
    const int e  = blockIdx.z;
    const int Me = (MODE == 0) ? M : g_cnt[e];
    const int bm = blockIdx.y * 128, bn = blockIdx.x * 128;
    if (bm >= Me) return;
    const __half* AhB = Ahp + (MODE == 2 ? (long long)e * aestride : 0LL);
    const __half* AlB = Alp + (MODE == 2 ? (long long)e * aestride : 0LL);
    const __half* BhB = Bhp + (long long)e * bestride;
    float* Cb = C + (long long)e * cstride;

    const uint32_t sb = smem_u32(smem);
    const int tid = threadIdx.x, wid = tid >> 5, lid = tid & 31;
    const int wm = wid & 3, wn = wid >> 2;

    uint32_t sOff[2]; uint32_t aval[2];
    const char *aHp[2], *aLp[2], *bHp[2];
    #pragma unroll
    for (int i = 0; i < 2; i++) {
        int q = tid + i * 256;
        int row = q >> 2, seg = q & 3;
        sOff[i] = (uint32_t)(row * 80 + seg * 16);
        int gm = bm + row;
        aval[i] = (gm < Me) ? 16u : 0u;
        long long arow;
        if (MODE == 1) arow = (gm < Me) ? (long long)g_tok[e * T_TOK + gm] : 0LL;
        else           arow = (gm < Me) ? (long long)gm : 0LL;
        aHp[i] = (const char*)(AhB + arow * (long long)lda) + seg * 16;
        aLp[i] = (const char*)(AlB + arow * (long long)lda) + seg * 16;
        long long brow = (long long)(bn + row);
        bHp[i] = (const char*)(BhB + brow * (long long)lda) + seg * 16;
    }

    const int laneRow = lid & 15, laneChk = lid >> 4;
    uint32_t aOff[2], bOff[4];
    #pragma unroll
    for (int t = 0; t < 2; t++)
        aOff[t] = (uint32_t)((wm * 32 + t * 16 + laneRow) * 80 + laneChk * 16);
    #pragma unroll
    for (int p = 0; p < 4; p++)
        bOff[p] = (uint32_t)(20480 + (wn * 64 + p * 16 + laneRow) * 80 + laneChk * 16);

    float    am[2][8][4];
    uint32_t cc[2][8][2];
    #pragma unroll
    for (int t = 0; t < 2; t++)
        #pragma unroll
        for (int n8 = 0; n8 < 8; n8++) {
            #pragma unroll
            for (int j = 0; j < 4; j++) am[t][n8][j] = 0.f;
            cc[t][n8][0] = 0u; cc[t][n8][1] = 0u;
        }

    const int NC = K / 32;

    #define ISSUE(c) do { \
        uint32_t st_ = sb + (uint32_t)((c) & 3) * 30720u; \
        long long kb_ = (long long)(c) * 64; \
        _Pragma("unroll") \
        for (int i_ = 0; i_ < 2; i_++) { \
            CPA16(st_ + sOff[i_],          aHp[i_] + kb_, aval[i_]); \
            CPA16(st_ + 10240u + sOff[i_], aLp[i_] + kb_, aval[i_]); \
            CPA16(st_ + 20480u + sOff[i_], bHp[i_] + kb_, 16u); \
        } \
    } while (0)

    ISSUE(0); CPA_COMMIT();
    if (NC > 1) { ISSUE(1); } CPA_COMMIT();
    if (NC > 2) { ISSUE(2); } CPA_COMMIT();

    for (int c = 0; c < NC; c++) {
        CPA_WAIT2();
        __syncthreads();
        const uint32_t stg = sb + (uint32_t)(c & 3) * 30720u;
        #pragma unroll
        for (int h = 0; h < 2; h++) {
            uint32_t ah0[4], ah1[4], al0[4], al1[4];
            LDM4(ah0, stg + aOff[0] + h * 32);
            LDM4(ah1, stg + aOff[1] + h * 32);
            LDM4(al0, stg + aOff[0] + 10240u + h * 32);
            LDM4(al1, stg + aOff[1] + 10240u + h * 32);
            #pragma unroll
            for (int p = 0; p < 4; p++) {
                uint32_t bh[4];
                LDM4(bh, stg + bOff[p] + h * 32);
                // main term (f32 acc)
                MMAF32(am[0][2 * p],     ah0, bh[0], bh[2]);
                MMAF32(am[0][2 * p + 1], ah0, bh[1], bh[3]);
                MMAF32(am[1][2 * p],     ah1, bh[0], bh[2]);
                MMAF32(am[1][2 * p + 1], ah1, bh[1], bh[3]);
                // correction (f16 acc): Al' * Bh  (x1024)
                MMAF16(cc[0][2 * p],     al0, bh[0], bh[2]);
                MMAF16(cc[0][2 * p + 1], al0, bh[1], bh[3]);
                MMAF16(cc[1][2 * p],     al1, bh[0], bh[2]);
                MMAF16(cc[1][2 * p + 1], al1, bh[1], bh[3]);
            }
        }
        __syncthreads();
        if (c + 3 < NC) ISSUE(c + 3);
        CPA_COMMIT();
    }
    #undef ISSUE

    const int g = lid >> 2, tg = lid & 3;
    #pragma unroll
    for (int t = 0; t < 2; t++) {
        #pragma unroll
        for (int half = 0; half < 2; half++) {
            int row = bm + wm * 32 + t * 16 + g + half * 8;
            if (row >= Me) continue;
            float* cp = Cb + (long long)row * ldc + bn + wn * 64 + tg * 2;
            const float* ap = ADD ? (addsrc + (long long)row * ldadd + bn + wn * 64 + tg * 2) : (const float*)0;
            #pragma unroll
            for (int n8 = 0; n8 < 8; n8++) {
                float2 cf = __half22float2(*(__half2*)&cc[t][n8][half]);
                float v0 = am[t][n8][half * 2]     + cf.x * CORR_SCALE;
                float v1 = am[t][n8][half * 2 + 1] + cf.y * CORR_SCALE;
                if (ADD) { v0 += ap[n8 * 8]; v1 += ap[n8 * 8 + 1]; }
                cp[n8 * 8] = v0; cp[n8 * 8 + 1] = v1;
            }
        }
    }
}

// ---------------- rmsnorm (optional fp32 out + fp16 planes) ----------------
__global__ __launch_bounds__(256) void rmsnorm_h(const float* __restrict__ in,
                                                 const float* __restrict__ w,
                                                 float* __restrict__ out,
                                                 __half* __restrict__ ph, __half* __restrict__ pl) {
    __shared__ float red[8];
    int t = blockIdx.x, tid = threadIdx.x;
    const float* row = in + (size_t)t * H_DIM;
    float ss = 0.f;
    for (int i = tid; i < H_DIM; i += 256) { float v = row[i]; ss += v * v; }
    #pragma unroll
    for (int o = 16; o; o >>= 1) ss += __shfl_xor_sync(0xffffffffu, ss, o);
    if ((tid & 31) == 0) red[tid >> 5] = ss;
    __syncthreads();
    float tot = red[0] + red[1] + red[2] + red[3] + red[4] + red[5] + red[6] + red[7];
    float inv = rsqrtf(tot * (1.0f / H_DIM) + 1e-6f);
    for (int i = tid * 2; i < H_DIM; i += 512) {
        float a = row[i] * inv * w[i];
        float b = row[i + 1] * inv * w[i + 1];
        if (out) { out[(size_t)t * H_DIM + i] = a; out[(size_t)t * H_DIM + i + 1] = b; }
        uint32_t h, l;
        hl2(a, b, h, l);
        ((uint32_t*)ph)[((size_t)t * H_DIM + i) >> 1] = h;
        ((uint32_t*)pl)[((size_t)t * H_DIM + i) >> 1] = l;
    }
}

// ---------------- flash attention (fp32, causal, D=128; parallel softmax; fp16-plane out) ----------------
__global__ void __launch_bounds__(256) attn_kernel() {
    extern __shared__ float sm[];
    float* Qs = sm;
    float* Ks = Qs + 64 * 129;
    float* Vs = Ks + 64 * 129;
    float* Ps = Vs + 64 * 132;
    float* mrow = Ps + 64 * 65;
    float* lrow = mrow + 64;
    float* corr = lrow + 64;
    float* pm4  = corr + 64;
    float* ps4  = pm4 + 256;

    int bh = blockIdx.y; int b = bh >> 4, h = bh & 15;
    int q0 = blockIdx.x * 64;
    int tb = b * S_LEN;
    int tid = threadIdx.x;
    int ty = tid / 16, tx = tid % 16;

    for (int i = tid; i < 64 * 32; i += 256) {
        int r = i >> 5, c4 = (i & 31) * 4;
        float4 v = *(const float4*)(g_Q + (size_t)(tb + q0 + r) * 2048 + h * 128 + c4);
        Qs[r * 129 + c4] = v.x; Qs[r * 129 + c4 + 1] = v.y;
        Qs[r * 129 + c4 + 2] = v.z; Qs[r * 129 + c4 + 3] = v.w;
    }
    if (tid < 64) { mrow[tid] = -1e30f; lrow[tid] = 0.f; }
    float acc[4][8];
    #pragma unroll
    for (int i = 0; i < 4; i++)
        #pragma unroll
        for (int j = 0; j < 8; j++) acc[i][j] = 0.f;
    const float scale = 1.0f / sqrtf(192.0f);
    __syncthreads();

    int nkt = blockIdx.x + 1;
    for (int kt = 0; kt < nkt; kt++) {
        int k0 = kt * 64;
        for (int i = tid; i < 64 * 32; i += 256) {
            int r = i >> 5, c4 = (i & 31) * 4;
            const float* kp = g_KV + (size_t)(tb + k0 + r) * 4096 + h * 128;
            float4 kv4 = *(const float4*)(kp + c4);
            Ks[r * 129 + c4] = kv4.x; Ks[r * 129 + c4 + 1] = kv4.y;
            Ks[r * 129 + c4 + 2] = kv4.z; Ks[r * 129 + c4 + 3] = kv4.w;
            float4 vv4 = *(const float4*)(kp + 2048 + c4);
            Vs[r * 132 + c4] = vv4.x; Vs[r * 132 + c4 + 1] = vv4.y;
            Vs[r * 132 + c4 + 2] = vv4.z; Vs[r * 132 + c4 + 3] = vv4.w;
        }
        __syncthreads();
        float s[4][4];
        #pragma unroll
        for (int i = 0; i < 4; i++)
            #pragma unroll
            for (int j = 0; j < 4; j++) s[i][j] = 0.f;
        #pragma unroll 4
        for (int k = 0; k < 128; k++) {
            float qa[4], kb[4];
            #pragma unroll
            for (int i = 0; i < 4; i++) qa[i] = Qs[(4 * ty + i) * 129 + k];
            #pragma unroll
            for (int j = 0; j < 4; j++) kb[j] = Ks[(4 * tx + j) * 129 + k];
            #pragma unroll
            for (int i = 0; i < 4; i++)
                #pragma unroll
                for (int j = 0; j < 4; j++) s[i][j] += qa[i] * kb[j];
        }
        #pragma unroll
        for (int i = 0; i < 4; i++)
            #pragma unroll
            for (int j = 0; j < 4; j++) {
                int rq = q0 + 4 * ty + i, ck = k0 + 4 * tx + j;
                Ps[(4 * ty + i) * 65 + 4 * tx + j] = (ck <= rq) ? s[i][j] * scale : -1e30f;
            }
        __syncthreads();
        {
            int r = tid & 63, qd = tid >> 6;
            float m0 = mrow[r];
            float pm = -1e30f;
            #pragma unroll 4
            for (int c = qd * 16; c < qd * 16 + 16; c++) pm = fmaxf(pm, Ps[r * 65 + c]);
            pm4[r * 4 + qd] = pm;
            __syncthreads();
            float mx = fmaxf(m0, fmaxf(fmaxf(pm4[r * 4], pm4[r * 4 + 1]),
                                       fmaxf(pm4[r * 4 + 2], pm4[r * 4 + 3])));
            float sum = 0.f;
            #pragma unroll 4
            for (int c = qd * 16; c < qd * 16 + 16; c++) {
                float p = __expf(Ps[r * 65 + c] - mx);
                Ps[r * 65 + c] = p; sum += p;
            }
            ps4[r * 4 + qd] = sum;
            __syncthreads();
            if (qd == 0) {
                float cr = __expf(m0 - mx);
                corr[r] = cr;
                lrow[r] = lrow[r] * cr + ps4[r * 4] + ps4[r * 4 + 1] + ps4[r * 4 + 2] + ps4[r * 4 + 3];
                mrow[r] = mx;
            }
        }
        __syncthreads();
        #pragma unroll
        for (int i = 0; i < 4; i++) {
            float cr = corr[4 * ty + i];
            #pragma unroll
            for (int j = 0; j < 8; j++) acc[i][j] *= cr;
        }
        #pragma unroll 2
        for (int c = 0; c < 64; c++) {
            float p[4], v[8];
            #pragma unroll
            for (int i = 0; i < 4; i++) p[i] = Ps[(4 * ty + i) * 65 + c];
            #pragma unroll
            for (int j = 0; j < 8; j++) v[j] = Vs[c * 132 + 8 * tx + j];
            #pragma unroll
            for (int i = 0; i < 4; i++)
                #pragma unroll
                for (int j = 0; j < 8; j++) acc[i][j] += p[i] * v[j];
        }
        __syncthreads();
    }
    #pragma unroll
    for (int i = 0; i < 4; i++) {
        int r = 4 * ty + i;
        float inv = 1.0f / lrow[r];
        float v[8];
        #pragma unroll
        for (int j = 0; j < 8; j++) v[j] = acc[i][j] * inv;
        size_t base = (size_t)(tb + q0 + r) * 2048 + h * 128 + 8 * tx;
        uint32_t h0, l0, h1, l1, h2, l2, h3, l3;
        hl2(v[0], v[1], h0, l0); hl2(v[2], v[3], h1, l1);
        hl2(v[4], v[5], h2, l2); hl2(v[6], v[7], h3, l3);
        *(uint2*)(c_ath + base)     = make_uint2(h0, h1);
        *(uint2*)(c_ath + base + 4) = make_uint2(h2, h3);
        *(uint2*)(c_atl + base)     = make_uint2(l0, l1);
        *(uint2*)(c_atl + base + 4) = make_uint2(l2, l3);
    }
}

// ---------------- gate ----------------
__global__ void __launch_bounds__(512) zero_cnt() { if (threadIdx.x < E_NUM) g_cnt[threadIdx.x] = 0; }

__global__ void __launch_bounds__(512) gate_kernel(const float* __restrict__ gate_w) {
    int t = blockIdx.x;
    int w = threadIdx.x >> 5, lane = threadIdx.x & 31;
    const float* x = g_X2 + (size_t)t * H_DIM;
    const float* gw = gate_w + (size_t)w * H_DIM;
    float s = 0.f;
    for (int i = lane; i < H_DIM; i += 32) s += x[i] * gw[i];
    #pragma unroll
    for (int o = 16; o; o >>= 1) s += __shfl_xor_sync(0xffffffffu, s, o);
    __shared__ float lg[E_NUM];
    if (lane == 0) lg[w] = s;
    __syncthreads();
    if (threadIdx.x == 0) {
        float mx = -1e30f;
        for (int e = 0; e < E_NUM; e++) mx = fmaxf(mx, lg[e]);
        float pe[E_NUM];
        for (int e = 0; e < E_NUM; e++) pe[e] = expf(lg[e] - mx);
        bool used[E_NUM];
        for (int e = 0; e < E_NUM; e++) used[e] = false;
        int sel[4]; float sw[4]; float wsum = 0.f;
        for (int j = 0; j < 4; j++) {
            int bi = -1; float bv = -1.f;
            for (int e = 0; e < E_NUM; e++)
                if (!used[e] && pe[e] > bv) { bv = pe[e]; bi = e; }
            used[bi] = true; sel[j] = bi; sw[j] = bv; wsum += bv;
        }
        for (int j = 0; j < 4; j++) {
            int e = sel[j];
            int pos = atomicAdd(&g_cnt[e], 1);
            g_tok[e * T_TOK + pos] = t;
            g_texp[t * 4 + j] = e;
            g_trow[t * 4 + j] = pos;
            g_twt [t * 4 + j] = sw[j] / wsum;
        }
    }
}

// ---------------- activations (fp16-plane out) ----------------
__device__ __forceinline__ float silu_f(float x) { return x / (1.0f + __expf(-x)); }

__global__ void __launch_bounds__(256) act_moe_h() {
    int e = blockIdx.y, r = blockIdx.x;
    if (r >= g_cnt[e]) return;
    const float* row = g_gu + ((size_t)e * T_TOK + r) * TWO_I;
    size_t pb = ((size_t)e * T_TOK + r) * I_DIM;
    for (int i = threadIdx.x * 2; i < I_DIM; i += 512) {
        float a = silu_f(row[i])     * row[I_DIM + i];
        float b = silu_f(row[i + 1]) * row[I_DIM + i + 1];
        uint32_t h, l;
        hl2(a, b, h, l);
        ((uint32_t*)c_guh)[(pb + i) >> 1] = h;
        ((uint32_t*)c_gul)[(pb + i) >> 1] = l;
    }
}

__global__ void __launch_bounds__(256) act_shared_h() {
    int t = blockIdx.x;
    const float* row = g_sgu + (size_t)t * SH2;
    size_t pb = (size_t)t * SHI_DIM;
    for (int i = threadIdx.x * 2; i < SHI_DIM; i += 512) {
        float a = silu_f(row[i])     * row[SHI_DIM + i];
        float b = silu_f(row[i + 1]) * row[SHI_DIM + i + 1];
        uint32_t h, l;
        hl2(a, b, h, l);
        ((uint32_t*)c_sah)[(pb + i) >> 1] = h;
        ((uint32_t*)c_sal)[(pb + i) >> 1] = l;
    }
}

// ---------------- final sum ----------------
__global__ void __launch_bounds__(256) final_sum(float* __restrict__ out) {
    int t = blockIdx.x;
    int e0 = g_texp[t * 4 + 0], e1 = g_texp[t * 4 + 1], e2 = g_texp[t * 4 + 2], e3 = g_texp[t * 4 + 3];
    int r0 = g_trow[t * 4 + 0], r1 = g_trow[t * 4 + 1], r2 = g_trow[t * 4 + 2], r3 = g_trow[t * 4 + 3];
    float w0 = g_twt[t * 4 + 0], w1v = g_twt[t * 4 + 1], w2v = g_twt[t * 4 + 2], w3 = g_twt[t * 4 + 3];
    const float* d0 = g_down + ((size_t)e0 * T_TOK + r0) * H_DIM;
    const float* d1 = g_down + ((size_t)e1 * T_TOK + r1) * H_DIM;
    const float* d2 = g_down + ((size_t)e2 * T_TOK + r2) * H_DIM;
    const float* d3 = g_down + ((size_t)e3 * T_TOK + r3) * H_DIM;
    for (int h = threadIdx.x; h < H_DIM; h += 256) {
        float v = out[(size_t)t * H_DIM + h];
        v += w0 * d0[h] + w1v * d1[h] + w2v * d2[h] + w3 * d3[h];
        out[(size_t)t * H_DIM + h] = v;
    }
}

// ---------------- launch ----------------
extern "C" void kernel_launch(void* const* d_in, const int* in_sizes, int n_in,
                              void* d_out, int out_size) {
    (void)in_sizes; (void)n_in; (void)out_size;
    const float* hidden  = (const float*)d_in[0];
    const float* ln1_w   = (const float*)d_in[2];
    const float* ln2_w   = (const float*)d_in[3];
    const float* q_w     = (const float*)d_in[4];
    const float* kv_w    = (const float*)d_in[5];
    const float* o_w     = (const float*)d_in[6];
    const float* gate_w  = (const float*)d_in[7];
    const float* w1      = (const float*)d_in[8];
    const float* w2      = (const float*)d_in[9];
    const float* sh_gu_w = (const float*)d_in[10];
    const float* sh_dn_w = (const float*)d_in[11];
    float* out = (float*)d_out;

    static cudaStream_t s1 = nullptr, s2 = nullptr;
    static cudaEvent_t ev[10];
    if (!s1) {
        cudaStreamCreateWithFlags(&s1, cudaStreamNonBlocking);
        cudaStreamCreateWithFlags(&s2, cudaStreamNonBlocking);
        for (int i = 0; i < 10; i++) cudaEventCreateWithFlags(&ev[i], cudaEventDisableTiming);
    }

    float *pQ, *pKV, *pHid, *pX2, *pSgu, *pGu, *pDown;
    cudaGetSymbolAddress((void**)&pQ, g_Q);
    cudaGetSymbolAddress((void**)&pKV, g_KV);
    cudaGetSymbolAddress((void**)&pHid, g_hid);
    cudaGetSymbolAddress((void**)&pX2, g_X2);
    cudaGetSymbolAddress((void**)&pSgu, g_sgu);
    cudaGetSymbolAddress((void**)&pGu, g_gu);
    cudaGetSymbolAddress((void**)&pDown, g_down);

    __half *Xh, *Xl, *ath, *atl, *X2h, *X2l, *guh, *gul, *sah, *sal;
    __half *qwh, *kvh, *owh, *w1h, *w2h, *sgh, *sdh;
    cudaGetSymbolAddress((void**)&Xh, c_Xh);   cudaGetSymbolAddress((void**)&Xl, c_Xl);
    cudaGetSymbolAddress((void**)&ath, c_ath); cudaGetSymbolAddress((void**)&atl, c_atl);
    cudaGetSymbolAddress((void**)&X2h, c_X2h); cudaGetSymbolAddress((void**)&X2l, c_X2l);
    cudaGetSymbolAddress((void**)&guh, c_guh); cudaGetSymbolAddress((void**)&gul, c_gul);
    cudaGetSymbolAddress((void**)&sah, c_sah); cudaGetSymbolAddress((void**)&sal, c_sal);
    cudaGetSymbolAddress((void**)&qwh, c_qwh);
    cudaGetSymbolAddress((void**)&kvh, c_kvh);
    cudaGetSymbolAddress((void**)&owh, c_owh);
    cudaGetSymbolAddress((void**)&w1h, c_w1h);
    cudaGetSymbolAddress((void**)&w2h, c_w2h);
    cudaGetSymbolAddress((void**)&sgh, c_sgh);
    cudaGetSymbolAddress((void**)&sdh, c_sdh);

    const int ATTN_SMEM = (64 * 129 * 2 + 64 * 132 + 64 * 65 + 64 * 3 + 512 + 64) * 4;
    cudaFuncSetAttribute(attn_kernel, cudaFuncAttributeMaxDynamicSharedMemorySize, ATTN_SMEM);
    cudaFuncSetAttribute(gemm_h<0, false>, cudaFuncAttributeMaxDynamicSharedMemorySize, GSMEM_BYTES);
    cudaFuncSetAttribute(gemm_h<0, true >, cudaFuncAttributeMaxDynamicSharedMemorySize, GSMEM_BYTES);
    cudaFuncSetAttribute(gemm_h<1, false>, cudaFuncAttributeMaxDynamicSharedMemorySize, GSMEM_BYTES);
    cudaFuncSetAttribute(gemm_h<2, false>, cudaFuncAttributeMaxDynamicSharedMemorySize, GSMEM_BYTES);

    // fork side streams from captured root
    cudaEventRecord(ev[0], 0);
    cudaStreamWaitEvent(s1, ev[0], 0);
    cudaStreamWaitEvent(s2, ev[0], 0);

    // s1: weight conversions (DRAM-bound; overlap under compute)
    convW<<<2048, 256, 0, s1>>>(q_w, qwh, 2048, 1);           cudaEventRecord(ev[1], s1);
    convW<<<4096, 256, 0, s1>>>(kv_w, kvh, 2048, 0);          cudaEventRecord(ev[2], s1);
    convW<<<2048, 256, 0, s1>>>(o_w, owh, 2048, 0);           cudaEventRecord(ev[3], s1);
    convW<<<E_NUM * TWO_I, 256, 0, s1>>>(w1, w1h, 2048, 0);   cudaEventRecord(ev[4], s1);
    convW<<<SH2, 256, 0, s1>>>(sh_gu_w, sgh, 2048, 0);        cudaEventRecord(ev[5], s1);
    convW<<<E_NUM * H_DIM, 256, 0, s1>>>(w2, w2h, 1408, 0);   cudaEventRecord(ev[6], s1);
    convW<<<H_DIM, 256, 0, s1>>>(sh_dn_w, sdh, 2816, 0);      cudaEventRecord(ev[7], s1);

    // s0: attention path
    rmsnorm_h<<<T_TOK, 256>>>(hidden, ln1_w, nullptr, Xh, Xl);
    cudaStreamWaitEvent(0, ev[1], 0);
    gemm_h<0, false><<<dim3(16, 16, 1), 256, GSMEM_BYTES>>>(
        Xh, Xl, 0LL, 2048, qwh, 0LL, pQ, 0LL, 2048, T_TOK, 2048, nullptr, 0);
    cudaStreamWaitEvent(0, ev[2], 0);
    gemm_h<0, false><<<dim3(32, 16, 1), 256, GSMEM_BYTES>>>(
        Xh, Xl, 0LL, 2048, kvh, 0LL, pKV, 0LL, 4096, T_TOK, 2048, nullptr, 0);
    attn_kernel<<<dim3(16, 32), 256, ATTN_SMEM>>>();
    cudaStreamWaitEvent(0, ev[3], 0);
    gemm_h<0, true><<<dim3(16, 16, 1), 256, GSMEM_BYTES>>>(
        ath, atl, 0LL, 2048, owh, 0LL, pHid, 0LL, H_DIM, T_TOK, 2048, hidden, H_DIM);
    rmsnorm_h<<<T_TOK, 256>>>(pHid, ln2_w, pX2, X2h, X2l);
    cudaEventRecord(ev[8], 0);  // X2 ready

    // s2: routed branch
    cudaStreamWaitEvent(s2, ev[8], 0);
    zero_cnt<<<1, 32, 0, s2>>>();
    gate_kernel<<<T_TOK, 512, 0, s2>>>(gate_w);
    cudaStreamWaitEvent(s2, ev[4], 0);
    gemm_h<1, false><<<dim3(22, 16, E_NUM), 256, GSMEM_BYTES, s2>>>(
        X2h, X2l, 0LL, 2048, w1h, (long long)TWO_I * H_DIM,
        pGu, (long long)T_TOK * TWO_I, TWO_I, 0, 2048, nullptr, 0);
    act_moe_h<<<dim3(T_TOK, E_NUM), 256, 0, s2>>>();
    cudaStreamWaitEvent(s2, ev[6], 0);
    gemm_h<2, false><<<dim3(16, 16, E_NUM), 256, GSMEM_BYTES, s2>>>(
        guh, gul, (long long)T_TOK * I_DIM, 1408, w2h, (long long)H_DIM * I_DIM,
        pDown, (long long)T_TOK * H_DIM, H_DIM, 0, 1408, nullptr, 0);
    cudaEventRecord(ev[9], s2);

    // s0: shared branch (concurrent with routed)
    cudaStreamWaitEvent(0, ev[5], 0);
    gemm_h<0, false><<<dim3(44, 16, 1), 256, GSMEM_BYTES>>>(
        X2h, X2l, 0LL, 2048, sgh, 0LL, pSgu, 0LL, SH2, T_TOK, 2048, nullptr, 0);
    act_shared_h<<<T_TOK, 256>>>();
    cudaStreamWaitEvent(0, ev[7], 0);
    gemm_h<0, true><<<dim3(16, 16, 1), 256, GSMEM_BYTES>>>(
        sah, sal, 0LL, 2816, sdh, 0LL, out, 0LL, H_DIM, T_TOK, 2816, pHid, H_DIM);

    // join routed, final combine
    cudaStreamWaitEvent(0, ev[9], 0);
    final_sum<<<T_TOK, 256>>>(out);
}

// round 9
// speedup vs baseline: 4.3916x; 1.6069x over previous
#include <cuda_runtime.h>
#include <cuda_fp16.h>
#include <cstdint>
#include <math.h>

#define T_TOK 2048
#define H_DIM 2048
#define S_LEN 1024
#define E_NUM 16
#define I_DIM 1408
#define TWO_I 2816
#define SHI_DIM 2816
#define SH2 5632

// ---------------- fp32 scratch ----------------
__device__ float g_Q   [(size_t)T_TOK * 2048];
__device__ float g_KV  [(size_t)T_TOK * 4096];
__device__ float g_hid [(size_t)T_TOK * H_DIM];
__device__ float g_X2  [(size_t)T_TOK * H_DIM];
__device__ float g_sgu [(size_t)T_TOK * SH2];
__device__ float g_gu  [(size_t)E_NUM * T_TOK * TWO_I];
__device__ float g_down[(size_t)E_NUM * T_TOK * H_DIM];
__device__ int   g_cnt [E_NUM];
__device__ int   g_tok [E_NUM * T_TOK];
__device__ int   g_texp[T_TOK * 4];
__device__ int   g_trow[T_TOK * 4];
__device__ float g_twt [T_TOK * 4];

// ---------------- fp16 planes (single, rn-rounded) ----------------
__device__ __half c_Xh [(size_t)T_TOK * H_DIM];
__device__ __half c_ath[(size_t)T_TOK * 2048];
__device__ __half c_X2h[(size_t)T_TOK * H_DIM];
__device__ __half c_guh[(size_t)E_NUM * T_TOK * I_DIM];
__device__ __half c_sah[(size_t)T_TOK * SHI_DIM];
__device__ __half c_qwh[(size_t)2048 * 2048];
__device__ __half c_kvh[(size_t)4096 * 2048];
__device__ __half c_owh[(size_t)2048 * 2048];
__device__ __half c_w1h[(size_t)E_NUM * TWO_I * H_DIM];
__device__ __half c_w2h[(size_t)E_NUM * H_DIM * I_DIM];
__device__ __half c_sgh[(size_t)SH2 * H_DIM];
__device__ __half c_sdh[(size_t)H_DIM * SHI_DIM];

// ================= helpers =================
static __device__ __forceinline__ uint32_t smem_u32(const void* p) {
    uint32_t a;
    asm("{ .reg .u64 t; cvta.to.shared.u64 t, %1; cvt.u32.u64 %0, t; }" : "=r"(a) : "l"(p));
    return a;
}
static __device__ __forceinline__ uint32_t h2only(float x, float y) {
    __half2 hp = __halves2half2(__float2half_rn(x), __float2half_rn(y));
    return *(uint32_t*)&hp;
}
#define LDM4(r, a) \
    asm volatile("ldmatrix.sync.aligned.m8n8.x4.shared.b16 {%0,%1,%2,%3}, [%4];" \
        : "=r"((r)[0]), "=r"((r)[1]), "=r"((r)[2]), "=r"((r)[3]) : "r"(a))
#define MMAF32(c, a, b0, b1) \
    asm volatile("mma.sync.aligned.m16n8k16.row.col.f32.f16.f16.f32 " \
        "{%0,%1,%2,%3}, {%4,%5,%6,%7}, {%8,%9}, {%0,%1,%2,%3};" \
        : "+f"((c)[0]), "+f"((c)[1]), "+f"((c)[2]), "+f"((c)[3]) \
        : "r"((a)[0]), "r"((a)[1]), "r"((a)[2]), "r"((a)[3]), "r"(b0), "r"(b1))
#define CPA16(d, s, n) \
    asm volatile("cp.async.cg.shared.global [%0], [%1], 16, %2;" :: "r"(d), "l"(s), "r"(n) : "memory")
#define CPA_COMMIT() asm volatile("cp.async.commit_group;" ::: "memory")
#define CPA_WAIT2()  asm volatile("cp.async.wait_group 2;" ::: "memory")

// ================= weight conversion (single fp16 plane) =================
__global__ void __launch_bounds__(256) convW(const float* __restrict__ src,
                                             __half* __restrict__ dh,
                                             int K, int remap) {
    int row = blockIdx.x, tid = threadIdx.x;
    int sr = remap ? ((row >> 7) * 192 + (row & 127)) : row;
    const float* s = src + (size_t)sr * K;
    for (int i = tid * 4; i < K; i += 1024) {
        float4 v = *(const float4*)(s + i);
        *(uint2*)(dh + (size_t)row * K + i) = make_uint2(h2only(v.x, v.y), h2only(v.z, v.w));
    }
}

// ================= HMMA fp16 GEMM (single term, f32-acc) =================
// C[M,N] = A @ W^T (+addsrc). 128x128 tile, BK=32, 8 warps, 4-stage cp.async ring.
// Stage: Ah[128x80B] Bh (10240B each) = 20480B; 4 stages = 81920B.
#define GSMEM_BYTES (4 * 20480)

template <int MODE, bool ADD>
__global__ void __launch_bounds__(256, 1) gemm_h(
    const __half* __restrict__ Ahp, long long aestride, int lda,
    const __half* __restrict__ Bhp, long long bestride,
    float* __restrict__ C, long long cstride, int ldc,
    int M, int K,
    const float* __restrict__ addsrc, int ldadd)
{
    extern __shared__ char smem[];
    const int e  = blockIdx.z;
    const int Me = (MODE == 0) ? M : g_cnt[e];
    const int bm = blockIdx.y * 128, bn = blockIdx.x * 128;
    if (bm >= Me) return;
    const __half* AhB = Ahp + (MODE == 2 ? (long long)e * aestride : 0LL);
    const __half* BhB = Bhp + (long long)e * bestride;
    float* Cb = C + (long long)e * cstride;

    const uint32_t sb = smem_u32(smem);
    const int tid = threadIdx.x, wid = tid >> 5, lid = tid & 31;
    const int wm = wid & 3, wn = wid >> 2;

    uint32_t sOff[2]; uint32_t aval[2];
    const char *aHp[2], *bHp[2];
    #pragma unroll
    for (int i = 0; i < 2; i++) {
        int q = tid + i * 256;
        int row = q >> 2, seg = q & 3;
        sOff[i] = (uint32_t)(row * 80 + seg * 16);
        int gm = bm + row;
        aval[i] = (gm < Me) ? 16u : 0u;
        long long arow;
        if (MODE == 1) arow = (gm < Me) ? (long long)g_tok[e * T_TOK + gm] : 0LL;
        else           arow = (gm < Me) ? (long long)gm : 0LL;
        aHp[i] = (const char*)(AhB + arow * (long long)lda) + seg * 16;
        long long brow = (long long)(bn + row);
        bHp[i] = (const char*)(BhB + brow * (long long)lda) + seg * 16;
    }

    const int laneRow = lid & 15, laneChk = lid >> 4;
    uint32_t aOff[2], bOff[4];
    #pragma unroll
    for (int t = 0; t < 2; t++)
        aOff[t] = (uint32_t)((wm * 32 + t * 16 + laneRow) * 80 + laneChk * 16);
    #pragma unroll
    for (int p = 0; p < 4; p++)
        bOff[p] = (uint32_t)(10240 + (wn * 64 + p * 16 + laneRow) * 80 + laneChk * 16);

    float am[2][8][4];
    #pragma unroll
    for (int t = 0; t < 2; t++)
        #pragma unroll
        for (int n8 = 0; n8 < 8; n8++)
            #pragma unroll
            for (int j = 0; j < 4; j++) am[t][n8][j] = 0.f;

    const int NC = K / 32;

    #define ISSUE(c) do { \
        uint32_t st_ = sb + (uint32_t)((c) & 3) * 20480u; \
        long long kb_ = (long long)(c) * 64; \
        _Pragma("unroll") \
        for (int i_ = 0; i_ < 2; i_++) { \
            CPA16(st_ + sOff[i_],          aHp[i_] + kb_, aval[i_]); \
            CPA16(st_ + 10240u + sOff[i_], bHp[i_] + kb_, 16u); \
        } \
    } while (0)

    ISSUE(0); CPA_COMMIT();
    if (NC > 1) { ISSUE(1); } CPA_COMMIT();
    if (NC > 2) { ISSUE(2); } CPA_COMMIT();

    for (int c = 0; c < NC; c++) {
        CPA_WAIT2();
        __syncthreads();
        const uint32_t stg = sb + (uint32_t)(c & 3) * 20480u;
        #pragma unroll
        for (int h = 0; h < 2; h++) {
            uint32_t ah0[4], ah1[4];
            LDM4(ah0, stg + aOff[0] + h * 32);
            LDM4(ah1, stg + aOff[1] + h * 32);
            #pragma unroll
            for (int p = 0; p < 4; p++) {
                uint32_t bh[4];
                LDM4(bh, stg + bOff[p] + h * 32);
                MMAF32(am[0][2 * p],     ah0, bh[0], bh[2]);
                MMAF32(am[0][2 * p + 1], ah0, bh[1], bh[3]);
                MMAF32(am[1][2 * p],     ah1, bh[0], bh[2]);
                MMAF32(am[1][2 * p + 1], ah1, bh[1], bh[3]);
            }
        }
        __syncthreads();
        if (c + 3 < NC) ISSUE(c + 3);
        CPA_COMMIT();
    }
    #undef ISSUE

    const int g = lid >> 2, tg = lid & 3;
    #pragma unroll
    for (int t = 0; t < 2; t++) {
        #pragma unroll
        for (int half = 0; half < 2; half++) {
            int row = bm + wm * 32 + t * 16 + g + half * 8;
            if (row >= Me) continue;
            float* cp = Cb + (long long)row * ldc + bn + wn * 64 + tg * 2;
            const float* ap = ADD ? (addsrc + (long long)row * ldadd + bn + wn * 64 + tg * 2) : (const float*)0;
            #pragma unroll
            for (int n8 = 0; n8 < 8; n8++) {
                float v0 = am[t][n8][half * 2], v1 = am[t][n8][half * 2 + 1];
                if (ADD) { v0 += ap[n8 * 8]; v1 += ap[n8 * 8 + 1]; }
                cp[n8 * 8] = v0; cp[n8 * 8 + 1] = v1;
            }
        }
    }
}

// ---------------- rmsnorm (optional fp32 out + fp16 plane) ----------------
__global__ __launch_bounds__(256) void rmsnorm_h(const float* __restrict__ in,
                                                 const float* __restrict__ w,
                                                 float* __restrict__ out,
                                                 __half* __restrict__ ph) {
    __shared__ float red[8];
    int t = blockIdx.x, tid = threadIdx.x;
    const float* row = in + (size_t)t * H_DIM;
    float ss = 0.f;
    for (int i = tid; i < H_DIM; i += 256) { float v = row[i]; ss += v * v; }
    #pragma unroll
    for (int o = 16; o; o >>= 1) ss += __shfl_xor_sync(0xffffffffu, ss, o);
    if ((tid & 31) == 0) red[tid >> 5] = ss;
    __syncthreads();
    float tot = red[0] + red[1] + red[2] + red[3] + red[4] + red[5] + red[6] + red[7];
    float inv = rsqrtf(tot * (1.0f / H_DIM) + 1e-6f);
    for (int i = tid * 2; i < H_DIM; i += 512) {
        float a = row[i] * inv * w[i];
        float b = row[i + 1] * inv * w[i + 1];
        if (out) { out[(size_t)t * H_DIM + i] = a; out[(size_t)t * H_DIM + i + 1] = b; }
        ((uint32_t*)ph)[((size_t)t * H_DIM + i) >> 1] = h2only(a, b);
    }
}

// ---------------- flash attention (fp32, causal, D=128; parallel softmax; fp16-plane out) ----------------
__global__ void __launch_bounds__(256) attn_kernel() {
    extern __shared__ float sm[];
    float* Qs = sm;
    float* Ks = Qs + 64 * 129;
    float* Vs = Ks + 64 * 129;
    float* Ps = Vs + 64 * 132;
    float* mrow = Ps + 64 * 65;
    float* lrow = mrow + 64;
    float* corr = lrow + 64;
    float* pm4  = corr + 64;
    float* ps4  = pm4 + 256;

    int bh = blockIdx.y; int b = bh >> 4, h = bh & 15;
    int q0 = blockIdx.x * 64;
    int tb = b * S_LEN;
    int tid = threadIdx.x;
    int ty = tid / 16, tx = tid % 16;

    for (int i = tid; i < 64 * 32; i += 256) {
        int r = i >> 5, c4 = (i & 31) * 4;
        float4 v = *(const float4*)(g_Q + (size_t)(tb + q0 + r) * 2048 + h * 128 + c4);
        Qs[r * 129 + c4] = v.x; Qs[r * 129 + c4 + 1] = v.y;
        Qs[r * 129 + c4 + 2] = v.z; Qs[r * 129 + c4 + 3] = v.w;
    }
    if (tid < 64) { mrow[tid] = -1e30f; lrow[tid] = 0.f; }
    float acc[4][8];
    #pragma unroll
    for (int i = 0; i < 4; i++)
        #pragma unroll
        for (int j = 0; j < 8; j++) acc[i][j] = 0.f;
    const float scale = 1.0f / sqrtf(192.0f);
    __syncthreads();

    int nkt = blockIdx.x + 1;
    for (int kt = 0; kt < nkt; kt++) {
        int k0 = kt * 64;
        for (int i = tid; i < 64 * 32; i += 256) {
            int r = i >> 5, c4 = (i & 31) * 4;
            const float* kp = g_KV + (size_t)(tb + k0 + r) * 4096 + h * 128;
            float4 kv4 = *(const float4*)(kp + c4);
            Ks[r * 129 + c4] = kv4.x; Ks[r * 129 + c4 + 1] = kv4.y;
            Ks[r * 129 + c4 + 2] = kv4.z; Ks[r * 129 + c4 + 3] = kv4.w;
            float4 vv4 = *(const float4*)(kp + 2048 + c4);
            Vs[r * 132 + c4] = vv4.x; Vs[r * 132 + c4 + 1] = vv4.y;
            Vs[r * 132 + c4 + 2] = vv4.z; Vs[r * 132 + c4 + 3] = vv4.w;
        }
        __syncthreads();
        float s[4][4];
        #pragma unroll
        for (int i = 0; i < 4; i++)
            #pragma unroll
            for (int j = 0; j < 4; j++) s[i][j] = 0.f;
        #pragma unroll 4
        for (int k = 0; k < 128; k++) {
            float qa[4], kb[4];
            #pragma unroll
            for (int i = 0; i < 4; i++) qa[i] = Qs[(4 * ty + i) * 129 + k];
            #pragma unroll
            for (int j = 0; j < 4; j++) kb[j] = Ks[(4 * tx + j) * 129 + k];
            #pragma unroll
            for (int i = 0; i < 4; i++)
                #pragma unroll
                for (int j = 0; j < 4; j++) s[i][j] += qa[i] * kb[j];
        }
        #pragma unroll
        for (int i = 0; i < 4; i++)
            #pragma unroll
            for (int j = 0; j < 4; j++) {
                int rq = q0 + 4 * ty + i, ck = k0 + 4 * tx + j;
                Ps[(4 * ty + i) * 65 + 4 * tx + j] = (ck <= rq) ? s[i][j] * scale : -1e30f;
            }
        __syncthreads();
        {
            int r = tid & 63, qd = tid >> 6;
            float m0 = mrow[r];
            float pm = -1e30f;
            #pragma unroll 4
            for (int c = qd * 16; c < qd * 16 + 16; c++) pm = fmaxf(pm, Ps[r * 65 + c]);
            pm4[r * 4 + qd] = pm;
            __syncthreads();
            float mx = fmaxf(m0, fmaxf(fmaxf(pm4[r * 4], pm4[r * 4 + 1]),
                                       fmaxf(pm4[r * 4 + 2], pm4[r * 4 + 3])));
            float sum = 0.f;
            #pragma unroll 4
            for (int c = qd * 16; c < qd * 16 + 16; c++) {
                float p = __expf(Ps[r * 65 + c] - mx);
                Ps[r * 65 + c] = p; sum += p;
            }
            ps4[r * 4 + qd] = sum;
            __syncthreads();
            if (qd == 0) {
                float cr = __expf(m0 - mx);
                corr[r] = cr;
                lrow[r] = lrow[r] * cr + ps4[r * 4] + ps4[r * 4 + 1] + ps4[r * 4 + 2] + ps4[r * 4 + 3];
                mrow[r] = mx;
            }
        }
        __syncthreads();
        #pragma unroll
        for (int i = 0; i < 4; i++) {
            float cr = corr[4 * ty + i];
            #pragma unroll
            for (int j = 0; j < 8; j++) acc[i][j] *= cr;
        }
        #pragma unroll 2
        for (int c = 0; c < 64; c++) {
            float p[4], v[8];
            #pragma unroll
            for (int i = 0; i < 4; i++) p[i] = Ps[(4 * ty + i) * 65 + c];
            #pragma unroll
            for (int j = 0; j < 8; j++) v[j] = Vs[c * 132 + 8 * tx + j];
            #pragma unroll
            for (int i = 0; i < 4; i++)
                #pragma unroll
                for (int j = 0; j < 8; j++) acc[i][j] += p[i] * v[j];
        }
        __syncthreads();
    }
    #pragma unroll
    for (int i = 0; i < 4; i++) {
        int r = 4 * ty + i;
        float inv = 1.0f / lrow[r];
        float v[8];
        #pragma unroll
        for (int j = 0; j < 8; j++) v[j] = acc[i][j] * inv;
        size_t base = (size_t)(tb + q0 + r) * 2048 + h * 128 + 8 * tx;
        *(uint2*)(c_ath + base)     = make_uint2(h2only(v[0], v[1]), h2only(v[2], v[3]));
        *(uint2*)(c_ath + base + 4) = make_uint2(h2only(v[4], v[5]), h2only(v[6], v[7]));
    }
}

// ---------------- gate ----------------
__global__ void __launch_bounds__(512) zero_cnt() { if (threadIdx.x < E_NUM) g_cnt[threadIdx.x] = 0; }

__global__ void __launch_bounds__(512) gate_kernel(const float* __restrict__ gate_w) {
    int t = blockIdx.x;
    int w = threadIdx.x >> 5, lane = threadIdx.x & 31;
    const float* x = g_X2 + (size_t)t * H_DIM;
    const float* gw = gate_w + (size_t)w * H_DIM;
    float s = 0.f;
    for (int i = lane; i < H_DIM; i += 32) s += x[i] * gw[i];
    #pragma unroll
    for (int o = 16; o; o >>= 1) s += __shfl_xor_sync(0xffffffffu, s, o);
    __shared__ float lg[E_NUM];
    if (lane == 0) lg[w] = s;
    __syncthreads();
    if (threadIdx.x == 0) {
        float mx = -1e30f;
        for (int e = 0; e < E_NUM; e++) mx = fmaxf(mx, lg[e]);
        float pe[E_NUM];
        for (int e = 0; e < E_NUM; e++) pe[e] = expf(lg[e] - mx);
        bool used[E_NUM];
        for (int e = 0; e < E_NUM; e++) used[e] = false;
        int sel[4]; float sw[4]; float wsum = 0.f;
        for (int j = 0; j < 4; j++) {
            int bi = -1; float bv = -1.f;
            for (int e = 0; e < E_NUM; e++)
                if (!used[e] && pe[e] > bv) { bv = pe[e]; bi = e; }
            used[bi] = true; sel[j] = bi; sw[j] = bv; wsum += bv;
        }
        for (int j = 0; j < 4; j++) {
            int e = sel[j];
            int pos = atomicAdd(&g_cnt[e], 1);
            g_tok[e * T_TOK + pos] = t;
            g_texp[t * 4 + j] = e;
            g_trow[t * 4 + j] = pos;
            g_twt [t * 4 + j] = sw[j] / wsum;
        }
    }
}

// ---------------- activations (fp16-plane out) ----------------
__device__ __forceinline__ float silu_f(float x) { return x / (1.0f + __expf(-x)); }

__global__ void __launch_bounds__(256) act_moe_h() {
    int e = blockIdx.y, r = blockIdx.x;
    if (r >= g_cnt[e]) return;
    const float* row = g_gu + ((size_t)e * T_TOK + r) * TWO_I;
    size_t pb = ((size_t)e * T_TOK + r) * I_DIM;
    for (int i = threadIdx.x * 2; i < I_DIM; i += 512) {
        float a = silu_f(row[i])     * row[I_DIM + i];
        float b = silu_f(row[i + 1]) * row[I_DIM + i + 1];
        ((uint32_t*)c_guh)[(pb + i) >> 1] = h2only(a, b);
    }
}

__global__ void __launch_bounds__(256) act_shared_h() {
    int t = blockIdx.x;
    const float* row = g_sgu + (size_t)t * SH2;
    size_t pb = (size_t)t * SHI_DIM;
    for (int i = threadIdx.x * 2; i < SHI_DIM; i += 512) {
        float a = silu_f(row[i])     * row[SHI_DIM + i];
        float b = silu_f(row[i + 1]) * row[SHI_DIM + i + 1];
        ((uint32_t*)c_sah)[(pb + i) >> 1] = h2only(a, b);
    }
}

// ---------------- final sum ----------------
__global__ void __launch_bounds__(256) final_sum(float* __restrict__ out) {
    int t = blockIdx.x;
    int e0 = g_texp[t * 4 + 0], e1 = g_texp[t * 4 + 1], e2 = g_texp[t * 4 + 2], e3 = g_texp[t * 4 + 3];
    int r0 = g_trow[t * 4 + 0], r1 = g_trow[t * 4 + 1], r2 = g_trow[t * 4 + 2], r3 = g_trow[t * 4 + 3];
    float w0 = g_twt[t * 4 + 0], w1v = g_twt[t * 4 + 1], w2v = g_twt[t * 4 + 2], w3 = g_twt[t * 4 + 3];
    const float* d0 = g_down + ((size_t)e0 * T_TOK + r0) * H_DIM;
    const float* d1 = g_down + ((size_t)e1 * T_TOK + r1) * H_DIM;
    const float* d2 = g_down + ((size_t)e2 * T_TOK + r2) * H_DIM;
    const float* d3 = g_down + ((size_t)e3 * T_TOK + r3) * H_DIM;
    for (int h = threadIdx.x; h < H_DIM; h += 256) {
        float v = out[(size_t)t * H_DIM + h];
        v += w0 * d0[h] + w1v * d1[h] + w2v * d2[h] + w3 * d3[h];
        out[(size_t)t * H_DIM + h] = v;
    }
}

// ---------------- launch ----------------
extern "C" void kernel_launch(void* const* d_in, const int* in_sizes, int n_in,
                              void* d_out, int out_size) {
    (void)in_sizes; (void)n_in; (void)out_size;
    const float* hidden  = (const float*)d_in[0];
    const float* ln1_w   = (const float*)d_in[2];
    const float* ln2_w   = (const float*)d_in[3];
    const float* q_w     = (const float*)d_in[4];
    const float* kv_w    = (const float*)d_in[5];
    const float* o_w     = (const float*)d_in[6];
    const float* gate_w  = (const float*)d_in[7];
    const float* w1      = (const float*)d_in[8];
    const float* w2      = (const float*)d_in[9];
    const float* sh_gu_w = (const float*)d_in[10];
    const float* sh_dn_w = (const float*)d_in[11];
    float* out = (float*)d_out;

    static cudaStream_t s1 = nullptr, s2 = nullptr;
    static cudaEvent_t ev[10];
    if (!s1) {
        cudaStreamCreateWithFlags(&s1, cudaStreamNonBlocking);
        cudaStreamCreateWithFlags(&s2, cudaStreamNonBlocking);
        for (int i = 0; i < 10; i++) cudaEventCreateWithFlags(&ev[i], cudaEventDisableTiming);
    }

    float *pQ, *pKV, *pHid, *pX2, *pSgu, *pGu, *pDown;
    cudaGetSymbolAddress((void**)&pQ, g_Q);
    cudaGetSymbolAddress((void**)&pKV, g_KV);
    cudaGetSymbolAddress((void**)&pHid, g_hid);
    cudaGetSymbolAddress((void**)&pX2, g_X2);
    cudaGetSymbolAddress((void**)&pSgu, g_sgu);
    cudaGetSymbolAddress((void**)&pGu, g_gu);
    cudaGetSymbolAddress((void**)&pDown, g_down);

    __half *Xh, *ath, *X2h, *guh, *sah;
    __half *qwh, *kvh, *owh, *w1h, *w2h, *sgh, *sdh;
    cudaGetSymbolAddress((void**)&Xh, c_Xh);
    cudaGetSymbolAddress((void**)&ath, c_ath);
    cudaGetSymbolAddress((void**)&X2h, c_X2h);
    cudaGetSymbolAddress((void**)&guh, c_guh);
    cudaGetSymbolAddress((void**)&sah, c_sah);
    cudaGetSymbolAddress((void**)&qwh, c_qwh);
    cudaGetSymbolAddress((void**)&kvh, c_kvh);
    cudaGetSymbolAddress((void**)&owh, c_owh);
    cudaGetSymbolAddress((void**)&w1h, c_w1h);
    cudaGetSymbolAddress((void**)&w2h, c_w2h);
    cudaGetSymbolAddress((void**)&sgh, c_sgh);
    cudaGetSymbolAddress((void**)&sdh, c_sdh);

    const int ATTN_SMEM = (64 * 129 * 2 + 64 * 132 + 64 * 65 + 64 * 3 + 512 + 64) * 4;
    cudaFuncSetAttribute(attn_kernel, cudaFuncAttributeMaxDynamicSharedMemorySize, ATTN_SMEM);
    cudaFuncSetAttribute(gemm_h<0, false>, cudaFuncAttributeMaxDynamicSharedMemorySize, GSMEM_BYTES);
    cudaFuncSetAttribute(gemm_h<0, true >, cudaFuncAttributeMaxDynamicSharedMemorySize, GSMEM_BYTES);
    cudaFuncSetAttribute(gemm_h<1, false>, cudaFuncAttributeMaxDynamicSharedMemorySize, GSMEM_BYTES);
    cudaFuncSetAttribute(gemm_h<2, false>, cudaFuncAttributeMaxDynamicSharedMemorySize, GSMEM_BYTES);

    // fork side streams from captured root
    cudaEventRecord(ev[0], 0);
    cudaStreamWaitEvent(s1, ev[0], 0);
    cudaStreamWaitEvent(s2, ev[0], 0);

    // s1: weight conversions (DRAM-bound; overlap under compute)
    convW<<<2048, 256, 0, s1>>>(q_w, qwh, 2048, 1);           cudaEventRecord(ev[1], s1);
    convW<<<4096, 256, 0, s1>>>(kv_w, kvh, 2048, 0);          cudaEventRecord(ev[2], s1);
    convW<<<2048, 256, 0, s1>>>(o_w, owh, 2048, 0);           cudaEventRecord(ev[3], s1);
    convW<<<E_NUM * TWO_I, 256, 0, s1>>>(w1, w1h, 2048, 0);   cudaEventRecord(ev[4], s1);
    convW<<<SH2, 256, 0, s1>>>(sh_gu_w, sgh, 2048, 0);        cudaEventRecord(ev[5], s1);
    convW<<<E_NUM * H_DIM, 256, 0, s1>>>(w2, w2h, 1408, 0);   cudaEventRecord(ev[6], s1);
    convW<<<H_DIM, 256, 0, s1>>>(sh_dn_w, sdh, 2816, 0);      cudaEventRecord(ev[7], s1);

    // s0: attention path
    rmsnorm_h<<<T_TOK, 256>>>(hidden, ln1_w, nullptr, Xh);
    cudaStreamWaitEvent(0, ev[1], 0);
    gemm_h<0, false><<<dim3(16, 16, 1), 256, GSMEM_BYTES>>>(
        Xh, 0LL, 2048, qwh, 0LL, pQ, 0LL, 2048, T_TOK, 2048, nullptr, 0);
    cudaStreamWaitEvent(0, ev[2], 0);
    gemm_h<0, false><<<dim3(32, 16, 1), 256, GSMEM_BYTES>>>(
        Xh, 0LL, 2048, kvh, 0LL, pKV, 0LL, 4096, T_TOK, 2048, nullptr, 0);
    attn_kernel<<<dim3(16, 32), 256, ATTN_SMEM>>>();
    cudaStreamWaitEvent(0, ev[3], 0);
    gemm_h<0, true><<<dim3(16, 16, 1), 256, GSMEM_BYTES>>>(
        ath, 0LL, 2048, owh, 0LL, pHid, 0LL, H_DIM, T_TOK, 2048, hidden, H_DIM);
    rmsnorm_h<<<T_TOK, 256>>>(pHid, ln2_w, pX2, X2h);
    cudaEventRecord(ev[8], 0);  // X2 ready

    // s2: routed branch
    cudaStreamWaitEvent(s2, ev[8], 0);
    zero_cnt<<<1, 32, 0, s2>>>();
    gate_kernel<<<T_TOK, 512, 0, s2>>>(gate_w);
    cudaStreamWaitEvent(s2, ev[4], 0);
    gemm_h<1, false><<<dim3(22, 16, E_NUM), 256, GSMEM_BYTES, s2>>>(
        X2h, 0LL, 2048, w1h, (long long)TWO_I * H_DIM,
        pGu, (long long)T_TOK * TWO_I, TWO_I, 0, 2048, nullptr, 0);
    act_moe_h<<<dim3(T_TOK, E_NUM), 256, 0, s2>>>();
    cudaStreamWaitEvent(s2, ev[6], 0);
    gemm_h<2, false><<<dim3(16, 16, E_NUM), 256, GSMEM_BYTES, s2>>>(
        guh, (long long)T_TOK * I_DIM, 1408, w2h, (long long)H_DIM * I_DIM,
        pDown, (long long)T_TOK * H_DIM, H_DIM, 0, 1408, nullptr, 0);
    cudaEventRecord(ev[9], s2);

    // s0: shared branch (concurrent with routed)
    cudaStreamWaitEvent(0, ev[5], 0);
    gemm_h<0, false><<<dim3(44, 16, 1), 256, GSMEM_BYTES>>>(
        X2h, 0LL, 2048, sgh, 0LL, pSgu, 0LL, SH2, T_TOK, 2048, nullptr, 0);
    act_shared_h<<<T_TOK, 256>>>();
    cudaStreamWaitEvent(0, ev[7], 0);
    gemm_h<0, true><<<dim3(16, 16, 1), 256, GSMEM_BYTES>>>(
        sah, 0LL, 2816, sdh, 0LL, out, 0LL, H_DIM, T_TOK, 2816, pHid, H_DIM);

    // join routed, final combine
    cudaStreamWaitEvent(0, ev[9], 0);
    final_sum<<<T_TOK, 256>>>(out);
}

// round 10
// speedup vs baseline: 5.7699x; 1.3138x over previous
#include <cuda_runtime.h>
#include <cuda_fp16.h>
#include <cstdint>
#include <math.h>

#define T_TOK 2048
#define H_DIM 2048
#define S_LEN 1024
#define E_NUM 16
#define I_DIM 1408
#define TWO_I 2816
#define SHI_DIM 2816
#define SH2 5632

// ---------------- fp32 scratch ----------------
__device__ float g_hid [(size_t)T_TOK * H_DIM];
__device__ float g_X2  [(size_t)T_TOK * H_DIM];
__device__ float g_sgu [(size_t)T_TOK * SH2];
__device__ float g_gu  [(size_t)E_NUM * T_TOK * TWO_I];
__device__ float g_down[(size_t)E_NUM * T_TOK * H_DIM];
__device__ int   g_cnt [E_NUM];
__device__ int   g_tok [E_NUM * T_TOK];
__device__ int   g_texp[T_TOK * 4];
__device__ int   g_trow[T_TOK * 4];
__device__ float g_twt [T_TOK * 4];

// ---------------- fp16 planes ----------------
__device__ __half c_Xh [(size_t)T_TOK * H_DIM];
__device__ __half c_qo [(size_t)T_TOK * 2048];   // Q projection out (fp16)
__device__ __half c_kvo[(size_t)T_TOK * 4096];   // KV projection out (fp16)
__device__ __half c_ath[(size_t)T_TOK * 2048];
__device__ __half c_X2h[(size_t)T_TOK * H_DIM];
__device__ __half c_guh[(size_t)E_NUM * T_TOK * I_DIM];
__device__ __half c_sah[(size_t)T_TOK * SHI_DIM];
__device__ __half c_qwh[(size_t)2048 * 2048];
__device__ __half c_kvh[(size_t)4096 * 2048];
__device__ __half c_owh[(size_t)2048 * 2048];
__device__ __half c_w1h[(size_t)E_NUM * TWO_I * H_DIM];
__device__ __half c_w2h[(size_t)E_NUM * H_DIM * I_DIM];
__device__ __half c_sgh[(size_t)SH2 * H_DIM];
__device__ __half c_sdh[(size_t)H_DIM * SHI_DIM];

// ================= helpers =================
static __device__ __forceinline__ uint32_t smem_u32(const void* p) {
    uint32_t a;
    asm("{ .reg .u64 t; cvta.to.shared.u64 t, %1; cvt.u32.u64 %0, t; }" : "=r"(a) : "l"(p));
    return a;
}
static __device__ __forceinline__ uint32_t h2only(float x, float y) {
    __half2 hp = __halves2half2(__float2half_rn(x), __float2half_rn(y));
    return *(uint32_t*)&hp;
}
#define LDM4(r, a) \
    asm volatile("ldmatrix.sync.aligned.m8n8.x4.shared.b16 {%0,%1,%2,%3}, [%4];" \
        : "=r"((r)[0]), "=r"((r)[1]), "=r"((r)[2]), "=r"((r)[3]) : "r"(a))
#define MMAF32(c, a, b0, b1) \
    asm volatile("mma.sync.aligned.m16n8k16.row.col.f32.f16.f16.f32 " \
        "{%0,%1,%2,%3}, {%4,%5,%6,%7}, {%8,%9}, {%0,%1,%2,%3};" \
        : "+f"((c)[0]), "+f"((c)[1]), "+f"((c)[2]), "+f"((c)[3]) \
        : "r"((a)[0]), "r"((a)[1]), "r"((a)[2]), "r"((a)[3]), "r"(b0), "r"(b1))
#define CPA16(d, s, n) \
    asm volatile("cp.async.cg.shared.global [%0], [%1], 16, %2;" :: "r"(d), "l"(s), "r"(n) : "memory")
#define CPA_COMMIT() asm volatile("cp.async.commit_group;" ::: "memory")
#define CPA_WAIT2()  asm volatile("cp.async.wait_group 2;" ::: "memory")

// ================= weight conversion =================
__global__ void __launch_bounds__(256) convW(const float* __restrict__ src,
                                             __half* __restrict__ dh,
                                             int K, int remap) {
    int row = blockIdx.x, tid = threadIdx.x;
    int sr = remap ? ((row >> 7) * 192 + (row & 127)) : row;
    const float* s = src + (size_t)sr * K;
    for (int i = tid * 4; i < K; i += 1024) {
        float4 v = *(const float4*)(s + i);
        *(uint2*)(dh + (size_t)row * K + i) = make_uint2(h2only(v.x, v.y), h2only(v.z, v.w));
    }
}

// ================= HMMA fp16 GEMM (single term, f32-acc) =================
#define GSMEM_BYTES (4 * 20480)

template <int MODE, bool ADD, bool OUTH>
__global__ void __launch_bounds__(256, 1) gemm_h(
    const __half* __restrict__ Ahp, long long aestride, int lda,
    const __half* __restrict__ Bhp, long long bestride,
    void* __restrict__ C, long long cstride, int ldc,
    int M, int K,
    const float* __restrict__ addsrc, int ldadd)
{
    extern __shared__ char smem[];
    const int e  = blockIdx.z;
    const int Me = (MODE == 0) ? M : g_cnt[e];
    const int bm = blockIdx.y * 128, bn = blockIdx.x * 128;
    if (bm >= Me) return;
    const __half* AhB = Ahp + (MODE == 2 ? (long long)e * aestride : 0LL);
    const __half* BhB = Bhp + (long long)e * bestride;

    const uint32_t sb = smem_u32(smem);
    const int tid = threadIdx.x, wid = tid >> 5, lid = tid & 31;
    const int wm = wid & 3, wn = wid >> 2;

    uint32_t sOff[2]; uint32_t aval[2];
    const char *aHp[2], *bHp[2];
    #pragma unroll
    for (int i = 0; i < 2; i++) {
        int q = tid + i * 256;
        int row = q >> 2, seg = q & 3;
        sOff[i] = (uint32_t)(row * 80 + seg * 16);
        int gm = bm + row;
        aval[i] = (gm < Me) ? 16u : 0u;
        long long arow;
        if (MODE == 1) arow = (gm < Me) ? (long long)g_tok[e * T_TOK + gm] : 0LL;
        else           arow = (gm < Me) ? (long long)gm : 0LL;
        aHp[i] = (const char*)(AhB + arow * (long long)lda) + seg * 16;
        long long brow = (long long)(bn + row);
        bHp[i] = (const char*)(BhB + brow * (long long)lda) + seg * 16;
    }

    const int laneRow = lid & 15, laneChk = lid >> 4;
    uint32_t aOff[2], bOff[4];
    #pragma unroll
    for (int t = 0; t < 2; t++)
        aOff[t] = (uint32_t)((wm * 32 + t * 16 + laneRow) * 80 + laneChk * 16);
    #pragma unroll
    for (int p = 0; p < 4; p++)
        bOff[p] = (uint32_t)(10240 + (wn * 64 + p * 16 + laneRow) * 80 + laneChk * 16);

    float am[2][8][4];
    #pragma unroll
    for (int t = 0; t < 2; t++)
        #pragma unroll
        for (int n8 = 0; n8 < 8; n8++)
            #pragma unroll
            for (int j = 0; j < 4; j++) am[t][n8][j] = 0.f;

    const int NC = K / 32;

    #define ISSUE(c) do { \
        uint32_t st_ = sb + (uint32_t)((c) & 3) * 20480u; \
        long long kb_ = (long long)(c) * 64; \
        _Pragma("unroll") \
        for (int i_ = 0; i_ < 2; i_++) { \
            CPA16(st_ + sOff[i_],          aHp[i_] + kb_, aval[i_]); \
            CPA16(st_ + 10240u + sOff[i_], bHp[i_] + kb_, 16u); \
        } \
    } while (0)

    ISSUE(0); CPA_COMMIT();
    if (NC > 1) { ISSUE(1); } CPA_COMMIT();
    if (NC > 2) { ISSUE(2); } CPA_COMMIT();

    for (int c = 0; c < NC; c++) {
        CPA_WAIT2();
        __syncthreads();
        const uint32_t stg = sb + (uint32_t)(c & 3) * 20480u;
        #pragma unroll
        for (int h = 0; h < 2; h++) {
            uint32_t ah0[4], ah1[4];
            LDM4(ah0, stg + aOff[0] + h * 32);
            LDM4(ah1, stg + aOff[1] + h * 32);
            #pragma unroll
            for (int p = 0; p < 4; p++) {
                uint32_t bh[4];
                LDM4(bh, stg + bOff[p] + h * 32);
                MMAF32(am[0][2 * p],     ah0, bh[0], bh[2]);
                MMAF32(am[0][2 * p + 1], ah0, bh[1], bh[3]);
                MMAF32(am[1][2 * p],     ah1, bh[0], bh[2]);
                MMAF32(am[1][2 * p + 1], ah1, bh[1], bh[3]);
            }
        }
        __syncthreads();
        if (c + 3 < NC) ISSUE(c + 3);
        CPA_COMMIT();
    }
    #undef ISSUE

    const int g = lid >> 2, tg = lid & 3;
    #pragma unroll
    for (int t = 0; t < 2; t++) {
        #pragma unroll
        for (int half = 0; half < 2; half++) {
            int row = bm + wm * 32 + t * 16 + g + half * 8;
            if (row >= Me) continue;
            long long base = (long long)e * cstride + (long long)row * ldc + bn + wn * 64 + tg * 2;
            const float* ap = ADD ? (addsrc + (long long)row * ldadd + bn + wn * 64 + tg * 2) : (const float*)0;
            #pragma unroll
            for (int n8 = 0; n8 < 8; n8++) {
                float v0 = am[t][n8][half * 2], v1 = am[t][n8][half * 2 + 1];
                if (ADD) { v0 += ap[n8 * 8]; v1 += ap[n8 * 8 + 1]; }
                if (OUTH) {
                    *(uint32_t*)((__half*)C + base + n8 * 8) = h2only(v0, v1);
                } else {
                    float* cp = (float*)C + base + n8 * 8;
                    cp[0] = v0; cp[1] = v1;
                }
            }
        }
    }
}

// ---------------- rmsnorm (optional fp32 out + fp16 plane) ----------------
__global__ __launch_bounds__(256) void rmsnorm_h(const float* __restrict__ in,
                                                 const float* __restrict__ w,
                                                 float* __restrict__ out,
                                                 __half* __restrict__ ph) {
    __shared__ float red[8];
    int t = blockIdx.x, tid = threadIdx.x;
    const float* row = in + (size_t)t * H_DIM;
    float ss = 0.f;
    for (int i = tid; i < H_DIM; i += 256) { float v = row[i]; ss += v * v; }
    #pragma unroll
    for (int o = 16; o; o >>= 1) ss += __shfl_xor_sync(0xffffffffu, ss, o);
    if ((tid & 31) == 0) red[tid >> 5] = ss;
    __syncthreads();
    float tot = red[0] + red[1] + red[2] + red[3] + red[4] + red[5] + red[6] + red[7];
    float inv = rsqrtf(tot * (1.0f / H_DIM) + 1e-6f);
    for (int i = tid * 2; i < H_DIM; i += 512) {
        float a = row[i] * inv * w[i];
        float b = row[i + 1] * inv * w[i + 1];
        if (out) { out[(size_t)t * H_DIM + i] = a; out[(size_t)t * H_DIM + i + 1] = b; }
        ((uint32_t*)ph)[((size_t)t * H_DIM + i) >> 1] = h2only(a, b);
    }
}

// ---------------- HMMA flash attention (fp16 QK/PV, fp32 softmax) ----------------
// SMEM byte layout:
// Qs 64x272B @0, Ks 64x272B @17408, Vt 128x144B @34816, Pf 64x144B @53248,
// Ps(f32) 64x65 @62464, mrow@79104, lrow@79360, corr@79616, pm4@79872, ps4@80896; total 81920
#define ATTN_SMEM 81920

__global__ void __launch_bounds__(256) attn_mma() {
    extern __shared__ char smem[];
    const uint32_t sb = smem_u32(smem);
    const uint32_t QS = 0, KS = 17408, VT = 34816, PF = 53248;
    float* Ps   = (float*)(smem + 62464);
    float* mrow = (float*)(smem + 79104);
    float* lrow = (float*)(smem + 79360);
    float* corr = (float*)(smem + 79616);
    float* pm4  = (float*)(smem + 79872);
    float* ps4  = (float*)(smem + 80896);
    __half* Vt  = (__half*)(smem + VT);
    __half* Pf  = (__half*)(smem + PF);

    int bh = blockIdx.y; int b = bh >> 4, h = bh & 15;
    int q0 = blockIdx.x * 64;
    int tb = b * S_LEN;
    int tid = threadIdx.x, wid = tid >> 5, lid = tid & 31;
    int wm = wid & 3, wn = wid >> 2;
    const int laneRow = lid & 15, laneChk = lid >> 4;
    const int g = lid >> 2, tg = lid & 3;
    const float scale = 1.0f / sqrtf(192.0f);

    // load Q tile (64 x 128 fp16)
    for (int i = tid; i < 1024; i += 256) {
        int r = i >> 4, c8 = i & 15;
        uint4 v = *(const uint4*)(c_qo + (size_t)(tb + q0 + r) * 2048 + h * 128 + c8 * 8);
        *(uint4*)(smem + QS + r * 272 + c8 * 16) = v;
    }
    if (tid < 64) { mrow[tid] = -1e30f; lrow[tid] = 0.f; }

    float acc[8][4];
    #pragma unroll
    for (int n8 = 0; n8 < 8; n8++)
        #pragma unroll
        for (int j = 0; j < 4; j++) acc[n8][j] = 0.f;
    __syncthreads();

    int nkt = blockIdx.x + 1;
    for (int kt = 0; kt < nkt; kt++) {
        int k0 = kt * 64;
        // load K tile
        for (int i = tid; i < 1024; i += 256) {
            int r = i >> 4, c8 = i & 15;
            uint4 v = *(const uint4*)(c_kvo + (size_t)(tb + k0 + r) * 4096 + h * 128 + c8 * 8);
            *(uint4*)(smem + KS + r * 272 + c8 * 16) = v;
        }
        // load V tile transposed -> Vt[d][key]
        #pragma unroll
        for (int it = 0; it < 4; it++) {
            int u = tid + it * 256;
            int key = (u & 15) | ((u >> 8) << 4);
            int d8 = (u >> 4) & 15;
            uint4 v = *(const uint4*)(c_kvo + (size_t)(tb + k0 + key) * 4096 + 2048 + h * 128 + d8 * 8);
            __half* hv = (__half*)&v;
            #pragma unroll
            for (int j = 0; j < 8; j++) Vt[(d8 * 8 + j) * 72 + key] = hv[j];
        }
        __syncthreads();

        // ---- QK^T: warp tile m16 (wm) x n32 (wn) ----
        float sc[4][4];
        #pragma unroll
        for (int f = 0; f < 4; f++)
            #pragma unroll
            for (int j = 0; j < 4; j++) sc[f][j] = 0.f;
        #pragma unroll
        for (int h8 = 0; h8 < 8; h8++) {
            uint32_t aq[4];
            LDM4(aq, sb + QS + (wm * 16 + laneRow) * 272 + h8 * 32 + laneChk * 16);
            #pragma unroll
            for (int p16 = 0; p16 < 2; p16++) {
                uint32_t bk[4];
                LDM4(bk, sb + KS + (wn * 32 + p16 * 16 + laneRow) * 272 + h8 * 32 + laneChk * 16);
                MMAF32(sc[p16 * 2],     aq, bk[0], bk[2]);
                MMAF32(sc[p16 * 2 + 1], aq, bk[1], bk[3]);
            }
        }
        // write scores with causal mask
        {
            int r0 = wm * 16 + g, r1 = r0 + 8;
            int gr0 = q0 + r0, gr1 = q0 + r1;
            #pragma unroll
            for (int f = 0; f < 4; f++) {
                int cb = wn * 32 + (f >> 1) * 16 + (f & 1) * 8 + tg * 2;
                int ck = k0 + cb;
                Ps[r0 * 65 + cb]     = (ck     <= gr0) ? sc[f][0] * scale : -1e30f;
                Ps[r0 * 65 + cb + 1] = (ck + 1 <= gr0) ? sc[f][1] * scale : -1e30f;
                Ps[r1 * 65 + cb]     = (ck     <= gr1) ? sc[f][2] * scale : -1e30f;
                Ps[r1 * 65 + cb + 1] = (ck + 1 <= gr1) ? sc[f][3] * scale : -1e30f;
            }
        }
        __syncthreads();

        // ---- softmax (fp32) + fp16 P tile ----
        {
            int r = tid & 63, qd = tid >> 6;
            float m0 = mrow[r];
            float pm = -1e30f;
            #pragma unroll 4
            for (int c = qd * 16; c < qd * 16 + 16; c++) pm = fmaxf(pm, Ps[r * 65 + c]);
            pm4[r * 4 + qd] = pm;
            __syncthreads();
            float mx = fmaxf(m0, fmaxf(fmaxf(pm4[r * 4], pm4[r * 4 + 1]),
                                       fmaxf(pm4[r * 4 + 2], pm4[r * 4 + 3])));
            float sum = 0.f;
            #pragma unroll 4
            for (int c = qd * 16; c < qd * 16 + 16; c++) {
                float p = __expf(Ps[r * 65 + c] - mx);
                sum += p;
                Pf[r * 72 + c] = __float2half_rn(p);
            }
            ps4[r * 4 + qd] = sum;
            __syncthreads();
            if (qd == 0) {
                float cr = __expf(m0 - mx);
                corr[r] = cr;
                lrow[r] = lrow[r] * cr + ps4[r * 4] + ps4[r * 4 + 1] + ps4[r * 4 + 2] + ps4[r * 4 + 3];
                mrow[r] = mx;
            }
        }
        __syncthreads();

        // rescale accumulators
        {
            float cr0 = corr[wm * 16 + g], cr1 = corr[wm * 16 + g + 8];
            #pragma unroll
            for (int n8 = 0; n8 < 8; n8++) {
                acc[n8][0] *= cr0; acc[n8][1] *= cr0;
                acc[n8][2] *= cr1; acc[n8][3] *= cr1;
            }
        }
        // ---- PV: warp tile m16 (wm) x n64 (wn over d=128) ----
        #pragma unroll
        for (int kh = 0; kh < 4; kh++) {
            uint32_t ap[4];
            LDM4(ap, sb + PF + (wm * 16 + laneRow) * 144 + kh * 32 + laneChk * 16);
            #pragma unroll
            for (int p16 = 0; p16 < 4; p16++) {
                uint32_t bv[4];
                LDM4(bv, sb + VT + (wn * 64 + p16 * 16 + laneRow) * 144 + kh * 32 + laneChk * 16);
                MMAF32(acc[p16 * 2],     ap, bv[0], bv[2]);
                MMAF32(acc[p16 * 2 + 1], ap, bv[1], bv[3]);
            }
        }
        __syncthreads();
    }

    // epilogue: divide by lrow, write fp16 plane
    {
        int r0 = wm * 16 + g, r1 = r0 + 8;
        float i0 = 1.0f / lrow[r0], i1 = 1.0f / lrow[r1];
        size_t b0 = (size_t)(tb + q0 + r0) * 2048 + h * 128;
        size_t b1 = (size_t)(tb + q0 + r1) * 2048 + h * 128;
        #pragma unroll
        for (int n8 = 0; n8 < 8; n8++) {
            int col = wn * 64 + (n8 >> 1) * 16 + (n8 & 1) * 8 + tg * 2;
            *(uint32_t*)(c_ath + b0 + col) = h2only(acc[n8][0] * i0, acc[n8][1] * i0);
            *(uint32_t*)(c_ath + b1 + col) = h2only(acc[n8][2] * i1, acc[n8][3] * i1);
        }
    }
}

// ---------------- gate ----------------
__global__ void __launch_bounds__(512) zero_cnt() { if (threadIdx.x < E_NUM) g_cnt[threadIdx.x] = 0; }

__global__ void __launch_bounds__(512) gate_kernel(const float* __restrict__ gate_w) {
    int t = blockIdx.x;
    int w = threadIdx.x >> 5, lane = threadIdx.x & 31;
    const float* x = g_X2 + (size_t)t * H_DIM;
    const float* gw = gate_w + (size_t)w * H_DIM;
    float s = 0.f;
    for (int i = lane; i < H_DIM; i += 32) s += x[i] * gw[i];
    #pragma unroll
    for (int o = 16; o; o >>= 1) s += __shfl_xor_sync(0xffffffffu, s, o);
    __shared__ float lg[E_NUM];
    if (lane == 0) lg[w] = s;
    __syncthreads();
    if (threadIdx.x == 0) {
        float mx = -1e30f;
        for (int e = 0; e < E_NUM; e++) mx = fmaxf(mx, lg[e]);
        float pe[E_NUM];
        for (int e = 0; e < E_NUM; e++) pe[e] = expf(lg[e] - mx);
        bool used[E_NUM];
        for (int e = 0; e < E_NUM; e++) used[e] = false;
        int sel[4]; float sw[4]; float wsum = 0.f;
        for (int j = 0; j < 4; j++) {
            int bi = -1; float bv = -1.f;
            for (int e = 0; e < E_NUM; e++)
                if (!used[e] && pe[e] > bv) { bv = pe[e]; bi = e; }
            used[bi] = true; sel[j] = bi; sw[j] = bv; wsum += bv;
        }
        for (int j = 0; j < 4; j++) {
            int e = sel[j];
            int pos = atomicAdd(&g_cnt[e], 1);
            g_tok[e * T_TOK + pos] = t;
            g_texp[t * 4 + j] = e;
            g_trow[t * 4 + j] = pos;
            g_twt [t * 4 + j] = sw[j] / wsum;
        }
    }
}

// ---------------- activations (fp16-plane out) ----------------
__device__ __forceinline__ float silu_f(float x) { return x / (1.0f + __expf(-x)); }

__global__ void __launch_bounds__(256) act_moe_h() {
    int e = blockIdx.y, r = blockIdx.x;
    if (r >= g_cnt[e]) return;
    const float* row = g_gu + ((size_t)e * T_TOK + r) * TWO_I;
    size_t pb = ((size_t)e * T_TOK + r) * I_DIM;
    for (int i = threadIdx.x * 2; i < I_DIM; i += 512) {
        float a = silu_f(row[i])     * row[I_DIM + i];
        float b = silu_f(row[i + 1]) * row[I_DIM + i + 1];
        ((uint32_t*)c_guh)[(pb + i) >> 1] = h2only(a, b);
    }
}

__global__ void __launch_bounds__(256) act_shared_h() {
    int t = blockIdx.x;
    const float* row = g_sgu + (size_t)t * SH2;
    size_t pb = (size_t)t * SHI_DIM;
    for (int i = threadIdx.x * 2; i < SHI_DIM; i += 512) {
        float a = silu_f(row[i])     * row[SHI_DIM + i];
        float b = silu_f(row[i + 1]) * row[SHI_DIM + i + 1];
        ((uint32_t*)c_sah)[(pb + i) >> 1] = h2only(a, b);
    }
}

// ---------------- final sum ----------------
__global__ void __launch_bounds__(256) final_sum(float* __restrict__ out) {
    int t = blockIdx.x;
    int e0 = g_texp[t * 4 + 0], e1 = g_texp[t * 4 + 1], e2 = g_texp[t * 4 + 2], e3 = g_texp[t * 4 + 3];
    int r0 = g_trow[t * 4 + 0], r1 = g_trow[t * 4 + 1], r2 = g_trow[t * 4 + 2], r3 = g_trow[t * 4 + 3];
    float w0 = g_twt[t * 4 + 0], w1v = g_twt[t * 4 + 1], w2v = g_twt[t * 4 + 2], w3 = g_twt[t * 4 + 3];
    const float* d0 = g_down + ((size_t)e0 * T_TOK + r0) * H_DIM;
    const float* d1 = g_down + ((size_t)e1 * T_TOK + r1) * H_DIM;
    const float* d2 = g_down + ((size_t)e2 * T_TOK + r2) * H_DIM;
    const float* d3 = g_down + ((size_t)e3 * T_TOK + r3) * H_DIM;
    for (int h = threadIdx.x; h < H_DIM; h += 256) {
        float v = out[(size_t)t * H_DIM + h];
        v += w0 * d0[h] + w1v * d1[h] + w2v * d2[h] + w3 * d3[h];
        out[(size_t)t * H_DIM + h] = v;
    }
}

// ---------------- launch ----------------
extern "C" void kernel_launch(void* const* d_in, const int* in_sizes, int n_in,
                              void* d_out, int out_size) {
    (void)in_sizes; (void)n_in; (void)out_size;
    const float* hidden  = (const float*)d_in[0];
    const float* ln1_w   = (const float*)d_in[2];
    const float* ln2_w   = (const float*)d_in[3];
    const float* q_w     = (const float*)d_in[4];
    const float* kv_w    = (const float*)d_in[5];
    const float* o_w     = (const float*)d_in[6];
    const float* gate_w  = (const float*)d_in[7];
    const float* w1      = (const float*)d_in[8];
    const float* w2      = (const float*)d_in[9];
    const float* sh_gu_w = (const float*)d_in[10];
    const float* sh_dn_w = (const float*)d_in[11];
    float* out = (float*)d_out;

    static cudaStream_t s1 = nullptr, s2 = nullptr;
    static cudaEvent_t ev[12];
    if (!s1) {
        cudaStreamCreateWithFlags(&s1, cudaStreamNonBlocking);
        cudaStreamCreateWithFlags(&s2, cudaStreamNonBlocking);
        for (int i = 0; i < 12; i++) cudaEventCreateWithFlags(&ev[i], cudaEventDisableTiming);
    }

    float *pHid, *pX2, *pSgu, *pGu, *pDown;
    cudaGetSymbolAddress((void**)&pHid, g_hid);
    cudaGetSymbolAddress((void**)&pX2, g_X2);
    cudaGetSymbolAddress((void**)&pSgu, g_sgu);
    cudaGetSymbolAddress((void**)&pGu, g_gu);
    cudaGetSymbolAddress((void**)&pDown, g_down);

    __half *Xh, *qo, *kvo, *ath, *X2h, *guh, *sah;
    __half *qwh, *kvh, *owh, *w1h, *w2h, *sgh, *sdh;
    cudaGetSymbolAddress((void**)&Xh, c_Xh);
    cudaGetSymbolAddress((void**)&qo, c_qo);
    cudaGetSymbolAddress((void**)&kvo, c_kvo);
    cudaGetSymbolAddress((void**)&ath, c_ath);
    cudaGetSymbolAddress((void**)&X2h, c_X2h);
    cudaGetSymbolAddress((void**)&guh, c_guh);
    cudaGetSymbolAddress((void**)&sah, c_sah);
    cudaGetSymbolAddress((void**)&qwh, c_qwh);
    cudaGetSymbolAddress((void**)&kvh, c_kvh);
    cudaGetSymbolAddress((void**)&owh, c_owh);
    cudaGetSymbolAddress((void**)&w1h, c_w1h);
    cudaGetSymbolAddress((void**)&w2h, c_w2h);
    cudaGetSymbolAddress((void**)&sgh, c_sgh);
    cudaGetSymbolAddress((void**)&sdh, c_sdh);

    cudaFuncSetAttribute(attn_mma, cudaFuncAttributeMaxDynamicSharedMemorySize, ATTN_SMEM);
    cudaFuncSetAttribute(gemm_h<0, false, false>, cudaFuncAttributeMaxDynamicSharedMemorySize, GSMEM_BYTES);
    cudaFuncSetAttribute(gemm_h<0, true,  false>, cudaFuncAttributeMaxDynamicSharedMemorySize, GSMEM_BYTES);
    cudaFuncSetAttribute(gemm_h<1, false, false>, cudaFuncAttributeMaxDynamicSharedMemorySize, GSMEM_BYTES);
    cudaFuncSetAttribute(gemm_h<2, false, false>, cudaFuncAttributeMaxDynamicSharedMemorySize, GSMEM_BYTES);
    cudaFuncSetAttribute(gemm_h<0, false, true >, cudaFuncAttributeMaxDynamicSharedMemorySize, GSMEM_BYTES);

    // fork side streams from captured root
    cudaEventRecord(ev[0], 0);
    cudaStreamWaitEvent(s1, ev[0], 0);
    cudaStreamWaitEvent(s2, ev[0], 0);

    // s1: weight conversions (DRAM-bound; overlap under compute)
    convW<<<2048, 256, 0, s1>>>(q_w, qwh, 2048, 1);           cudaEventRecord(ev[1], s1);
    convW<<<4096, 256, 0, s1>>>(kv_w, kvh, 2048, 0);          cudaEventRecord(ev[2], s1);
    convW<<<2048, 256, 0, s1>>>(o_w, owh, 2048, 0);           cudaEventRecord(ev[3], s1);
    convW<<<E_NUM * TWO_I, 256, 0, s1>>>(w1, w1h, 2048, 0);   cudaEventRecord(ev[4], s1);
    convW<<<SH2, 256, 0, s1>>>(sh_gu_w, sgh, 2048, 0);        cudaEventRecord(ev[5], s1);
    convW<<<E_NUM * H_DIM, 256, 0, s1>>>(w2, w2h, 1408, 0);   cudaEventRecord(ev[6], s1);
    convW<<<H_DIM, 256, 0, s1>>>(sh_dn_w, sdh, 2816, 0);      cudaEventRecord(ev[7], s1);

    // s0: rmsnorm -> fp16 X plane
    rmsnorm_h<<<T_TOK, 256>>>(hidden, ln1_w, nullptr, Xh);
    cudaEventRecord(ev[10], 0);

    // s2: KV projection (fp16 out), concurrent with Q projection on s0
    cudaStreamWaitEvent(s2, ev[10], 0);
    cudaStreamWaitEvent(s2, ev[2], 0);
    gemm_h<0, false, true><<<dim3(32, 16, 1), 256, GSMEM_BYTES, s2>>>(
        Xh, 0LL, 2048, kvh, 0LL, kvo, 0LL, 4096, T_TOK, 2048, nullptr, 0);
    cudaEventRecord(ev[11], s2);

    // s0: Q projection (fp16 out)
    cudaStreamWaitEvent(0, ev[1], 0);
    gemm_h<0, false, true><<<dim3(16, 16, 1), 256, GSMEM_BYTES>>>(
        Xh, 0LL, 2048, qwh, 0LL, qo, 0LL, 2048, T_TOK, 2048, nullptr, 0);

    // s0: attention (needs Q + KV)
    cudaStreamWaitEvent(0, ev[11], 0);
    attn_mma<<<dim3(16, 32), 256, ATTN_SMEM>>>();

    // s0: hid = attn @ o_w^T + hidden
    cudaStreamWaitEvent(0, ev[3], 0);
    gemm_h<0, true, false><<<dim3(16, 16, 1), 256, GSMEM_BYTES>>>(
        ath, 0LL, 2048, owh, 0LL, pHid, 0LL, H_DIM, T_TOK, 2048, hidden, H_DIM);
    rmsnorm_h<<<T_TOK, 256>>>(pHid, ln2_w, pX2, X2h);
    cudaEventRecord(ev[8], 0);  // X2 ready

    // s2: routed branch
    cudaStreamWaitEvent(s2, ev[8], 0);
    zero_cnt<<<1, 32, 0, s2>>>();
    gate_kernel<<<T_TOK, 512, 0, s2>>>(gate_w);
    cudaStreamWaitEvent(s2, ev[4], 0);
    gemm_h<1, false, false><<<dim3(22, 16, E_NUM), 256, GSMEM_BYTES, s2>>>(
        X2h, 0LL, 2048, w1h, (long long)TWO_I * H_DIM,
        pGu, (long long)T_TOK * TWO_I, TWO_I, 0, 2048, nullptr, 0);
    act_moe_h<<<dim3(T_TOK, E_NUM), 256, 0, s2>>>();
    cudaStreamWaitEvent(s2, ev[6], 0);
    gemm_h<2, false, false><<<dim3(16, 16, E_NUM), 256, GSMEM_BYTES, s2>>>(
        guh, (long long)T_TOK * I_DIM, 1408, w2h, (long long)H_DIM * I_DIM,
        pDown, (long long)T_TOK * H_DIM, H_DIM, 0, 1408, nullptr, 0);
    cudaEventRecord(ev[9], s2);

    // s0: shared branch (concurrent with routed)
    cudaStreamWaitEvent(0, ev[5], 0);
    gemm_h<0, false, false><<<dim3(44, 16, 1), 256, GSMEM_BYTES>>>(
        X2h, 0LL, 2048, sgh, 0LL, pSgu, 0LL, SH2, T_TOK, 2048, nullptr, 0);
    act_shared_h<<<T_TOK, 256>>>();
    cudaStreamWaitEvent(0, ev[7], 0);
    gemm_h<0, true, false><<<dim3(16, 16, 1), 256, GSMEM_BYTES>>>(
        sah, 0LL, 2816, sdh, 0LL, out, 0LL, H_DIM, T_TOK, 2816, pHid, H_DIM);

    // join routed, final combine
    cudaStreamWaitEvent(0, ev[9], 0);
    final_sum<<<T_TOK, 256>>>(out);
}

// round 11
// speedup vs baseline: 5.8063x; 1.0063x over previous
#include <cuda_runtime.h>
#include <cuda_fp16.h>
#include <cstdint>
#include <math.h>

#define T_TOK 2048
#define H_DIM 2048
#define S_LEN 1024
#define E_NUM 16
#define I_DIM 1408
#define TWO_I 2816
#define SHI_DIM 2816
#define SH2 5632

// ---------------- fp32 scratch ----------------
__device__ float g_hid [(size_t)T_TOK * H_DIM];
__device__ float g_X2  [(size_t)T_TOK * H_DIM];
__device__ float g_down[(size_t)E_NUM * T_TOK * H_DIM];
__device__ int   g_cnt [E_NUM];
__device__ int   g_tok [E_NUM * T_TOK];
__device__ int   g_texp[T_TOK * 4];
__device__ int   g_trow[T_TOK * 4];
__device__ float g_twt [T_TOK * 4];

// ---------------- fp16 planes ----------------
__device__ __half c_Xh  [(size_t)T_TOK * H_DIM];
__device__ __half c_qkvo[(size_t)T_TOK * 6144];       // q cols 0-2047, k 2048-4095, v 4096-6143
__device__ __half c_ath [(size_t)T_TOK * 2048];
__device__ __half c_X2h [(size_t)T_TOK * H_DIM];
__device__ __half c_guh [(size_t)E_NUM * T_TOK * I_DIM];
__device__ __half c_sah [(size_t)T_TOK * SHI_DIM];
__device__ __half c_qkvw[(size_t)6144 * 2048];
__device__ __half c_owh [(size_t)2048 * 2048];
__device__ __half c_w1h [(size_t)E_NUM * TWO_I * H_DIM];   // interleaved g/u rows
__device__ __half c_w2h [(size_t)E_NUM * H_DIM * I_DIM];
__device__ __half c_sgh [(size_t)SH2 * H_DIM];             // interleaved g/u rows
__device__ __half c_sdh [(size_t)H_DIM * SHI_DIM];

// ================= helpers =================
static __device__ __forceinline__ uint32_t smem_u32(const void* p) {
    uint32_t a;
    asm("{ .reg .u64 t; cvta.to.shared.u64 t, %1; cvt.u32.u64 %0, t; }" : "=r"(a) : "l"(p));
    return a;
}
static __device__ __forceinline__ uint32_t h2only(float x, float y) {
    __half2 hp = __halves2half2(__float2half_rn(x), __float2half_rn(y));
    return *(uint32_t*)&hp;
}
__device__ __forceinline__ float silu_f(float x) { return x / (1.0f + __expf(-x)); }
#define LDM4(r, a) \
    asm volatile("ldmatrix.sync.aligned.m8n8.x4.shared.b16 {%0,%1,%2,%3}, [%4];" \
        : "=r"((r)[0]), "=r"((r)[1]), "=r"((r)[2]), "=r"((r)[3]) : "r"(a))
#define MMAF32(c, a, b0, b1) \
    asm volatile("mma.sync.aligned.m16n8k16.row.col.f32.f16.f16.f32 " \
        "{%0,%1,%2,%3}, {%4,%5,%6,%7}, {%8,%9}, {%0,%1,%2,%3};" \
        : "+f"((c)[0]), "+f"((c)[1]), "+f"((c)[2]), "+f"((c)[3]) \
        : "r"((a)[0]), "r"((a)[1]), "r"((a)[2]), "r"((a)[3]), "r"(b0), "r"(b1))
#define CPA16(d, s, n) \
    asm volatile("cp.async.cg.shared.global [%0], [%1], 16, %2;" :: "r"(d), "l"(s), "r"(n) : "memory")
#define CPA_COMMIT() asm volatile("cp.async.commit_group;" ::: "memory")
#define CPA_WAIT2()  asm volatile("cp.async.wait_group 2;" ::: "memory")

// ================= conversions =================
__global__ void __launch_bounds__(256) convW(const float* __restrict__ src,
                                             __half* __restrict__ dh, int K) {
    int row = blockIdx.x, tid = threadIdx.x;
    const float* s = src + (size_t)row * K;
    for (int i = tid * 4; i < K; i += 1024) {
        float4 v = *(const float4*)(s + i);
        *(uint2*)(dh + (size_t)row * K + i) = make_uint2(h2only(v.x, v.y), h2only(v.z, v.w));
    }
}
// q_w (remapped, rows 0..2047) + kv_w (rows 2048..6143) into one plane
__global__ void __launch_bounds__(256) convQKV(const float* __restrict__ qw,
                                               const float* __restrict__ kvw) {
    int n = blockIdx.x, tid = threadIdx.x;
    const float* s;
    if (n < 2048) s = qw + (size_t)((n >> 7) * 192 + (n & 127)) * 2048;
    else          s = kvw + (size_t)(n - 2048) * 2048;
    for (int i = tid * 4; i < 2048; i += 1024) {
        float4 v = *(const float4*)(s + i);
        *(uint2*)(c_qkvw + (size_t)n * 2048 + i) = make_uint2(h2only(v.x, v.y), h2only(v.z, v.w));
    }
}
// interleave gate/up rows: dst row 2j = src row j, dst row 2j+1 = src row I+j (per expert block)
__global__ void __launch_bounds__(256) convPair(const float* __restrict__ src,
                                                __half* __restrict__ dh,
                                                int K, int I) {
    int n = blockIdx.x, tid = threadIdx.x;
    int twoI = 2 * I;
    int e = n / twoI, r = n % twoI;
    int sr = (r & 1) ? (I + (r >> 1)) : (r >> 1);
    const float* s = src + ((size_t)e * twoI + sr) * K;
    for (int i = tid * 4; i < K; i += 1024) {
        float4 v = *(const float4*)(s + i);
        *(uint2*)(dh + (size_t)n * K + i) = make_uint2(h2only(v.x, v.y), h2only(v.z, v.w));
    }
}

// ================= HMMA fp16 GEMM =================
// EPI: 0 = f32 out, 1 = f32 out + addsrc, 2 = fp16 out, 3 = silu(g)*u fp16 out (paired cols)
#define GSMEM_BYTES (4 * 20480)

template <int MODE, int EPI>
__global__ void __launch_bounds__(256, 1) gemm_h(
    const __half* __restrict__ Ahp, long long aestride, int lda,
    const __half* __restrict__ Bhp, long long bestride,
    void* __restrict__ C, long long cstride, int ldc,
    int M, int K,
    const float* __restrict__ addsrc, int ldadd)
{
    extern __shared__ char smem[];
    const int e  = blockIdx.z;
    const int Me = (MODE == 0) ? M : g_cnt[e];
    const int bm = blockIdx.y * 128, bn = blockIdx.x * 128;
    if (bm >= Me) return;
    const __half* AhB = Ahp + (MODE == 2 ? (long long)e * aestride : 0LL);
    const __half* BhB = Bhp + (long long)e * bestride;

    const uint32_t sb = smem_u32(smem);
    const int tid = threadIdx.x, wid = tid >> 5, lid = tid & 31;
    const int wm = wid & 3, wn = wid >> 2;

    uint32_t sOff[2]; uint32_t aval[2];
    const char *aHp[2], *bHp[2];
    #pragma unroll
    for (int i = 0; i < 2; i++) {
        int q = tid + i * 256;
        int row = q >> 2, seg = q & 3;
        sOff[i] = (uint32_t)(row * 80 + seg * 16);
        int gm = bm + row;
        aval[i] = (gm < Me) ? 16u : 0u;
        long long arow;
        if (MODE == 1) arow = (gm < Me) ? (long long)g_tok[e * T_TOK + gm] : 0LL;
        else           arow = (gm < Me) ? (long long)gm : 0LL;
        aHp[i] = (const char*)(AhB + arow * (long long)lda) + seg * 16;
        long long brow = (long long)(bn + row);
        bHp[i] = (const char*)(BhB + brow * (long long)lda) + seg * 16;
    }

    const int laneRow = lid & 15, laneChk = lid >> 4;
    uint32_t aOff[2], bOff[4];
    #pragma unroll
    for (int t = 0; t < 2; t++)
        aOff[t] = (uint32_t)((wm * 32 + t * 16 + laneRow) * 80 + laneChk * 16);
    #pragma unroll
    for (int p = 0; p < 4; p++)
        bOff[p] = (uint32_t)(10240 + (wn * 64 + p * 16 + laneRow) * 80 + laneChk * 16);

    float am[2][8][4];
    #pragma unroll
    for (int t = 0; t < 2; t++)
        #pragma unroll
        for (int n8 = 0; n8 < 8; n8++)
            #pragma unroll
            for (int j = 0; j < 4; j++) am[t][n8][j] = 0.f;

    const int NC = K / 32;

    #define ISSUE(c) do { \
        uint32_t st_ = sb + (uint32_t)((c) & 3) * 20480u; \
        long long kb_ = (long long)(c) * 64; \
        _Pragma("unroll") \
        for (int i_ = 0; i_ < 2; i_++) { \
            CPA16(st_ + sOff[i_],          aHp[i_] + kb_, aval[i_]); \
            CPA16(st_ + 10240u + sOff[i_], bHp[i_] + kb_, 16u); \
        } \
    } while (0)

    ISSUE(0); CPA_COMMIT();
    if (NC > 1) { ISSUE(1); } CPA_COMMIT();
    if (NC > 2) { ISSUE(2); } CPA_COMMIT();

    for (int c = 0; c < NC; c++) {
        CPA_WAIT2();
        __syncthreads();
        const uint32_t stg = sb + (uint32_t)(c & 3) * 20480u;
        #pragma unroll
        for (int h = 0; h < 2; h++) {
            uint32_t ah0[4], ah1[4];
            LDM4(ah0, stg + aOff[0] + h * 32);
            LDM4(ah1, stg + aOff[1] + h * 32);
            #pragma unroll
            for (int p = 0; p < 4; p++) {
                uint32_t bh[4];
                LDM4(bh, stg + bOff[p] + h * 32);
                MMAF32(am[0][2 * p],     ah0, bh[0], bh[2]);
                MMAF32(am[0][2 * p + 1], ah0, bh[1], bh[3]);
                MMAF32(am[1][2 * p],     ah1, bh[0], bh[2]);
                MMAF32(am[1][2 * p + 1], ah1, bh[1], bh[3]);
            }
        }
        __syncthreads();
        if (c + 3 < NC) ISSUE(c + 3);
        CPA_COMMIT();
    }
    #undef ISSUE

    const int g = lid >> 2, tg = lid & 3;
    #pragma unroll
    for (int t = 0; t < 2; t++) {
        #pragma unroll
        for (int half = 0; half < 2; half++) {
            int row = bm + wm * 32 + t * 16 + g + half * 8;
            if (row >= Me) continue;
            #pragma unroll
            for (int n8 = 0; n8 < 8; n8++) {
                float v0 = am[t][n8][half * 2], v1 = am[t][n8][half * 2 + 1];
                if (EPI == 3) {
                    // paired cols: v0 = gate, v1 = up -> one fp16 at col/2
                    long long idx = (long long)e * cstride + (long long)row * ldc
                                  + (bn >> 1) + wn * 32 + n8 * 4 + tg;
                    ((__half*)C)[idx] = __float2half_rn(silu_f(v0) * v1);
                } else {
                    long long base = (long long)e * cstride + (long long)row * ldc
                                   + bn + wn * 64 + tg * 2 + n8 * 8;
                    if (EPI == 1) {
                        const float* ap = addsrc + (long long)row * ldadd + bn + wn * 64 + tg * 2 + n8 * 8;
                        v0 += ap[0]; v1 += ap[1];
                    }
                    if (EPI == 2) *(uint32_t*)((__half*)C + base) = h2only(v0, v1);
                    else { float* cp = (float*)C + base; cp[0] = v0; cp[1] = v1; }
                }
            }
        }
    }
}

// ---------------- rmsnorm (optional fp32 out + fp16 plane) ----------------
__global__ __launch_bounds__(256) void rmsnorm_h(const float* __restrict__ in,
                                                 const float* __restrict__ w,
                                                 float* __restrict__ out,
                                                 __half* __restrict__ ph) {
    __shared__ float red[8];
    int t = blockIdx.x, tid = threadIdx.x;
    const float* row = in + (size_t)t * H_DIM;
    float ss = 0.f;
    for (int i = tid; i < H_DIM; i += 256) { float v = row[i]; ss += v * v; }
    #pragma unroll
    for (int o = 16; o; o >>= 1) ss += __shfl_xor_sync(0xffffffffu, ss, o);
    if ((tid & 31) == 0) red[tid >> 5] = ss;
    __syncthreads();
    float tot = red[0] + red[1] + red[2] + red[3] + red[4] + red[5] + red[6] + red[7];
    float inv = rsqrtf(tot * (1.0f / H_DIM) + 1e-6f);
    for (int i = tid * 2; i < H_DIM; i += 512) {
        float a = row[i] * inv * w[i];
        float b = row[i + 1] * inv * w[i + 1];
        if (out) { out[(size_t)t * H_DIM + i] = a; out[(size_t)t * H_DIM + i + 1] = b; }
        ((uint32_t*)ph)[((size_t)t * H_DIM + i) >> 1] = h2only(a, b);
    }
}

// ---------------- HMMA flash attention ----------------
#define ATTN_SMEM 81920

__global__ void __launch_bounds__(256) attn_mma() {
    extern __shared__ char smem[];
    const uint32_t sb = smem_u32(smem);
    const uint32_t QS = 0, KS = 17408, VT = 34816, PF = 53248;
    float* Ps   = (float*)(smem + 62464);
    float* mrow = (float*)(smem + 79104);
    float* lrow = (float*)(smem + 79360);
    float* corr = (float*)(smem + 79616);
    float* pm4  = (float*)(smem + 79872);
    float* ps4  = (float*)(smem + 80896);
    __half* Vt  = (__half*)(smem + VT);
    __half* Pf  = (__half*)(smem + PF);

    int bh = blockIdx.y; int b = bh >> 4, h = bh & 15;
    int q0 = blockIdx.x * 64;
    int tb = b * S_LEN;
    int tid = threadIdx.x, wid = tid >> 5, lid = tid & 31;
    int wm = wid & 3, wn = wid >> 2;
    const int laneRow = lid & 15, laneChk = lid >> 4;
    const int g = lid >> 2, tg = lid & 3;
    const float scale = 1.0f / sqrtf(192.0f);

    for (int i = tid; i < 1024; i += 256) {
        int r = i >> 4, c8 = i & 15;
        uint4 v = *(const uint4*)(c_qkvo + (size_t)(tb + q0 + r) * 6144 + h * 128 + c8 * 8);
        *(uint4*)(smem + QS + r * 272 + c8 * 16) = v;
    }
    if (tid < 64) { mrow[tid] = -1e30f; lrow[tid] = 0.f; }

    float acc[8][4];
    #pragma unroll
    for (int n8 = 0; n8 < 8; n8++)
        #pragma unroll
        for (int j = 0; j < 4; j++) acc[n8][j] = 0.f;
    __syncthreads();

    int nkt = blockIdx.x + 1;
    for (int kt = 0; kt < nkt; kt++) {
        int k0 = kt * 64;
        for (int i = tid; i < 1024; i += 256) {
            int r = i >> 4, c8 = i & 15;
            uint4 v = *(const uint4*)(c_qkvo + (size_t)(tb + k0 + r) * 6144 + 2048 + h * 128 + c8 * 8);
            *(uint4*)(smem + KS + r * 272 + c8 * 16) = v;
        }
        #pragma unroll
        for (int it = 0; it < 4; it++) {
            int u = tid + it * 256;
            int key = (u & 15) | ((u >> 8) << 4);
            int d8 = (u >> 4) & 15;
            uint4 v = *(const uint4*)(c_qkvo + (size_t)(tb + k0 + key) * 6144 + 4096 + h * 128 + d8 * 8);
            __half* hv = (__half*)&v;
            #pragma unroll
            for (int j = 0; j < 8; j++) Vt[(d8 * 8 + j) * 72 + key] = hv[j];
        }
        __syncthreads();

        float sc[4][4];
        #pragma unroll
        for (int f = 0; f < 4; f++)
            #pragma unroll
            for (int j = 0; j < 4; j++) sc[f][j] = 0.f;
        #pragma unroll
        for (int h8 = 0; h8 < 8; h8++) {
            uint32_t aq[4];
            LDM4(aq, sb + QS + (wm * 16 + laneRow) * 272 + h8 * 32 + laneChk * 16);
            #pragma unroll
            for (int p16 = 0; p16 < 2; p16++) {
                uint32_t bk[4];
                LDM4(bk, sb + KS + (wn * 32 + p16 * 16 + laneRow) * 272 + h8 * 32 + laneChk * 16);
                MMAF32(sc[p16 * 2],     aq, bk[0], bk[2]);
                MMAF32(sc[p16 * 2 + 1], aq, bk[1], bk[3]);
            }
        }
        {
            int r0 = wm * 16 + g, r1 = r0 + 8;
            int gr0 = q0 + r0, gr1 = q0 + r1;
            #pragma unroll
            for (int f = 0; f < 4; f++) {
                int cb = wn * 32 + (f >> 1) * 16 + (f & 1) * 8 + tg * 2;
                int ck = k0 + cb;
                Ps[r0 * 65 + cb]     = (ck     <= gr0) ? sc[f][0] * scale : -1e30f;
                Ps[r0 * 65 + cb + 1] = (ck + 1 <= gr0) ? sc[f][1] * scale : -1e30f;
                Ps[r1 * 65 + cb]     = (ck     <= gr1) ? sc[f][2] * scale : -1e30f;
                Ps[r1 * 65 + cb + 1] = (ck + 1 <= gr1) ? sc[f][3] * scale : -1e30f;
            }
        }
        __syncthreads();

        {
            int r = tid & 63, qd = tid >> 6;
            float m0 = mrow[r];
            float pm = -1e30f;
            #pragma unroll 4
            for (int c = qd * 16; c < qd * 16 + 16; c++) pm = fmaxf(pm, Ps[r * 65 + c]);
            pm4[r * 4 + qd] = pm;
            __syncthreads();
            float mx = fmaxf(m0, fmaxf(fmaxf(pm4[r * 4], pm4[r * 4 + 1]),
                                       fmaxf(pm4[r * 4 + 2], pm4[r * 4 + 3])));
            float sum = 0.f;
            #pragma unroll 4
            for (int c = qd * 16; c < qd * 16 + 16; c++) {
                float p = __expf(Ps[r * 65 + c] - mx);
                sum += p;
                Pf[r * 72 + c] = __float2half_rn(p);
            }
            ps4[r * 4 + qd] = sum;
            __syncthreads();
            if (qd == 0) {
                float cr = __expf(m0 - mx);
                corr[r] = cr;
                lrow[r] = lrow[r] * cr + ps4[r * 4] + ps4[r * 4 + 1] + ps4[r * 4 + 2] + ps4[r * 4 + 3];
                mrow[r] = mx;
            }
        }
        __syncthreads();

        {
            float cr0 = corr[wm * 16 + g], cr1 = corr[wm * 16 + g + 8];
            #pragma unroll
            for (int n8 = 0; n8 < 8; n8++) {
                acc[n8][0] *= cr0; acc[n8][1] *= cr0;
                acc[n8][2] *= cr1; acc[n8][3] *= cr1;
            }
        }
        #pragma unroll
        for (int kh = 0; kh < 4; kh++) {
            uint32_t ap[4];
            LDM4(ap, sb + PF + (wm * 16 + laneRow) * 144 + kh * 32 + laneChk * 16);
            #pragma unroll
            for (int p16 = 0; p16 < 4; p16++) {
                uint32_t bv[4];
                LDM4(bv, sb + VT + (wn * 64 + p16 * 16 + laneRow) * 144 + kh * 32 + laneChk * 16);
                MMAF32(acc[p16 * 2],     ap, bv[0], bv[2]);
                MMAF32(acc[p16 * 2 + 1], ap, bv[1], bv[3]);
            }
        }
        __syncthreads();
    }

    {
        int r0 = wm * 16 + g, r1 = r0 + 8;
        float i0 = 1.0f / lrow[r0], i1 = 1.0f / lrow[r1];
        size_t b0 = (size_t)(tb + q0 + r0) * 2048 + h * 128;
        size_t b1 = (size_t)(tb + q0 + r1) * 2048 + h * 128;
        #pragma unroll
        for (int n8 = 0; n8 < 8; n8++) {
            int col = wn * 64 + (n8 >> 1) * 16 + (n8 & 1) * 8 + tg * 2;
            *(uint32_t*)(c_ath + b0 + col) = h2only(acc[n8][0] * i0, acc[n8][1] * i0);
            *(uint32_t*)(c_ath + b1 + col) = h2only(acc[n8][2] * i1, acc[n8][3] * i1);
        }
    }
}

// ---------------- gate ----------------
__global__ void __launch_bounds__(512) zero_cnt() { if (threadIdx.x < E_NUM) g_cnt[threadIdx.x] = 0; }

__global__ void __launch_bounds__(512) gate_kernel(const float* __restrict__ gate_w) {
    int t = blockIdx.x;
    int w = threadIdx.x >> 5, lane = threadIdx.x & 31;
    const float* x = g_X2 + (size_t)t * H_DIM;
    const float* gw = gate_w + (size_t)w * H_DIM;
    float s = 0.f;
    for (int i = lane; i < H_DIM; i += 32) s += x[i] * gw[i];
    #pragma unroll
    for (int o = 16; o; o >>= 1) s += __shfl_xor_sync(0xffffffffu, s, o);
    __shared__ float lg[E_NUM];
    if (lane == 0) lg[w] = s;
    __syncthreads();
    if (threadIdx.x == 0) {
        float mx = -1e30f;
        for (int e = 0; e < E_NUM; e++) mx = fmaxf(mx, lg[e]);
        float pe[E_NUM];
        for (int e = 0; e < E_NUM; e++) pe[e] = expf(lg[e] - mx);
        bool used[E_NUM];
        for (int e = 0; e < E_NUM; e++) used[e] = false;
        int sel[4]; float sw[4]; float wsum = 0.f;
        for (int j = 0; j < 4; j++) {
            int bi = -1; float bv = -1.f;
            for (int e = 0; e < E_NUM; e++)
                if (!used[e] && pe[e] > bv) { bv = pe[e]; bi = e; }
            used[bi] = true; sel[j] = bi; sw[j] = bv; wsum += bv;
        }
        for (int j = 0; j < 4; j++) {
            int e = sel[j];
            int pos = atomicAdd(&g_cnt[e], 1);
            g_tok[e * T_TOK + pos] = t;
            g_texp[t * 4 + j] = e;
            g_trow[t * 4 + j] = pos;
            g_twt [t * 4 + j] = sw[j] / wsum;
        }
    }
}

// ---------------- final sum ----------------
__global__ void __launch_bounds__(256) final_sum(float* __restrict__ out) {
    int t = blockIdx.x;
    int e0 = g_texp[t * 4 + 0], e1 = g_texp[t * 4 + 1], e2 = g_texp[t * 4 + 2], e3 = g_texp[t * 4 + 3];
    int r0 = g_trow[t * 4 + 0], r1 = g_trow[t * 4 + 1], r2 = g_trow[t * 4 + 2], r3 = g_trow[t * 4 + 3];
    float w0 = g_twt[t * 4 + 0], w1v = g_twt[t * 4 + 1], w2v = g_twt[t * 4 + 2], w3 = g_twt[t * 4 + 3];
    const float* d0 = g_down + ((size_t)e0 * T_TOK + r0) * H_DIM;
    const float* d1 = g_down + ((size_t)e1 * T_TOK + r1) * H_DIM;
    const float* d2 = g_down + ((size_t)e2 * T_TOK + r2) * H_DIM;
    const float* d3 = g_down + ((size_t)e3 * T_TOK + r3) * H_DIM;
    for (int h = threadIdx.x; h < H_DIM; h += 256) {
        float v = out[(size_t)t * H_DIM + h];
        v += w0 * d0[h] + w1v * d1[h] + w2v * d2[h] + w3 * d3[h];
        out[(size_t)t * H_DIM + h] = v;
    }
}

// ---------------- launch ----------------
extern "C" void kernel_launch(void* const* d_in, const int* in_sizes, int n_in,
                              void* d_out, int out_size) {
    (void)in_sizes; (void)n_in; (void)out_size;
    const float* hidden  = (const float*)d_in[0];
    const float* ln1_w   = (const float*)d_in[2];
    const float* ln2_w   = (const float*)d_in[3];
    const float* q_w     = (const float*)d_in[4];
    const float* kv_w    = (const float*)d_in[5];
    const float* o_w     = (const float*)d_in[6];
    const float* gate_w  = (const float*)d_in[7];
    const float* w1      = (const float*)d_in[8];
    const float* w2      = (const float*)d_in[9];
    const float* sh_gu_w = (const float*)d_in[10];
    const float* sh_dn_w = (const float*)d_in[11];
    float* out = (float*)d_out;

    static cudaStream_t s1 = nullptr, s2 = nullptr;
    static cudaEvent_t ev[12];
    if (!s1) {
        cudaStreamCreateWithFlags(&s1, cudaStreamNonBlocking);
        cudaStreamCreateWithFlags(&s2, cudaStreamNonBlocking);
        for (int i = 0; i < 12; i++) cudaEventCreateWithFlags(&ev[i], cudaEventDisableTiming);
    }

    float *pHid, *pX2, *pDown;
    cudaGetSymbolAddress((void**)&pHid, g_hid);
    cudaGetSymbolAddress((void**)&pX2, g_X2);
    cudaGetSymbolAddress((void**)&pDown, g_down);

    __half *Xh, *qkvo, *ath, *X2h, *guh, *sah;
    __half *qkvw, *owh, *w1h, *w2h, *sgh, *sdh;
    cudaGetSymbolAddress((void**)&Xh, c_Xh);
    cudaGetSymbolAddress((void**)&qkvo, c_qkvo);
    cudaGetSymbolAddress((void**)&ath, c_ath);
    cudaGetSymbolAddress((void**)&X2h, c_X2h);
    cudaGetSymbolAddress((void**)&guh, c_guh);
    cudaGetSymbolAddress((void**)&sah, c_sah);
    cudaGetSymbolAddress((void**)&qkvw, c_qkvw);
    cudaGetSymbolAddress((void**)&owh, c_owh);
    cudaGetSymbolAddress((void**)&w1h, c_w1h);
    cudaGetSymbolAddress((void**)&w2h, c_w2h);
    cudaGetSymbolAddress((void**)&sgh, c_sgh);
    cudaGetSymbolAddress((void**)&sdh, c_sdh);

    cudaFuncSetAttribute(attn_mma, cudaFuncAttributeMaxDynamicSharedMemorySize, ATTN_SMEM);
    cudaFuncSetAttribute(gemm_h<0, 0>, cudaFuncAttributeMaxDynamicSharedMemorySize, GSMEM_BYTES);
    cudaFuncSetAttribute(gemm_h<0, 1>, cudaFuncAttributeMaxDynamicSharedMemorySize, GSMEM_BYTES);
    cudaFuncSetAttribute(gemm_h<0, 2>, cudaFuncAttributeMaxDynamicSharedMemorySize, GSMEM_BYTES);
    cudaFuncSetAttribute(gemm_h<0, 3>, cudaFuncAttributeMaxDynamicSharedMemorySize, GSMEM_BYTES);
    cudaFuncSetAttribute(gemm_h<1, 3>, cudaFuncAttributeMaxDynamicSharedMemorySize, GSMEM_BYTES);
    cudaFuncSetAttribute(gemm_h<2, 0>, cudaFuncAttributeMaxDynamicSharedMemorySize, GSMEM_BYTES);

    // fork side streams
    cudaEventRecord(ev[0], 0);
    cudaStreamWaitEvent(s1, ev[0], 0);
    cudaStreamWaitEvent(s2, ev[0], 0);

    // s1: conversions — attention-phase weights first (tiny), then MoE weights
    convQKV<<<6144, 256, 0, s1>>>(q_w, kv_w);                     cudaEventRecord(ev[1], s1);
    convW<<<2048, 256, 0, s1>>>(o_w, owh, 2048);                  cudaEventRecord(ev[3], s1);
    convPair<<<E_NUM * TWO_I, 256, 0, s1>>>(w1, w1h, 2048, I_DIM);   cudaEventRecord(ev[4], s1);
    convPair<<<SH2, 256, 0, s1>>>(sh_gu_w, sgh, 2048, SHI_DIM);   cudaEventRecord(ev[5], s1);
    convW<<<E_NUM * H_DIM, 256, 0, s1>>>(w2, w2h, 1408);          cudaEventRecord(ev[6], s1);
    convW<<<H_DIM, 256, 0, s1>>>(sh_dn_w, sdh, 2816);             cudaEventRecord(ev[7], s1);

    // s0: rmsnorm -> fp16 X plane
    rmsnorm_h<<<T_TOK, 256>>>(hidden, ln1_w, nullptr, Xh);

    // s0: merged QKV projection (fp16 out)
    cudaStreamWaitEvent(0, ev[1], 0);
    gemm_h<0, 2><<<dim3(48, 16, 1), 256, GSMEM_BYTES>>>(
        Xh, 0LL, 2048, qkvw, 0LL, qkvo, 0LL, 6144, T_TOK, 2048, nullptr, 0);

    // s0: attention
    attn_mma<<<dim3(16, 32), 256, ATTN_SMEM>>>();

    // s0: hid = attn @ o_w^T + hidden
    cudaStreamWaitEvent(0, ev[3], 0);
    gemm_h<0, 1><<<dim3(16, 16, 1), 256, GSMEM_BYTES>>>(
        ath, 0LL, 2048, owh, 0LL, pHid, 0LL, H_DIM, T_TOK, 2048, hidden, H_DIM);
    rmsnorm_h<<<T_TOK, 256>>>(pHid, ln2_w, pX2, X2h);
    cudaEventRecord(ev[8], 0);  // X2 ready

    // s2: routed branch (GU with fused silu epilogue)
    cudaStreamWaitEvent(s2, ev[8], 0);
    zero_cnt<<<1, 32, 0, s2>>>();
    gate_kernel<<<T_TOK, 512, 0, s2>>>(gate_w);
    cudaStreamWaitEvent(s2, ev[4], 0);
    gemm_h<1, 3><<<dim3(22, 16, E_NUM), 256, GSMEM_BYTES, s2>>>(
        X2h, 0LL, 2048, w1h, (long long)TWO_I * H_DIM,
        guh, (long long)T_TOK * I_DIM, I_DIM, 0, 2048, nullptr, 0);
    cudaStreamWaitEvent(s2, ev[6], 0);
    gemm_h<2, 0><<<dim3(16, 16, E_NUM), 256, GSMEM_BYTES, s2>>>(
        guh, (long long)T_TOK * I_DIM, 1408, w2h, (long long)H_DIM * I_DIM,
        pDown, (long long)T_TOK * H_DIM, H_DIM, 0, 1408, nullptr, 0);
    cudaEventRecord(ev[9], s2);

    // s0: shared branch (GU with fused silu epilogue)
    cudaStreamWaitEvent(0, ev[5], 0);
    gemm_h<0, 3><<<dim3(44, 16, 1), 256, GSMEM_BYTES>>>(
        X2h, 0LL, 2048, sgh, 0LL, sah, 0LL, SHI_DIM, T_TOK, 2048, nullptr, 0);
    cudaStreamWaitEvent(0, ev[7], 0);
    gemm_h<0, 1><<<dim3(16, 16, 1), 256, GSMEM_BYTES>>>(
        sah, 0LL, 2816, sdh, 0LL, out, 0LL, H_DIM, T_TOK, 2816, pHid, H_DIM);

    // join routed, final combine
    cudaStreamWaitEvent(0, ev[9], 0);
    final_sum<<<T_TOK, 256>>>(out);
}